// round 11
// baseline (speedup 1.0000x reference)
#include <cuda_runtime.h>
#include <cuda_bf16.h>
#include <math.h>

#define NN 50000
#define EE 800000
#define OUTC 40
#define NTILE 196            // ceil(50000/256)

__device__ __align__(128) float g_scratch[29000000];

#define PACK2(dst, lo, hi) asm("mov.b64 %0, {%1, %2};" : "=l"(dst) : "f"(lo), "f"(hi))
#define UNPK2(lo, hi, v)   asm("mov.b64 {%0, %1}, %2;" : "=f"(lo), "=f"(hi) : "l"(v))
#define FMA2(acc, a, b)    asm("fma.rn.f32x2 %0, %1, %2, %0;" : "+l"(acc) : "l"(a), "l"(b))

// ======================= init: counts, flag, float stat accumulators =======
__global__ void init_kernel(int* c1, int* c2, int* flag64, float* statz) {
    int i = blockIdx.x * blockDim.x + threadIdx.x;
    if (i < NN) { c1[i] = 1; c2[i] = 0; }     // c1 starts at 1 (self-loop)
    if (i == 0) *flag64 = 1;
    if (i < 640) statz[i] = 0.f;
}

__global__ void detect_kernel(const int* __restrict__ w, int* flag64) {
    int any = 0;
    for (int i = blockIdx.x * blockDim.x + threadIdx.x; i < EE; i += gridDim.x * blockDim.x)
        any |= w[2 * i + 1];
    if (any) atomicAnd(flag64, 0);
}

// convert edge_index to int32 row/col AND histogram in one pass
__global__ void convert_hist_kernel(const int* __restrict__ w, const int* __restrict__ flag64,
                                    int* __restrict__ rowA, int* __restrict__ colA,
                                    int* c1, int* c2) {
    int e = blockIdx.x * blockDim.x + threadIdx.x;
    if (e >= EE) return;
    int r, c;
    if (*flag64) { r = w[2 * e]; c = w[2 * (EE + e)]; }
    else         { r = w[e];     c = w[EE + e]; }
    rowA[e] = r; colA[e] = c;
    atomicAdd(&c1[c], 1);
    atomicAdd(&c2[r], 1);
}

// ---- parallel 3-phase exclusive scan over two arrays (gridDim.y selects) ----
__global__ void scan_p1(const int* __restrict__ cnt1, const int* __restrict__ cnt2,
                        int* __restrict__ btot) {
    const int* cnt = blockIdx.y ? cnt2 : cnt1;
    __shared__ int sw[8];
    int idx = blockIdx.x * 256 + threadIdx.x;
    int v = (idx < NN) ? cnt[idx] : 0;
#pragma unroll
    for (int d = 16; d; d >>= 1) v += __shfl_xor_sync(0xffffffffu, v, d);
    if ((threadIdx.x & 31) == 0) sw[threadIdx.x >> 5] = v;
    __syncthreads();
    if (threadIdx.x == 0) {
        int s = 0;
#pragma unroll
        for (int i = 0; i < 8; i++) s += sw[i];
        btot[blockIdx.y * (NTILE + 1) + blockIdx.x] = s;
    }
}

__global__ void scan_p2(int* __restrict__ btot) {
    int* b = btot + blockIdx.y * (NTILE + 1);
    __shared__ int sw[8], sw2[9];
    int t = threadIdx.x, lane = t & 31, wid = t >> 5;
    int v = (t < NTILE) ? b[t] : 0;
    int inc = v;
#pragma unroll
    for (int d = 1; d < 32; d <<= 1) { int y = __shfl_up_sync(0xffffffffu, inc, d); if (lane >= d) inc += y; }
    if (lane == 31) sw[wid] = inc;
    __syncthreads();
    if (t == 0) { sw2[0] = 0; for (int i = 0; i < 8; i++) sw2[i + 1] = sw2[i] + sw[i]; }
    __syncthreads();
    int excl = sw2[wid] + inc - v;
    if (t < NTILE) b[t] = excl;
    if (t == 0) b[NTILE] = sw2[8];
}

// scan phase 3 + cursor init + self-loop placement
__global__ void scan_p3(const int* __restrict__ cnt1, const int* __restrict__ cnt2,
                        const int* __restrict__ btot,
                        int* __restrict__ off1, int* __restrict__ off2,
                        int* __restrict__ cur1, int* __restrict__ cur2, int* __restrict__ csr1) {
    const int* cnt = blockIdx.y ? cnt2 : cnt1;
    int* off = blockIdx.y ? off2 : off1;
    const int* b = btot + blockIdx.y * (NTILE + 1);
    __shared__ int sw[8], sw2[9];
    int t = threadIdx.x, lane = t & 31, wid = t >> 5;
    int idx = blockIdx.x * 256 + t;
    int v = (idx < NN) ? cnt[idx] : 0;
    int inc = v;
#pragma unroll
    for (int d = 1; d < 32; d <<= 1) { int y = __shfl_up_sync(0xffffffffu, inc, d); if (lane >= d) inc += y; }
    if (lane == 31) sw[wid] = inc;
    __syncthreads();
    if (t == 0) { sw2[0] = 0; for (int i = 0; i < 8; i++) sw2[i + 1] = sw2[i] + sw[i]; }
    __syncthreads();
    int excl = b[blockIdx.x] + sw2[wid] + inc - v;
    if (idx < NN) {
        off[idx] = excl;
        if (blockIdx.y == 0) { cur1[idx] = excl + 1; csr1[excl] = idx; }
        else                 cur2[idx] = excl;
    }
    if (blockIdx.x == 0 && t == 0) off[NN] = b[NTILE];
}

__global__ void fill_kernel(const int* __restrict__ rowA, const int* __restrict__ colA,
                            int* cur1, int* csr1,
                            int* cur2, int* csr2c, int* csr2e) {
    int e = blockIdx.x * blockDim.x + threadIdx.x;
    if (e >= EE) return;
    int r = rowA[e];
    int c = colA[e];
    int p = atomicAdd(&cur1[c], 1);
    csr1[p] = r;
    int q = atomicAdd(&cur2[r], 1);
    csr2c[q] = c;
    csr2e[q] = e;
}

// ======================= weight fusion: Wf = Wg1 @ W_res, bf = Wg1 @ b_res ==
__global__ void wfuse_kernel(const float* __restrict__ Wg1, const float* __restrict__ W_res,
                             const float* __restrict__ b_res,
                             float* __restrict__ Wf, float* __restrict__ bf) {
    __shared__ float sWg[128];
    __shared__ float red[128];
    int d = blockIdx.x, k = threadIdx.x;
    sWg[k] = Wg1[d * 128 + k];
    __syncthreads();
    float s = 0.f;
#pragma unroll 8
    for (int j = 0; j < 128; j++) s = fmaf(sWg[j], W_res[j * 128 + k], s);
    Wf[d * 128 + k] = s;
    red[k] = sWg[k] * b_res[k];
    __syncthreads();
    for (int st = 64; st; st >>= 1) { if (k < st) red[k] += red[k + st]; __syncthreads(); }
    if (k == 0) bf[d] = red[0];
}

// ======================= GEMM (K = 128 fixed, f32x2 FMA) ====================

template <int TC, bool BNIN, bool ATTN, bool STATS, bool SPLITW>
__global__ void __launch_bounds__(128, 4)
gemm_k128(const float* __restrict__ A, const float* __restrict__ W,
          int ldw, int woff, const float* __restrict__ bias,
          float* __restrict__ out, int opitch, int ocol, int nrows,
          const float* __restrict__ bnm, const float* __restrict__ bnr,
          const float* __restrict__ bng, const float* __restrict__ bnb,
          const float* __restrict__ as, const float* __restrict__ ad,
          float* __restrict__ asrc, float* __restrict__ adst,
          float* gsum, float* gsq) {
    constexpr int CT = TC / 16;
    constexpr int PA = 68;
    constexpr int PW = TC + 4;
    __shared__ float sA[32 * PA];
    __shared__ float sW[32 * PW];
    const int tid = threadIdx.x;
    const int trow = tid >> 4;     // 0..7
    const int tcol = tid & 15;     // 0..15
    const int r0 = blockIdx.x * 64;

    unsigned long long acc2[4][CT];   // row-pairs x cols
#pragma unroll
    for (int p = 0; p < 4; p++)
#pragma unroll
        for (int j = 0; j < CT; j++) acc2[p][j] = 0ull;

    for (int kb = 0; kb < 128; kb += 32) {
        float bm = 0.f, br = 0.f, bgm = 0.f, bbt = 0.f;
        if (BNIN) {
            int kf = kb + (tid & 31);
            bm = bnm[kf]; br = bnr[kf]; bgm = bng[kf]; bbt = bnb[kf];
        }
        __syncthreads();
#pragma unroll
        for (int i = 0; i < 16; i++) {
            int idx = tid + i * 128;
            int row = idx >> 5, kk = idx & 31;
            int gr = r0 + row;
            float v = (gr < nrows) ? A[(size_t)gr * 128 + kb + kk] : 0.f;
            if (BNIN && gr < nrows) {
                float t = (v - bm) * br * bgm + bbt;
                v = (t > 0.f) ? t : expm1f(t);
            }
            sA[kk * PA + row] = v;
        }
#pragma unroll
        for (int i = 0; i < (TC * 32) / 128; i++) {
            int idx = tid + i * 128;
            int col = idx >> 5, kk = idx & 31;
            int wrow = SPLITW ? (col & 63) : col;
            int wko  = SPLITW ? ((col >> 6) * 128) : 0;
            sW[kk * PW + col] = W[(size_t)wrow * ldw + woff + wko + kb + kk];
        }
        __syncthreads();
#pragma unroll
        for (int kk = 0; kk < 32; kk++) {
            unsigned long long ap[4];
#pragma unroll
            for (int p = 0; p < 4; p++)
                ap[p] = *(const unsigned long long*)&sA[kk * PA + trow * 8 + 2 * p];
            float w[CT];
#pragma unroll
            for (int j = 0; j < CT; j += 4) {
                float4 wv = *(const float4*)&sW[kk * PW + tcol * CT + j];
                w[j] = wv.x; w[j + 1] = wv.y; w[j + 2] = wv.z; w[j + 3] = wv.w;
            }
            unsigned long long wd[CT];
#pragma unroll
            for (int j = 0; j < CT; j++) PACK2(wd[j], w[j], w[j]);
#pragma unroll
            for (int p = 0; p < 4; p++)
#pragma unroll
                for (int j = 0; j < CT; j++) FMA2(acc2[p][j], ap[p], wd[j]);
        }
    }
    // ---- store ----
#pragma unroll
    for (int p = 0; p < 4; p++) {
        int gr0 = r0 + trow * 8 + 2 * p;
#pragma unroll
        for (int j = 0; j < CT; j++) {
            int col = tcol * CT + j;
            float b = bias ? bias[col] : 0.f;
            float lo, hi;
            UNPK2(lo, hi, acc2[p][j]);
            if (gr0 < nrows)     out[(size_t)gr0 * opitch + ocol + col]       = lo + b;
            if (gr0 + 1 < nrows) out[(size_t)(gr0 + 1) * opitch + ocol + col] = hi + b;
        }
    }
    // ---- fused attention dots (TC=128 only) ----
    if (ATTN) {
#pragma unroll
        for (int p = 0; p < 4; p++) {
            float s1lo = 0.f, s2lo = 0.f, s1hi = 0.f, s2hi = 0.f;
#pragma unroll
            for (int j = 0; j < CT; j++) {
                int col = tcol * CT + j;
                float aS = __ldg(&as[col]), aD = __ldg(&ad[col]);
                float lo, hi;
                UNPK2(lo, hi, acc2[p][j]);
                s1lo = fmaf(lo, aS, s1lo); s2lo = fmaf(lo, aD, s2lo);
                s1hi = fmaf(hi, aS, s1hi); s2hi = fmaf(hi, aD, s2hi);
            }
            s1lo += __shfl_xor_sync(0xffffffffu, s1lo, 1);
            s2lo += __shfl_xor_sync(0xffffffffu, s2lo, 1);
            s1hi += __shfl_xor_sync(0xffffffffu, s1hi, 1);
            s2hi += __shfl_xor_sync(0xffffffffu, s2hi, 1);
            if (!(tcol & 1)) {
                int h = tcol >> 1;
                int rlo = r0 + trow * 8 + 2 * p;
                if (rlo < nrows)     { asrc[rlo * 8 + h] = s1lo;       adst[rlo * 8 + h] = s2lo; }
                if (rlo + 1 < nrows) { asrc[(rlo + 1) * 8 + h] = s1hi; adst[(rlo + 1) * 8 + h] = s2hi; }
            }
        }
    }
    // ---- fused per-feature BN statistics ----
    if (STATS) {
        __shared__ float s_s[8][TC], s_q[8][TC];
#pragma unroll
        for (int j = 0; j < CT; j++) {
            int col = tcol * CT + j;
            float b = bias ? bias[col] : 0.f;
            float ps = 0.f, pq = 0.f;
#pragma unroll
            for (int p = 0; p < 4; p++) {
                int gr0 = r0 + trow * 8 + 2 * p;
                float lo, hi;
                UNPK2(lo, hi, acc2[p][j]);
                if (gr0 < nrows)     { float v = lo + b; ps += v; pq = fmaf(v, v, pq); }
                if (gr0 + 1 < nrows) { float v = hi + b; ps += v; pq = fmaf(v, v, pq); }
            }
            s_s[trow][col] = ps;
            s_q[trow][col] = pq;
        }
        __syncthreads();
        if (tid < TC) {
            float S = 0.f, Q = 0.f;
#pragma unroll
            for (int w = 0; w < 8; w++) { S += s_s[w][tid]; Q += s_q[w][tid]; }
            atomicAdd(&gsum[tid], S);
            atomicAdd(&gsq[tid],  Q);
        }
    }
}

// ======================= GAT aggregation (online softmax + BN stats) =======
// one warp per node; unrolled x2 for memory-level parallelism

__global__ void __launch_bounds__(256)
gat_aggregate(const float* __restrict__ hfeat,
              const float* __restrict__ asrc, const float* __restrict__ adst,
              const int* __restrict__ off, const int* __restrict__ csr,
              const float* __restrict__ bg, float* __restrict__ outp,
              float* gsum, float* gsq) {
    __shared__ float s_v[8][128];
    int gw = (blockIdx.x * blockDim.x + threadIdx.x) >> 5;
    int lane = threadIdx.x & 31;
    int wib = threadIdx.x >> 5;
    int head = lane >> 2;
    float ad = adst[gw * 8 + head];
    float mm = -INFINITY, den = 0.f;
    float4 acc = make_float4(0.f, 0.f, 0.f, 0.f);
    int s0 = off[gw], s1 = off[gw + 1];
    int i = s0;
    for (; i + 1 < s1; i += 2) {
        int sa = csr[i], sb = csr[i + 1];
        float ea = asrc[sa * 8 + head] + ad;
        float eb = asrc[sb * 8 + head] + ad;
        ea = (ea >= 0.f) ? ea : 0.2f * ea;
        eb = (eb >= 0.f) ? eb : 0.2f * eb;
        float4 ha = *(const float4*)&hfeat[(size_t)sa * 128 + lane * 4];
        float4 hb = *(const float4*)&hfeat[(size_t)sb * 128 + lane * 4];
        float m2 = fmaxf(ea, eb);
        if (m2 > mm) {
            float sc = __expf(mm - m2);
            den *= sc;
            acc.x *= sc; acc.y *= sc; acc.z *= sc; acc.w *= sc;
            mm = m2;
        }
        float pa = __expf(ea - mm);
        float pb = __expf(eb - mm);
        den += pa + pb;
        acc.x = fmaf(ha.x, pa, fmaf(hb.x, pb, acc.x));
        acc.y = fmaf(ha.y, pa, fmaf(hb.y, pb, acc.y));
        acc.z = fmaf(ha.z, pa, fmaf(hb.z, pb, acc.z));
        acc.w = fmaf(ha.w, pa, fmaf(hb.w, pb, acc.w));
    }
    if (i < s1) {
        int s = csr[i];
        float e = asrc[s * 8 + head] + ad;
        e = (e >= 0.f) ? e : 0.2f * e;
        if (e > mm) {
            float sc = __expf(mm - e);
            den *= sc;
            acc.x *= sc; acc.y *= sc; acc.z *= sc; acc.w *= sc;
            mm = e;
        }
        float p = __expf(e - mm);
        den += p;
        float4 hv = *(const float4*)&hfeat[(size_t)s * 128 + lane * 4];
        acc.x = fmaf(hv.x, p, acc.x);
        acc.y = fmaf(hv.y, p, acc.y);
        acc.z = fmaf(hv.z, p, acc.z);
        acc.w = fmaf(hv.w, p, acc.w);
    }
    float inv = 1.f / (den + 1e-16f);
    float4 bgv = *(const float4*)&bg[lane * 4];
    acc.x = fmaf(acc.x, inv, bgv.x);
    acc.y = fmaf(acc.y, inv, bgv.y);
    acc.z = fmaf(acc.z, inv, bgv.z);
    acc.w = fmaf(acc.w, inv, bgv.w);
    *(float4*)&outp[(size_t)gw * 128 + lane * 4] = acc;
    *(float4*)&s_v[wib][lane * 4] = acc;
    __syncthreads();
    int t = threadIdx.x;
    if (t < 128) {
        float S = 0.f, Q = 0.f;
#pragma unroll
        for (int w = 0; w < 8; w++) { float v = s_v[w][t]; S += v; Q = fmaf(v, v, Q); }
        atomicAdd(&gsum[t], S);
        atomicAdd(&gsq[t],  Q);
    }
}

// ======================= BN finalize + BN-ELU ==============================

__global__ void bn_finalize(const float* __restrict__ gs, const float* __restrict__ gq,
                            float* mean, float* rstd, int F) {
    int f = threadIdx.x;
    if (f < F) {
        double invN = 1.0 / (double)NN;
        double mu = (double)gs[f] * invN;
        double var = (double)gq[f] * invN - mu * mu;
        if (var < 0.0) var = 0.0;
        mean[f] = (float)mu;
        rstd[f] = rsqrtf((float)var + 1e-5f);
    }
}

__global__ void bn_elu_kernel(const float* __restrict__ x, const float* __restrict__ mean,
                              const float* __restrict__ rstd, const float* __restrict__ gamma,
                              const float* __restrict__ beta, float* __restrict__ out, int total) {
    int i = (blockIdx.x * blockDim.x + threadIdx.x) * 4;
    if (i >= total) return;
    float4 v = *(const float4*)&x[i];
    int f = i & 127;
    float r[4] = {v.x, v.y, v.z, v.w};
#pragma unroll
    for (int k = 0; k < 4; k++) {
        int ff = f + k;
        float t = (r[k] - mean[ff]) * rstd[ff] * gamma[ff] + beta[ff];
        r[k] = (t > 0.f) ? t : expm1f(t);
    }
    *(float4*)&out[i] = make_float4(r[0], r[1], r[2], r[3]);
}

// ======================= Edge scorer + gumbel gate =========================

__global__ void edge_logits_kernel(const float* __restrict__ prpc,
                                   const int* __restrict__ rowA, const int* __restrict__ colA,
                                   const float* __restrict__ gumbel,
                                   const float* __restrict__ bs1,
                                   const float* __restrict__ ws2,
                                   const float* __restrict__ bs2,
                                   float* __restrict__ wout, float* __restrict__ lrout) {
    __shared__ float sw2[64];
    __shared__ float sb1[64];
    if (threadIdx.x < 64) { sw2[threadIdx.x] = ws2[threadIdx.x]; sb1[threadIdx.x] = bs1[threadIdx.x]; }
    __syncthreads();
    int ge = (blockIdx.x * blockDim.x + threadIdx.x) >> 5;
    if (ge >= EE) return;
    int lane = threadIdx.x & 31;
    int r = rowA[ge];
    int c = colA[ge];
    float p0 = prpc[(size_t)r * 128 + lane]      + prpc[(size_t)c * 128 + 64 + lane] + sb1[lane];
    float p1 = prpc[(size_t)r * 128 + 32 + lane] + prpc[(size_t)c * 128 + 96 + lane] + sb1[32 + lane];
    p0 = fmaxf(p0, 0.f);
    p1 = fmaxf(p1, 0.f);
    float part = p0 * sw2[lane] + p1 * sw2[32 + lane];
#pragma unroll
    for (int d = 16; d; d >>= 1) part += __shfl_xor_sync(0xffffffffu, part, d);
    if (lane == 0) {
        float lr = part + bs2[0];
        lrout[ge] = lr;
        float g0 = gumbel[2 * (size_t)ge];
        float g1 = gumbel[2 * (size_t)ge + 1];
        wout[ge] = (lr + g1 > g0) ? 1.f : 0.f;
    }
}

// ==== sparse agg + fused Wc1 linear + BN stats =============================
// h_sparse row built per warp in smem, then row @ Wc1^T (64x128) + bc1 -> outC
// Wc1 cached in smem transposed [f][j]; BN stats accumulated per block.

__global__ void __launch_bounds__(256)
sparse_agg_wc1(const float* __restrict__ hbase,
               const int* __restrict__ off2,
               const int* __restrict__ col, const int* __restrict__ eid,
               const float* __restrict__ w,
               const float* __restrict__ Wc1, const float* __restrict__ bc1,
               float* __restrict__ outC, float* gsum, float* gsq) {
    __shared__ float sW1[128 * 64];    // [f*64 + j]
    __shared__ float srow[8][128];
    __shared__ float sc[8][64];
    __shared__ float sb[64];
    int tid = threadIdx.x;
    for (int idx = tid; idx < 64 * 128; idx += 256) {
        int j = idx >> 7, f = idx & 127;
        sW1[f * 64 + j] = Wc1[idx];
    }
    if (tid < 64) sb[tid] = bc1[tid];
    __syncthreads();

    int gw = (blockIdx.x * 256 + tid) >> 5;
    int lane = tid & 31;
    int wib = tid >> 5;

    float4 acc = *(const float4*)&hbase[(size_t)gw * 128 + lane * 4];
    int s0 = off2[gw], s1 = off2[gw + 1];
    int i = s0;
    for (; i + 1 < s1; i += 2) {
        int e0 = eid[i],  e1 = eid[i + 1];
        int c0 = col[i],  c1 = col[i + 1];
        float w0 = w[e0], w1 = w[e1];
        if (w0 != 0.f) {
            float4 h = *(const float4*)&hbase[(size_t)c0 * 128 + lane * 4];
            acc.x += h.x; acc.y += h.y; acc.z += h.z; acc.w += h.w;
        }
        if (w1 != 0.f) {
            float4 h = *(const float4*)&hbase[(size_t)c1 * 128 + lane * 4];
            acc.x += h.x; acc.y += h.y; acc.z += h.z; acc.w += h.w;
        }
    }
    if (i < s1) {
        int e = eid[i];
        if (w[e] != 0.f) {
            int c = col[i];
            float4 h = *(const float4*)&hbase[(size_t)c * 128 + lane * 4];
            acc.x += h.x; acc.y += h.y; acc.z += h.z; acc.w += h.w;
        }
    }
    *(float4*)&srow[wib][lane * 4] = acc;
    __syncwarp();

    // row @ Wc1^T: lane computes cols (lane, lane+32)
    float c0 = sb[lane], c1 = sb[lane + 32];
#pragma unroll 8
    for (int f = 0; f < 128; f++) {
        float rv = srow[wib][f];
        c0 = fmaf(rv, sW1[f * 64 + lane], c0);
        c1 = fmaf(rv, sW1[f * 64 + lane + 32], c1);
    }
    outC[(size_t)gw * 64 + lane]      = c0;
    outC[(size_t)gw * 64 + 32 + lane] = c1;
    sc[wib][lane] = c0;
    sc[wib][lane + 32] = c1;
    __syncthreads();
    if (tid < 64) {
        float S = 0.f, Q = 0.f;
#pragma unroll
        for (int ww = 0; ww < 8; ww++) { float v = sc[ww][tid]; S += v; Q = fmaf(v, v, Q); }
        atomicAdd(&gsum[tid], S);
        atomicAdd(&gsq[tid],  Q);
    }
}

// ======================= Classifier head ===================================

__global__ void __launch_bounds__(256)
classifier_kernel(const float* __restrict__ cpre, const float* __restrict__ mean,
                  const float* __restrict__ rstd, const float* __restrict__ gc,
                  const float* __restrict__ bec, const float* __restrict__ Wc2,
                  const float* __restrict__ bc2, float* __restrict__ outls) {
    __shared__ float sW[64 * 64];
    __shared__ float sb[40];
    __shared__ float sc[8][64];
    for (int idx = threadIdx.x; idx < 64 * 64; idx += blockDim.x) {
        int f = idx >> 6, j = idx & 63;
        sW[idx] = (j < 40) ? Wc2[j * 64 + f] : 0.f;
    }
    if (threadIdx.x < 40) sb[threadIdx.x] = bc2[threadIdx.x];
    __syncthreads();
    int gw = (blockIdx.x * blockDim.x + threadIdx.x) >> 5;
    int lane = threadIdx.x & 31;
    int wib = threadIdx.x >> 5;
    if (gw >= NN) return;
    float v0 = cpre[(size_t)gw * 64 + lane];
    float v1 = cpre[(size_t)gw * 64 + 32 + lane];
    int f0 = lane, f1 = lane + 32;
    sc[wib][lane]      = fmaxf((v0 - mean[f0]) * rstd[f0] * gc[f0] + bec[f0], 0.f);
    sc[wib][lane + 32] = fmaxf((v1 - mean[f1]) * rstd[f1] * gc[f1] + bec[f1], 0.f);
    __syncwarp();
    float l0 = sb[lane];
    float l1 = (lane < 8) ? sb[lane + 32] : 0.f;
#pragma unroll
    for (int f = 0; f < 64; f++) {
        float cv = sc[wib][f];
        l0 = fmaf(cv, sW[f * 64 + lane], l0);
        l1 = fmaf(cv, sW[f * 64 + lane + 32], l1);
    }
    float mx = fmaxf(l0, (lane < 8) ? l1 : -INFINITY);
#pragma unroll
    for (int d = 16; d; d >>= 1) mx = fmaxf(mx, __shfl_xor_sync(0xffffffffu, mx, d));
    float s = expf(l0 - mx) + ((lane < 8) ? expf(l1 - mx) : 0.f);
#pragma unroll
    for (int d = 16; d; d >>= 1) s += __shfl_xor_sync(0xffffffffu, s, d);
    float lse = mx + logf(s);
    outls[(size_t)gw * 40 + lane] = l0 - lse;
    if (lane < 8) outls[(size_t)gw * 40 + 32 + lane] = l1 - lse;
}

// ======================= Host orchestration ================================

extern "C" void kernel_launch(void* const* d_in, const int* in_sizes, int n_in,
                              void* d_out, int out_size) {
    (void)in_sizes; (void)n_in; (void)out_size;

    float* S = nullptr;
    cudaGetSymbolAddress((void**)&S, g_scratch);

    float* bufA = S;                       // N*128
    float* bufH = S + 6400000;             // N*128
    float* bufG = S + 12800000;            // N*128
    float* bufC = S + 19200000;            // N*64
    float* asrc = S + 22400000;            // N*8
    float* adst = S + 22800000;
    float* fpar = S + 23200000;
    float* mean1 = fpar,       * rstd1 = fpar + 128;
    float* mean2 = fpar + 256, * rstd2 = fpar + 384;
    float* meanc = fpar + 512, * rstdc = fpar + 640;
    float* stat  = S + 23201024;
    float* s1s = stat,       * s1q = stat + 128;
    float* s2s = stat + 256, * s2q = stat + 384;
    float* scs = stat + 512, * scq = stat + 576;
    float* Wf   = S + 23300000;            // 128*128 fused weight
    float* bf   = Wf + 16384;              // 128 fused bias
    int* ip    = (int*)(S + 24000000);
    int* rowA  = ip;
    int* colA  = rowA + EE;
    int* off1  = colA + EE;
    int* off2  = off1 + (NN + 1);
    int* cur1  = off2 + (NN + 1);
    int* cur2  = cur1 + NN;
    int* cnt1  = cur2 + NN;
    int* cnt2  = cnt1 + NN;
    int* csr1  = cnt2 + NN;
    int* csr2c = csr1 + (EE + NN);
    int* csr2e = csr2c + EE;
    int* flag64 = csr2e + EE;
    int* btot   = flag64 + 1;

    const float* x      = (const float*)d_in[0];
    const int*   eiw    = (const int*)d_in[1];
    const float* gumbel = (const float*)d_in[2];
    const float* W_res  = (const float*)d_in[3];
    const float* b_res  = (const float*)d_in[4];
    const float* Wg1    = (const float*)d_in[5];
    const float* as1    = (const float*)d_in[6];
    const float* ad1    = (const float*)d_in[7];
    const float* bg1    = (const float*)d_in[8];
    const float* g1     = (const float*)d_in[9];
    const float* be1    = (const float*)d_in[10];
    const float* Wg2    = (const float*)d_in[11];
    const float* as2    = (const float*)d_in[12];
    const float* ad2    = (const float*)d_in[13];
    const float* bg2    = (const float*)d_in[14];
    const float* g2     = (const float*)d_in[15];
    const float* be2    = (const float*)d_in[16];
    const float* Ws1    = (const float*)d_in[17];
    const float* bs1    = (const float*)d_in[18];
    const float* Ws2    = (const float*)d_in[19];
    const float* bs2    = (const float*)d_in[20];
    const float* Wc1    = (const float*)d_in[21];
    const float* bc1    = (const float*)d_in[22];
    const float* gc     = (const float*)d_in[23];
    const float* bec    = (const float*)d_in[24];
    const float* Wc2    = (const float*)d_in[25];
    const float* bc2    = (const float*)d_in[26];

    float* out_ls = (float*)d_out;
    float* out_w  = out_ls + (size_t)NN * OUTC;
    float* out_lr = out_w + EE;

    const int NB   = (NN + 255) / 256;
    const int EB   = (EE + 255) / 256;
    const int WRPN = (NN * 32) / 256;
    const int WRPE = (EE * 32) / 256;
    const int GEMG = (NN + 63) / 64;

    // ---- fork: CSR build on side stream, GEMMs on main stream ----
    cudaStream_t s1str;
    cudaEvent_t evFork, evJoin;
    cudaStreamCreateWithFlags(&s1str, cudaStreamNonBlocking);
    cudaEventCreateWithFlags(&evFork, cudaEventDisableTiming);
    cudaEventCreateWithFlags(&evJoin, cudaEventDisableTiming);

    cudaEventRecord(evFork, 0);
    cudaStreamWaitEvent(s1str, evFork, 0);

    // side stream: CSR build chain
    init_kernel<<<NB, 256, 0, s1str>>>(cnt1, cnt2, flag64, stat);
    detect_kernel<<<256, 256, 0, s1str>>>(eiw, flag64);
    convert_hist_kernel<<<EB, 256, 0, s1str>>>(eiw, flag64, rowA, colA, cnt1, cnt2);
    scan_p1<<<dim3(NTILE, 2), 256, 0, s1str>>>(cnt1, cnt2, btot);
    scan_p2<<<dim3(1, 2), 256, 0, s1str>>>(btot);
    scan_p3<<<dim3(NTILE, 2), 256, 0, s1str>>>(cnt1, cnt2, btot, off1, off2, cur1, cur2, csr1);
    fill_kernel<<<EB, 256, 0, s1str>>>(rowA, colA, cur1, csr1, cur2, csr2c, csr2e);
    cudaEventRecord(evJoin, s1str);

    // main stream: weight fusion, then fused h1 GEMM (+attention dots)
    wfuse_kernel<<<128, 128>>>(Wg1, W_res, b_res, Wf, bf);
    gemm_k128<128, false, true, false, false><<<GEMG, 128>>>(
        x, Wf, 128, 0, bf, bufH, 128, 0, NN,
        nullptr, nullptr, nullptr, nullptr, as1, ad1, asrc, adst, nullptr, nullptr);

    // join: aggregation needs CSR + stats-zeroing from side stream
    cudaStreamWaitEvent(0, evJoin, 0);

    gat_aggregate<<<WRPN, 256>>>(bufH, asrc, adst, off1, csr1, bg1, bufG, s1s, s1q);
    bn_finalize<<<1, 128>>>(s1s, s1q, mean1, rstd1, 128);

    // GAT layer 2 (BN+ELU of layer1 fused into A-load)
    gemm_k128<128, true, true, false, false><<<GEMG, 128>>>(
        bufG, Wg2, 128, 0, nullptr, bufH, 128, 0, NN,
        mean1, rstd1, g1, be1, as2, ad2, asrc, adst, nullptr, nullptr);
    gat_aggregate<<<WRPN, 256>>>(bufH, asrc, adst, off1, csr1, bg2, bufG, s2s, s2q);
    bn_finalize<<<1, 128>>>(s2s, s2q, mean2, rstd2, 128);
    bn_elu_kernel<<<(NN * 32 + 255) / 256, 256>>>(bufG, mean2, rstd2, g2, be2, bufA, NN * 128);
    // bufA = h_base

    // edge scorer: single merged SPLITW GEMM (pr | pc)
    gemm_k128<128, false, false, false, true><<<GEMG, 128>>>(
        bufA, Ws1, 256, 0, nullptr, bufH, 128, 0, NN,
        nullptr, nullptr, nullptr, nullptr, nullptr, nullptr, nullptr, nullptr, nullptr, nullptr);
    edge_logits_kernel<<<WRPE, 256>>>(bufH, rowA, colA, gumbel, bs1, Ws2, bs2, out_w, out_lr);

    // sparse aggregation + fused Wc1 linear + BN stats
    sparse_agg_wc1<<<WRPN, 256>>>(bufA, off2, csr2c, csr2e, out_w, Wc1, bc1, bufC, scs, scq);
    bn_finalize<<<1, 64>>>(scs, scq, meanc, rstdc, 64);
    classifier_kernel<<<WRPN, 256>>>(bufC, meanc, rstdc, gc, bec, Wc2, bc2, out_ls);
}

// round 12
// speedup vs baseline: 1.2683x; 1.2683x over previous
#include <cuda_runtime.h>
#include <cuda_bf16.h>
#include <cuda_pipeline.h>
#include <math.h>

#define NN 50000
#define EE 800000
#define OUTC 40
#define NTILE 196            // ceil(50000/256)

__device__ __align__(128) float g_scratch[29000000];

#define PACK2(dst, lo, hi) asm("mov.b64 %0, {%1, %2};" : "=l"(dst) : "f"(lo), "f"(hi))
#define UNPK2(lo, hi, v)   asm("mov.b64 {%0, %1}, %2;" : "=f"(lo), "=f"(hi) : "l"(v))
#define FMA2(acc, a, b)    asm("fma.rn.f32x2 %0, %1, %2, %0;" : "+l"(acc) : "l"(a), "l"(b))

// ======================= init: counts, flag, float stat accumulators =======
__global__ void init_kernel(int* c1, int* c2, int* flag64, float* statz) {
    int i = blockIdx.x * blockDim.x + threadIdx.x;
    if (i < NN) { c1[i] = 1; c2[i] = 0; }     // c1 starts at 1 (self-loop)
    if (i == 0) *flag64 = 1;
    if (i < 640) statz[i] = 0.f;
}

__global__ void detect_kernel(const int* __restrict__ w, int* flag64) {
    int any = 0;
    for (int i = blockIdx.x * blockDim.x + threadIdx.x; i < EE; i += gridDim.x * blockDim.x)
        any |= w[2 * i + 1];
    if (any) atomicAnd(flag64, 0);
}

// convert edge_index to int32 row/col AND histogram in one pass
__global__ void convert_hist_kernel(const int* __restrict__ w, const int* __restrict__ flag64,
                                    int* __restrict__ rowA, int* __restrict__ colA,
                                    int* c1, int* c2) {
    int e = blockIdx.x * blockDim.x + threadIdx.x;
    if (e >= EE) return;
    int r, c;
    if (*flag64) { r = w[2 * e]; c = w[2 * (EE + e)]; }
    else         { r = w[e];     c = w[EE + e]; }
    rowA[e] = r; colA[e] = c;
    atomicAdd(&c1[c], 1);
    atomicAdd(&c2[r], 1);
}

// ---- parallel 3-phase exclusive scan over two arrays (gridDim.y selects) ----
__global__ void scan_p1(const int* __restrict__ cnt1, const int* __restrict__ cnt2,
                        int* __restrict__ btot) {
    const int* cnt = blockIdx.y ? cnt2 : cnt1;
    __shared__ int sw[8];
    int idx = blockIdx.x * 256 + threadIdx.x;
    int v = (idx < NN) ? cnt[idx] : 0;
#pragma unroll
    for (int d = 16; d; d >>= 1) v += __shfl_xor_sync(0xffffffffu, v, d);
    if ((threadIdx.x & 31) == 0) sw[threadIdx.x >> 5] = v;
    __syncthreads();
    if (threadIdx.x == 0) {
        int s = 0;
#pragma unroll
        for (int i = 0; i < 8; i++) s += sw[i];
        btot[blockIdx.y * (NTILE + 1) + blockIdx.x] = s;
    }
}

__global__ void scan_p2(int* __restrict__ btot) {
    int* b = btot + blockIdx.y * (NTILE + 1);
    __shared__ int sw[8], sw2[9];
    int t = threadIdx.x, lane = t & 31, wid = t >> 5;
    int v = (t < NTILE) ? b[t] : 0;
    int inc = v;
#pragma unroll
    for (int d = 1; d < 32; d <<= 1) { int y = __shfl_up_sync(0xffffffffu, inc, d); if (lane >= d) inc += y; }
    if (lane == 31) sw[wid] = inc;
    __syncthreads();
    if (t == 0) { sw2[0] = 0; for (int i = 0; i < 8; i++) sw2[i + 1] = sw2[i] + sw[i]; }
    __syncthreads();
    int excl = sw2[wid] + inc - v;
    if (t < NTILE) b[t] = excl;
    if (t == 0) b[NTILE] = sw2[8];
}

// scan phase 3 + cursor init + self-loop placement
__global__ void scan_p3(const int* __restrict__ cnt1, const int* __restrict__ cnt2,
                        const int* __restrict__ btot,
                        int* __restrict__ off1, int* __restrict__ off2,
                        int* __restrict__ cur1, int* __restrict__ cur2, int* __restrict__ csr1) {
    const int* cnt = blockIdx.y ? cnt2 : cnt1;
    int* off = blockIdx.y ? off2 : off1;
    const int* b = btot + blockIdx.y * (NTILE + 1);
    __shared__ int sw[8], sw2[9];
    int t = threadIdx.x, lane = t & 31, wid = t >> 5;
    int idx = blockIdx.x * 256 + t;
    int v = (idx < NN) ? cnt[idx] : 0;
    int inc = v;
#pragma unroll
    for (int d = 1; d < 32; d <<= 1) { int y = __shfl_up_sync(0xffffffffu, inc, d); if (lane >= d) inc += y; }
    if (lane == 31) sw[wid] = inc;
    __syncthreads();
    if (t == 0) { sw2[0] = 0; for (int i = 0; i < 8; i++) sw2[i + 1] = sw2[i] + sw[i]; }
    __syncthreads();
    int excl = b[blockIdx.x] + sw2[wid] + inc - v;
    if (idx < NN) {
        off[idx] = excl;
        if (blockIdx.y == 0) { cur1[idx] = excl + 1; csr1[excl] = idx; }
        else                 cur2[idx] = excl;
    }
    if (blockIdx.x == 0 && t == 0) off[NN] = b[NTILE];
}

__global__ void fill_kernel(const int* __restrict__ rowA, const int* __restrict__ colA,
                            int* cur1, int* csr1,
                            int* cur2, int* csr2c, int* csr2e) {
    int e = blockIdx.x * blockDim.x + threadIdx.x;
    if (e >= EE) return;
    int r = rowA[e];
    int c = colA[e];
    int p = atomicAdd(&cur1[c], 1);
    csr1[p] = r;
    int q = atomicAdd(&cur2[r], 1);
    csr2c[q] = c;
    csr2e[q] = e;
}

// ======================= weight fusion: Wf = Wg1 @ W_res, bf = Wg1 @ b_res ==
__global__ void wfuse_kernel(const float* __restrict__ Wg1, const float* __restrict__ W_res,
                             const float* __restrict__ b_res,
                             float* __restrict__ Wf, float* __restrict__ bf) {
    __shared__ float sWg[128];
    __shared__ float red[128];
    int d = blockIdx.x, k = threadIdx.x;
    sWg[k] = Wg1[d * 128 + k];
    __syncthreads();
    float s = 0.f;
#pragma unroll 8
    for (int j = 0; j < 128; j++) s = fmaf(sWg[j], W_res[j * 128 + k], s);
    Wf[d * 128 + k] = s;
    red[k] = sWg[k] * b_res[k];
    __syncthreads();
    for (int st = 64; st; st >>= 1) { if (k < st) red[k] += red[k + st]; __syncthreads(); }
    if (k == 0) bf[d] = red[0];
}

// ======================= GEMM (K = 128 fixed, f32x2 FMA) ====================
// non-BNIN path: cp.async double-buffered tile loads overlapped with compute.
// BNIN path: synchronous loads (ELU transform applied at load time).

template <int TC, bool BNIN, bool ATTN, bool STATS, bool SPLITW>
__global__ void __launch_bounds__(128, 4)
gemm_k128(const float* __restrict__ A, const float* __restrict__ W,
          int ldw, int woff, const float* __restrict__ bias,
          float* __restrict__ out, int opitch, int ocol, int nrows,
          const float* __restrict__ bnm, const float* __restrict__ bnr,
          const float* __restrict__ bng, const float* __restrict__ bnb,
          const float* __restrict__ as, const float* __restrict__ ad,
          float* __restrict__ asrc, float* __restrict__ adst,
          float* gsum, float* gsq) {
    constexpr int CT = TC / 16;
    constexpr int PA = 68;
    constexpr int PW = TC + 4;
    constexpr int NBUF = BNIN ? 1 : 2;
    __shared__ float sA[NBUF][32 * PA];
    __shared__ float sW[NBUF][32 * PW];
    const int tid = threadIdx.x;
    const int trow = tid >> 4;     // 0..7
    const int tcol = tid & 15;     // 0..15
    const int r0 = blockIdx.x * 64;

    unsigned long long acc2[4][CT];   // row-pairs x cols
#pragma unroll
    for (int p = 0; p < 4; p++)
#pragma unroll
        for (int j = 0; j < CT; j++) acc2[p][j] = 0ull;

    // async tile loader (non-BNIN only)
    auto loadTiles = [&](int buf, int kb) {
#pragma unroll
        for (int i = 0; i < 16; i++) {
            int idx = tid + i * 128;
            int row = idx >> 5, kk = idx & 31;
            int gr = r0 + row;
            if (gr < nrows)
                __pipeline_memcpy_async(&sA[buf][kk * PA + row],
                                        &A[(size_t)gr * 128 + kb + kk], 4);
            else
                sA[buf][kk * PA + row] = 0.f;
        }
#pragma unroll
        for (int i = 0; i < (TC * 32) / 128; i++) {
            int idx = tid + i * 128;
            int col = idx >> 5, kk = idx & 31;
            int wrow = SPLITW ? (col & 63) : col;
            int wko  = SPLITW ? ((col >> 6) * 128) : 0;
            __pipeline_memcpy_async(&sW[buf][kk * PW + col],
                                    &W[(size_t)wrow * ldw + woff + wko + kb + kk], 4);
        }
        __pipeline_commit();
    };

    if (!BNIN) loadTiles(0, 0);
    int buf = 0;

    for (int kb = 0; kb < 128; kb += 32) {
        if (BNIN) {
            float bm, br, bgm, bbt;
            int kf = kb + (tid & 31);
            bm = bnm[kf]; br = bnr[kf]; bgm = bng[kf]; bbt = bnb[kf];
            __syncthreads();
#pragma unroll
            for (int i = 0; i < 16; i++) {
                int idx = tid + i * 128;
                int row = idx >> 5, kk = idx & 31;
                int gr = r0 + row;
                float v = (gr < nrows) ? A[(size_t)gr * 128 + kb + kk] : 0.f;
                if (gr < nrows) {
                    float t = (v - bm) * br * bgm + bbt;
                    v = (t > 0.f) ? t : expm1f(t);
                }
                sA[0][kk * PA + row] = v;
            }
#pragma unroll
            for (int i = 0; i < (TC * 32) / 128; i++) {
                int idx = tid + i * 128;
                int col = idx >> 5, kk = idx & 31;
                int wrow = SPLITW ? (col & 63) : col;
                int wko  = SPLITW ? ((col >> 6) * 128) : 0;
                sW[0][kk * PW + col] = W[(size_t)wrow * ldw + woff + wko + kb + kk];
            }
            __syncthreads();
        } else {
            if (kb + 32 < 128) loadTiles(buf ^ 1, kb + 32);
            if (kb + 32 < 128) __pipeline_wait_prior(1);
            else               __pipeline_wait_prior(0);
            __syncthreads();
        }
        const float* cA = sA[BNIN ? 0 : buf];
        const float* cW = sW[BNIN ? 0 : buf];
#pragma unroll
        for (int kk = 0; kk < 32; kk++) {
            unsigned long long ap[4];
#pragma unroll
            for (int p = 0; p < 4; p++)
                ap[p] = *(const unsigned long long*)&cA[kk * PA + trow * 8 + 2 * p];
            float w[CT];
#pragma unroll
            for (int j = 0; j < CT; j += 4) {
                float4 wv = *(const float4*)&cW[kk * PW + tcol * CT + j];
                w[j] = wv.x; w[j + 1] = wv.y; w[j + 2] = wv.z; w[j + 3] = wv.w;
            }
            unsigned long long wd[CT];
#pragma unroll
            for (int j = 0; j < CT; j++) PACK2(wd[j], w[j], w[j]);
#pragma unroll
            for (int p = 0; p < 4; p++)
#pragma unroll
                for (int j = 0; j < CT; j++) FMA2(acc2[p][j], ap[p], wd[j]);
        }
        if (!BNIN) {
            __syncthreads();   // all warps done with buf before it is refilled
            buf ^= 1;
        }
    }
    // ---- store ----
#pragma unroll
    for (int p = 0; p < 4; p++) {
        int gr0 = r0 + trow * 8 + 2 * p;
#pragma unroll
        for (int j = 0; j < CT; j++) {
            int col = tcol * CT + j;
            float b = bias ? bias[col] : 0.f;
            float lo, hi;
            UNPK2(lo, hi, acc2[p][j]);
            if (gr0 < nrows)     out[(size_t)gr0 * opitch + ocol + col]       = lo + b;
            if (gr0 + 1 < nrows) out[(size_t)(gr0 + 1) * opitch + ocol + col] = hi + b;
        }
    }
    // ---- fused attention dots (TC=128 only) ----
    if (ATTN) {
#pragma unroll
        for (int p = 0; p < 4; p++) {
            float s1lo = 0.f, s2lo = 0.f, s1hi = 0.f, s2hi = 0.f;
#pragma unroll
            for (int j = 0; j < CT; j++) {
                int col = tcol * CT + j;
                float aS = __ldg(&as[col]), aD = __ldg(&ad[col]);
                float lo, hi;
                UNPK2(lo, hi, acc2[p][j]);
                s1lo = fmaf(lo, aS, s1lo); s2lo = fmaf(lo, aD, s2lo);
                s1hi = fmaf(hi, aS, s1hi); s2hi = fmaf(hi, aD, s2hi);
            }
            s1lo += __shfl_xor_sync(0xffffffffu, s1lo, 1);
            s2lo += __shfl_xor_sync(0xffffffffu, s2lo, 1);
            s1hi += __shfl_xor_sync(0xffffffffu, s1hi, 1);
            s2hi += __shfl_xor_sync(0xffffffffu, s2hi, 1);
            if (!(tcol & 1)) {
                int h = tcol >> 1;
                int rlo = r0 + trow * 8 + 2 * p;
                if (rlo < nrows)     { asrc[rlo * 8 + h] = s1lo;       adst[rlo * 8 + h] = s2lo; }
                if (rlo + 1 < nrows) { asrc[(rlo + 1) * 8 + h] = s1hi; adst[(rlo + 1) * 8 + h] = s2hi; }
            }
        }
    }
    // ---- fused per-feature BN statistics ----
    if (STATS) {
        __shared__ float s_s[8][TC], s_q[8][TC];
#pragma unroll
        for (int j = 0; j < CT; j++) {
            int col = tcol * CT + j;
            float b = bias ? bias[col] : 0.f;
            float ps = 0.f, pq = 0.f;
#pragma unroll
            for (int p = 0; p < 4; p++) {
                int gr0 = r0 + trow * 8 + 2 * p;
                float lo, hi;
                UNPK2(lo, hi, acc2[p][j]);
                if (gr0 < nrows)     { float v = lo + b; ps += v; pq = fmaf(v, v, pq); }
                if (gr0 + 1 < nrows) { float v = hi + b; ps += v; pq = fmaf(v, v, pq); }
            }
            s_s[trow][col] = ps;
            s_q[trow][col] = pq;
        }
        __syncthreads();
        if (tid < TC) {
            float S = 0.f, Q = 0.f;
#pragma unroll
            for (int w = 0; w < 8; w++) { S += s_s[w][tid]; Q += s_q[w][tid]; }
            atomicAdd(&gsum[tid], S);
            atomicAdd(&gsq[tid],  Q);
        }
    }
}

// ======================= GAT aggregation (online softmax + BN stats) =======
// one warp per node; unrolled x2 for memory-level parallelism

__global__ void __launch_bounds__(256)
gat_aggregate(const float* __restrict__ hfeat,
              const float* __restrict__ asrc, const float* __restrict__ adst,
              const int* __restrict__ off, const int* __restrict__ csr,
              const float* __restrict__ bg, float* __restrict__ outp,
              float* gsum, float* gsq) {
    __shared__ float s_v[8][128];
    int gw = (blockIdx.x * blockDim.x + threadIdx.x) >> 5;
    int lane = threadIdx.x & 31;
    int wib = threadIdx.x >> 5;
    int head = lane >> 2;
    float ad = adst[gw * 8 + head];
    float mm = -INFINITY, den = 0.f;
    float4 acc = make_float4(0.f, 0.f, 0.f, 0.f);
    int s0 = off[gw], s1 = off[gw + 1];
    int i = s0;
    for (; i + 1 < s1; i += 2) {
        int sa = csr[i], sb = csr[i + 1];
        float ea = asrc[sa * 8 + head] + ad;
        float eb = asrc[sb * 8 + head] + ad;
        ea = (ea >= 0.f) ? ea : 0.2f * ea;
        eb = (eb >= 0.f) ? eb : 0.2f * eb;
        float4 ha = *(const float4*)&hfeat[(size_t)sa * 128 + lane * 4];
        float4 hb = *(const float4*)&hfeat[(size_t)sb * 128 + lane * 4];
        float m2 = fmaxf(ea, eb);
        if (m2 > mm) {
            float sc = __expf(mm - m2);
            den *= sc;
            acc.x *= sc; acc.y *= sc; acc.z *= sc; acc.w *= sc;
            mm = m2;
        }
        float pa = __expf(ea - mm);
        float pb = __expf(eb - mm);
        den += pa + pb;
        acc.x = fmaf(ha.x, pa, fmaf(hb.x, pb, acc.x));
        acc.y = fmaf(ha.y, pa, fmaf(hb.y, pb, acc.y));
        acc.z = fmaf(ha.z, pa, fmaf(hb.z, pb, acc.z));
        acc.w = fmaf(ha.w, pa, fmaf(hb.w, pb, acc.w));
    }
    if (i < s1) {
        int s = csr[i];
        float e = asrc[s * 8 + head] + ad;
        e = (e >= 0.f) ? e : 0.2f * e;
        if (e > mm) {
            float sc = __expf(mm - e);
            den *= sc;
            acc.x *= sc; acc.y *= sc; acc.z *= sc; acc.w *= sc;
            mm = e;
        }
        float p = __expf(e - mm);
        den += p;
        float4 hv = *(const float4*)&hfeat[(size_t)s * 128 + lane * 4];
        acc.x = fmaf(hv.x, p, acc.x);
        acc.y = fmaf(hv.y, p, acc.y);
        acc.z = fmaf(hv.z, p, acc.z);
        acc.w = fmaf(hv.w, p, acc.w);
    }
    float inv = 1.f / (den + 1e-16f);
    float4 bgv = *(const float4*)&bg[lane * 4];
    acc.x = fmaf(acc.x, inv, bgv.x);
    acc.y = fmaf(acc.y, inv, bgv.y);
    acc.z = fmaf(acc.z, inv, bgv.z);
    acc.w = fmaf(acc.w, inv, bgv.w);
    *(float4*)&outp[(size_t)gw * 128 + lane * 4] = acc;
    *(float4*)&s_v[wib][lane * 4] = acc;
    __syncthreads();
    int t = threadIdx.x;
    if (t < 128) {
        float S = 0.f, Q = 0.f;
#pragma unroll
        for (int w = 0; w < 8; w++) { float v = s_v[w][t]; S += v; Q = fmaf(v, v, Q); }
        atomicAdd(&gsum[t], S);
        atomicAdd(&gsq[t],  Q);
    }
}

// ======================= BN finalize + BN-ELU ==============================

__global__ void bn_finalize(const float* __restrict__ gs, const float* __restrict__ gq,
                            float* mean, float* rstd, int F) {
    int f = threadIdx.x;
    if (f < F) {
        double invN = 1.0 / (double)NN;
        double mu = (double)gs[f] * invN;
        double var = (double)gq[f] * invN - mu * mu;
        if (var < 0.0) var = 0.0;
        mean[f] = (float)mu;
        rstd[f] = rsqrtf((float)var + 1e-5f);
    }
}

__global__ void bn_elu_kernel(const float* __restrict__ x, const float* __restrict__ mean,
                              const float* __restrict__ rstd, const float* __restrict__ gamma,
                              const float* __restrict__ beta, float* __restrict__ out, int total) {
    int i = (blockIdx.x * blockDim.x + threadIdx.x) * 4;
    if (i >= total) return;
    float4 v = *(const float4*)&x[i];
    int f = i & 127;
    float r[4] = {v.x, v.y, v.z, v.w};
#pragma unroll
    for (int k = 0; k < 4; k++) {
        int ff = f + k;
        float t = (r[k] - mean[ff]) * rstd[ff] * gamma[ff] + beta[ff];
        r[k] = (t > 0.f) ? t : expm1f(t);
    }
    *(float4*)&out[i] = make_float4(r[0], r[1], r[2], r[3]);
}

// ======================= Edge scorer + gumbel gate =========================

__global__ void edge_logits_kernel(const float* __restrict__ prpc,
                                   const int* __restrict__ rowA, const int* __restrict__ colA,
                                   const float* __restrict__ gumbel,
                                   const float* __restrict__ bs1,
                                   const float* __restrict__ ws2,
                                   const float* __restrict__ bs2,
                                   float* __restrict__ wout, float* __restrict__ lrout) {
    __shared__ float sw2[64];
    __shared__ float sb1[64];
    if (threadIdx.x < 64) { sw2[threadIdx.x] = ws2[threadIdx.x]; sb1[threadIdx.x] = bs1[threadIdx.x]; }
    __syncthreads();
    int ge = (blockIdx.x * blockDim.x + threadIdx.x) >> 5;
    if (ge >= EE) return;
    int lane = threadIdx.x & 31;
    int r = rowA[ge];
    int c = colA[ge];
    float p0 = prpc[(size_t)r * 128 + lane]      + prpc[(size_t)c * 128 + 64 + lane] + sb1[lane];
    float p1 = prpc[(size_t)r * 128 + 32 + lane] + prpc[(size_t)c * 128 + 96 + lane] + sb1[32 + lane];
    p0 = fmaxf(p0, 0.f);
    p1 = fmaxf(p1, 0.f);
    float part = p0 * sw2[lane] + p1 * sw2[32 + lane];
#pragma unroll
    for (int d = 16; d; d >>= 1) part += __shfl_xor_sync(0xffffffffu, part, d);
    if (lane == 0) {
        float lr = part + bs2[0];
        lrout[ge] = lr;
        float g0 = gumbel[2 * (size_t)ge];
        float g1 = gumbel[2 * (size_t)ge + 1];
        wout[ge] = (lr + g1 > g0) ? 1.f : 0.f;
    }
}

// h_sparse = h_base + segment_sum(weights * h_base[col], row), unrolled x2
__global__ void sparse_agg_kernel(const float* __restrict__ hbase,
                                  const int* __restrict__ off2,
                                  const int* __restrict__ col, const int* __restrict__ eid,
                                  const float* __restrict__ w, float* __restrict__ outp) {
    int gw = (blockIdx.x * blockDim.x + threadIdx.x) >> 5;
    if (gw >= NN) return;
    int lane = threadIdx.x & 31;
    float4 acc = *(const float4*)&hbase[(size_t)gw * 128 + lane * 4];
    int s0 = off2[gw], s1 = off2[gw + 1];
    int i = s0;
    for (; i + 1 < s1; i += 2) {
        int e0 = eid[i],  e1 = eid[i + 1];
        int c0 = col[i],  c1 = col[i + 1];
        float w0 = w[e0], w1 = w[e1];
        if (w0 != 0.f) {
            float4 h = *(const float4*)&hbase[(size_t)c0 * 128 + lane * 4];
            acc.x += h.x; acc.y += h.y; acc.z += h.z; acc.w += h.w;
        }
        if (w1 != 0.f) {
            float4 h = *(const float4*)&hbase[(size_t)c1 * 128 + lane * 4];
            acc.x += h.x; acc.y += h.y; acc.z += h.z; acc.w += h.w;
        }
    }
    if (i < s1) {
        int e = eid[i];
        if (w[e] != 0.f) {
            int c = col[i];
            float4 h = *(const float4*)&hbase[(size_t)c * 128 + lane * 4];
            acc.x += h.x; acc.y += h.y; acc.z += h.z; acc.w += h.w;
        }
    }
    *(float4*)&outp[(size_t)gw * 128 + lane * 4] = acc;
}

// ======================= Classifier head ===================================

__global__ void __launch_bounds__(256)
classifier_kernel(const float* __restrict__ cpre, const float* __restrict__ mean,
                  const float* __restrict__ rstd, const float* __restrict__ gc,
                  const float* __restrict__ bec, const float* __restrict__ Wc2,
                  const float* __restrict__ bc2, float* __restrict__ outls) {
    __shared__ float sW[64 * 64];
    __shared__ float sb[40];
    __shared__ float sc[8][64];
    for (int idx = threadIdx.x; idx < 64 * 64; idx += blockDim.x) {
        int f = idx >> 6, j = idx & 63;
        sW[idx] = (j < 40) ? Wc2[j * 64 + f] : 0.f;
    }
    if (threadIdx.x < 40) sb[threadIdx.x] = bc2[threadIdx.x];
    __syncthreads();
    int gw = (blockIdx.x * blockDim.x + threadIdx.x) >> 5;
    int lane = threadIdx.x & 31;
    int wib = threadIdx.x >> 5;
    if (gw >= NN) return;
    float v0 = cpre[(size_t)gw * 64 + lane];
    float v1 = cpre[(size_t)gw * 64 + 32 + lane];
    int f0 = lane, f1 = lane + 32;
    sc[wib][lane]      = fmaxf((v0 - mean[f0]) * rstd[f0] * gc[f0] + bec[f0], 0.f);
    sc[wib][lane + 32] = fmaxf((v1 - mean[f1]) * rstd[f1] * gc[f1] + bec[f1], 0.f);
    __syncwarp();
    float l0 = sb[lane];
    float l1 = (lane < 8) ? sb[lane + 32] : 0.f;
#pragma unroll
    for (int f = 0; f < 64; f++) {
        float cv = sc[wib][f];
        l0 = fmaf(cv, sW[f * 64 + lane], l0);
        l1 = fmaf(cv, sW[f * 64 + lane + 32], l1);
    }
    float mx = fmaxf(l0, (lane < 8) ? l1 : -INFINITY);
#pragma unroll
    for (int d = 16; d; d >>= 1) mx = fmaxf(mx, __shfl_xor_sync(0xffffffffu, mx, d));
    float s = expf(l0 - mx) + ((lane < 8) ? expf(l1 - mx) : 0.f);
#pragma unroll
    for (int d = 16; d; d >>= 1) s += __shfl_xor_sync(0xffffffffu, s, d);
    float lse = mx + logf(s);
    outls[(size_t)gw * 40 + lane] = l0 - lse;
    if (lane < 8) outls[(size_t)gw * 40 + 32 + lane] = l1 - lse;
}

// ======================= Host orchestration ================================

extern "C" void kernel_launch(void* const* d_in, const int* in_sizes, int n_in,
                              void* d_out, int out_size) {
    (void)in_sizes; (void)n_in; (void)out_size;

    float* S = nullptr;
    cudaGetSymbolAddress((void**)&S, g_scratch);

    float* bufA = S;                       // N*128
    float* bufH = S + 6400000;             // N*128
    float* bufG = S + 12800000;            // N*128
    float* bufC = S + 19200000;            // N*64
    float* asrc = S + 22400000;            // N*8
    float* adst = S + 22800000;
    float* fpar = S + 23200000;
    float* mean1 = fpar,       * rstd1 = fpar + 128;
    float* mean2 = fpar + 256, * rstd2 = fpar + 384;
    float* meanc = fpar + 512, * rstdc = fpar + 640;
    float* stat  = S + 23201024;
    float* s1s = stat,       * s1q = stat + 128;
    float* s2s = stat + 256, * s2q = stat + 384;
    float* scs = stat + 512, * scq = stat + 576;
    float* Wf   = S + 23300000;            // 128*128 fused weight
    float* bf   = Wf + 16384;              // 128 fused bias
    int* ip    = (int*)(S + 24000000);
    int* rowA  = ip;
    int* colA  = rowA + EE;
    int* off1  = colA + EE;
    int* off2  = off1 + (NN + 1);
    int* cur1  = off2 + (NN + 1);
    int* cur2  = cur1 + NN;
    int* cnt1  = cur2 + NN;
    int* cnt2  = cnt1 + NN;
    int* csr1  = cnt2 + NN;
    int* csr2c = csr1 + (EE + NN);
    int* csr2e = csr2c + EE;
    int* flag64 = csr2e + EE;
    int* btot   = flag64 + 1;

    const float* x      = (const float*)d_in[0];
    const int*   eiw    = (const int*)d_in[1];
    const float* gumbel = (const float*)d_in[2];
    const float* W_res  = (const float*)d_in[3];
    const float* b_res  = (const float*)d_in[4];
    const float* Wg1    = (const float*)d_in[5];
    const float* as1    = (const float*)d_in[6];
    const float* ad1    = (const float*)d_in[7];
    const float* bg1    = (const float*)d_in[8];
    const float* g1     = (const float*)d_in[9];
    const float* be1    = (const float*)d_in[10];
    const float* Wg2    = (const float*)d_in[11];
    const float* as2    = (const float*)d_in[12];
    const float* ad2    = (const float*)d_in[13];
    const float* bg2    = (const float*)d_in[14];
    const float* g2     = (const float*)d_in[15];
    const float* be2    = (const float*)d_in[16];
    const float* Ws1    = (const float*)d_in[17];
    const float* bs1    = (const float*)d_in[18];
    const float* Ws2    = (const float*)d_in[19];
    const float* bs2    = (const float*)d_in[20];
    const float* Wc1    = (const float*)d_in[21];
    const float* bc1    = (const float*)d_in[22];
    const float* gc     = (const float*)d_in[23];
    const float* bec    = (const float*)d_in[24];
    const float* Wc2    = (const float*)d_in[25];
    const float* bc2    = (const float*)d_in[26];

    float* out_ls = (float*)d_out;
    float* out_w  = out_ls + (size_t)NN * OUTC;
    float* out_lr = out_w + EE;

    const int NB   = (NN + 255) / 256;
    const int EB   = (EE + 255) / 256;
    const int WRPN = (NN * 32) / 256;
    const int WRPE = (EE * 32) / 256;
    const int GEMG = (NN + 63) / 64;

    // ---- fork: CSR build on side stream, GEMMs on main stream ----
    cudaStream_t s1str;
    cudaEvent_t evFork, evJoin;
    cudaStreamCreateWithFlags(&s1str, cudaStreamNonBlocking);
    cudaEventCreateWithFlags(&evFork, cudaEventDisableTiming);
    cudaEventCreateWithFlags(&evJoin, cudaEventDisableTiming);

    cudaEventRecord(evFork, 0);
    cudaStreamWaitEvent(s1str, evFork, 0);

    // side stream: CSR build chain
    init_kernel<<<NB, 256, 0, s1str>>>(cnt1, cnt2, flag64, stat);
    detect_kernel<<<256, 256, 0, s1str>>>(eiw, flag64);
    convert_hist_kernel<<<EB, 256, 0, s1str>>>(eiw, flag64, rowA, colA, cnt1, cnt2);
    scan_p1<<<dim3(NTILE, 2), 256, 0, s1str>>>(cnt1, cnt2, btot);
    scan_p2<<<dim3(1, 2), 256, 0, s1str>>>(btot);
    scan_p3<<<dim3(NTILE, 2), 256, 0, s1str>>>(cnt1, cnt2, btot, off1, off2, cur1, cur2, csr1);
    fill_kernel<<<EB, 256, 0, s1str>>>(rowA, colA, cur1, csr1, cur2, csr2c, csr2e);
    cudaEventRecord(evJoin, s1str);

    // main stream: weight fusion, then fused h1 GEMM (+attention dots)
    wfuse_kernel<<<128, 128>>>(Wg1, W_res, b_res, Wf, bf);
    gemm_k128<128, false, true, false, false><<<GEMG, 128>>>(
        x, Wf, 128, 0, bf, bufH, 128, 0, NN,
        nullptr, nullptr, nullptr, nullptr, as1, ad1, asrc, adst, nullptr, nullptr);

    // join: aggregation needs CSR + stats-zeroing from side stream
    cudaStreamWaitEvent(0, evJoin, 0);

    gat_aggregate<<<WRPN, 256>>>(bufH, asrc, adst, off1, csr1, bg1, bufG, s1s, s1q);
    bn_finalize<<<1, 128>>>(s1s, s1q, mean1, rstd1, 128);

    // GAT layer 2 (BN+ELU of layer1 fused into A-load)
    gemm_k128<128, true, true, false, false><<<GEMG, 128>>>(
        bufG, Wg2, 128, 0, nullptr, bufH, 128, 0, NN,
        mean1, rstd1, g1, be1, as2, ad2, asrc, adst, nullptr, nullptr);
    gat_aggregate<<<WRPN, 256>>>(bufH, asrc, adst, off1, csr1, bg2, bufG, s2s, s2q);
    bn_finalize<<<1, 128>>>(s2s, s2q, mean2, rstd2, 128);
    bn_elu_kernel<<<(NN * 32 + 255) / 256, 256>>>(bufG, mean2, rstd2, g2, be2, bufA, NN * 128);
    // bufA = h_base

    // edge scorer: single merged SPLITW GEMM (pr | pc)
    gemm_k128<128, false, false, false, true><<<GEMG, 128>>>(
        bufA, Ws1, 256, 0, nullptr, bufH, 128, 0, NN,
        nullptr, nullptr, nullptr, nullptr, nullptr, nullptr, nullptr, nullptr, nullptr, nullptr);
    edge_logits_kernel<<<WRPE, 256>>>(bufH, rowA, colA, gumbel, bs1, Ws2, bs2, out_w, out_lr);

    // sparse aggregation
    sparse_agg_kernel<<<WRPN, 256>>>(bufA, off2, csr2c, csr2e, out_w, bufG);

    // classifier (BN stats fused into GEMM)
    gemm_k128<64, false, false, true, false><<<GEMG, 128>>>(
        bufG, Wc1, 128, 0, bc1, bufC, 64, 0, NN,
        nullptr, nullptr, nullptr, nullptr, nullptr, nullptr, nullptr, nullptr, scs, scq);
    bn_finalize<<<1, 64>>>(scs, scq, meanc, rstdc, 64);
    classifier_kernel<<<WRPN, 256>>>(bufC, meanc, rstdc, gc, bec, Wc2, bc2, out_ls);
}

// round 13
// speedup vs baseline: 1.4710x; 1.1598x over previous
#include <cuda_runtime.h>
#include <cuda_bf16.h>
#include <cuda_pipeline.h>
#include <math.h>

#define NN 50000
#define EE 800000
#define OUTC 40
#define NTILE 196            // ceil(50000/256)

__device__ __align__(128) float g_scratch[29000000];

#define PACK2(dst, lo, hi) asm("mov.b64 %0, {%1, %2};" : "=l"(dst) : "f"(lo), "f"(hi))
#define UNPK2(lo, hi, v)   asm("mov.b64 {%0, %1}, %2;" : "=f"(lo), "=f"(hi) : "l"(v))
#define FMA2(acc, a, b)    asm("fma.rn.f32x2 %0, %1, %2, %0;" : "+l"(acc) : "l"(a), "l"(b))

// ======================= init: counts, flag, float stat accumulators =======
__global__ void init_kernel(int* c1, int* c2, int* flag64, float* statz) {
    int i = blockIdx.x * blockDim.x + threadIdx.x;
    if (i < NN) { c1[i] = 1; c2[i] = 0; }     // c1 starts at 1 (self-loop)
    if (i == 0) *flag64 = 1;
    if (i < 640) statz[i] = 0.f;
}

__global__ void detect_kernel(const int* __restrict__ w, int* flag64) {
    int any = 0;
    for (int i = blockIdx.x * blockDim.x + threadIdx.x; i < EE; i += gridDim.x * blockDim.x)
        any |= w[2 * i + 1];
    if (any) atomicAnd(flag64, 0);
}

// convert edge_index to int32 row/col AND histogram in one pass
__global__ void convert_hist_kernel(const int* __restrict__ w, const int* __restrict__ flag64,
                                    int* __restrict__ rowA, int* __restrict__ colA,
                                    int* c1, int* c2) {
    int e = blockIdx.x * blockDim.x + threadIdx.x;
    if (e >= EE) return;
    int r, c;
    if (*flag64) { r = w[2 * e]; c = w[2 * (EE + e)]; }
    else         { r = w[e];     c = w[EE + e]; }
    rowA[e] = r; colA[e] = c;
    atomicAdd(&c1[c], 1);
    atomicAdd(&c2[r], 1);
}

// ---- parallel 3-phase exclusive scan over two arrays (gridDim.y selects) ----
__global__ void scan_p1(const int* __restrict__ cnt1, const int* __restrict__ cnt2,
                        int* __restrict__ btot) {
    const int* cnt = blockIdx.y ? cnt2 : cnt1;
    __shared__ int sw[8];
    int idx = blockIdx.x * 256 + threadIdx.x;
    int v = (idx < NN) ? cnt[idx] : 0;
#pragma unroll
    for (int d = 16; d; d >>= 1) v += __shfl_xor_sync(0xffffffffu, v, d);
    if ((threadIdx.x & 31) == 0) sw[threadIdx.x >> 5] = v;
    __syncthreads();
    if (threadIdx.x == 0) {
        int s = 0;
#pragma unroll
        for (int i = 0; i < 8; i++) s += sw[i];
        btot[blockIdx.y * (NTILE + 1) + blockIdx.x] = s;
    }
}

__global__ void scan_p2(int* __restrict__ btot) {
    int* b = btot + blockIdx.y * (NTILE + 1);
    __shared__ int sw[8], sw2[9];
    int t = threadIdx.x, lane = t & 31, wid = t >> 5;
    int v = (t < NTILE) ? b[t] : 0;
    int inc = v;
#pragma unroll
    for (int d = 1; d < 32; d <<= 1) { int y = __shfl_up_sync(0xffffffffu, inc, d); if (lane >= d) inc += y; }
    if (lane == 31) sw[wid] = inc;
    __syncthreads();
    if (t == 0) { sw2[0] = 0; for (int i = 0; i < 8; i++) sw2[i + 1] = sw2[i] + sw[i]; }
    __syncthreads();
    int excl = sw2[wid] + inc - v;
    if (t < NTILE) b[t] = excl;
    if (t == 0) b[NTILE] = sw2[8];
}

// scan phase 3 + cursor init + self-loop placement
__global__ void scan_p3(const int* __restrict__ cnt1, const int* __restrict__ cnt2,
                        const int* __restrict__ btot,
                        int* __restrict__ off1, int* __restrict__ off2,
                        int* __restrict__ cur1, int* __restrict__ cur2, int* __restrict__ csr1) {
    const int* cnt = blockIdx.y ? cnt2 : cnt1;
    int* off = blockIdx.y ? off2 : off1;
    const int* b = btot + blockIdx.y * (NTILE + 1);
    __shared__ int sw[8], sw2[9];
    int t = threadIdx.x, lane = t & 31, wid = t >> 5;
    int idx = blockIdx.x * 256 + t;
    int v = (idx < NN) ? cnt[idx] : 0;
    int inc = v;
#pragma unroll
    for (int d = 1; d < 32; d <<= 1) { int y = __shfl_up_sync(0xffffffffu, inc, d); if (lane >= d) inc += y; }
    if (lane == 31) sw[wid] = inc;
    __syncthreads();
    if (t == 0) { sw2[0] = 0; for (int i = 0; i < 8; i++) sw2[i + 1] = sw2[i] + sw[i]; }
    __syncthreads();
    int excl = b[blockIdx.x] + sw2[wid] + inc - v;
    if (idx < NN) {
        off[idx] = excl;
        if (blockIdx.y == 0) { cur1[idx] = excl + 1; csr1[excl] = idx; }
        else                 cur2[idx] = excl;
    }
    if (blockIdx.x == 0 && t == 0) off[NN] = b[NTILE];
}

__global__ void fill_kernel(const int* __restrict__ rowA, const int* __restrict__ colA,
                            int* cur1, int* csr1,
                            int* cur2, int* csr2c, int* csr2e) {
    int e = blockIdx.x * blockDim.x + threadIdx.x;
    if (e >= EE) return;
    int r = rowA[e];
    int c = colA[e];
    int p = atomicAdd(&cur1[c], 1);
    csr1[p] = r;
    int q = atomicAdd(&cur2[r], 1);
    csr2c[q] = c;
    csr2e[q] = e;
}

// ======================= weight fusion: Wf = Wg1 @ W_res, bf = Wg1 @ b_res ==
__global__ void wfuse_kernel(const float* __restrict__ Wg1, const float* __restrict__ W_res,
                             const float* __restrict__ b_res,
                             float* __restrict__ Wf, float* __restrict__ bf) {
    __shared__ float sWg[128];
    __shared__ float red[128];
    int d = blockIdx.x, k = threadIdx.x;
    sWg[k] = Wg1[d * 128 + k];
    __syncthreads();
    float s = 0.f;
#pragma unroll 8
    for (int j = 0; j < 128; j++) s = fmaf(sWg[j], W_res[j * 128 + k], s);
    Wf[d * 128 + k] = s;
    red[k] = sWg[k] * b_res[k];
    __syncthreads();
    for (int st = 64; st; st >>= 1) { if (k < st) red[k] += red[k + st]; __syncthreads(); }
    if (k == 0) bf[d] = red[0];
}

// ======================= GEMM (K = 128 fixed, f32x2 FMA, cp.async) =========

template <int TC, bool ATTN, bool STATS, bool SPLITW>
__global__ void __launch_bounds__(128, 4)
gemm_k128(const float* __restrict__ A, const float* __restrict__ W,
          int ldw, int woff, const float* __restrict__ bias,
          float* __restrict__ out, int opitch, int ocol, int nrows,
          const float* __restrict__ as, const float* __restrict__ ad,
          float* __restrict__ asrc, float* __restrict__ adst,
          float* gsum, float* gsq) {
    constexpr int CT = TC / 16;
    constexpr int PA = 68;
    constexpr int PW = TC + 4;
    __shared__ float sA[2][32 * PA];
    __shared__ float sW[2][32 * PW];
    const int tid = threadIdx.x;
    const int trow = tid >> 4;     // 0..7
    const int tcol = tid & 15;     // 0..15
    const int r0 = blockIdx.x * 64;

    unsigned long long acc2[4][CT];   // row-pairs x cols
#pragma unroll
    for (int p = 0; p < 4; p++)
#pragma unroll
        for (int j = 0; j < CT; j++) acc2[p][j] = 0ull;

    auto loadTiles = [&](int buf, int kb) {
#pragma unroll
        for (int i = 0; i < 16; i++) {
            int idx = tid + i * 128;
            int row = idx >> 5, kk = idx & 31;
            int gr = r0 + row;
            if (gr < nrows)
                __pipeline_memcpy_async(&sA[buf][kk * PA + row],
                                        &A[(size_t)gr * 128 + kb + kk], 4);
            else
                sA[buf][kk * PA + row] = 0.f;
        }
#pragma unroll
        for (int i = 0; i < (TC * 32) / 128; i++) {
            int idx = tid + i * 128;
            int col = idx >> 5, kk = idx & 31;
            int wrow = SPLITW ? (col & 63) : col;
            int wko  = SPLITW ? ((col >> 6) * 128) : 0;
            __pipeline_memcpy_async(&sW[buf][kk * PW + col],
                                    &W[(size_t)wrow * ldw + woff + wko + kb + kk], 4);
        }
        __pipeline_commit();
    };

    loadTiles(0, 0);
    int buf = 0;

    for (int kb = 0; kb < 128; kb += 32) {
        if (kb + 32 < 128) loadTiles(buf ^ 1, kb + 32);
        if (kb + 32 < 128) __pipeline_wait_prior(1);
        else               __pipeline_wait_prior(0);
        __syncthreads();
        const float* cA = sA[buf];
        const float* cW = sW[buf];
#pragma unroll
        for (int kk = 0; kk < 32; kk++) {
            unsigned long long ap[4];
#pragma unroll
            for (int p = 0; p < 4; p++)
                ap[p] = *(const unsigned long long*)&cA[kk * PA + trow * 8 + 2 * p];
            float w[CT];
#pragma unroll
            for (int j = 0; j < CT; j += 4) {
                float4 wv = *(const float4*)&cW[kk * PW + tcol * CT + j];
                w[j] = wv.x; w[j + 1] = wv.y; w[j + 2] = wv.z; w[j + 3] = wv.w;
            }
            unsigned long long wd[CT];
#pragma unroll
            for (int j = 0; j < CT; j++) PACK2(wd[j], w[j], w[j]);
#pragma unroll
            for (int p = 0; p < 4; p++)
#pragma unroll
                for (int j = 0; j < CT; j++) FMA2(acc2[p][j], ap[p], wd[j]);
        }
        __syncthreads();
        buf ^= 1;
    }
    // ---- store ----
#pragma unroll
    for (int p = 0; p < 4; p++) {
        int gr0 = r0 + trow * 8 + 2 * p;
#pragma unroll
        for (int j = 0; j < CT; j++) {
            int col = tcol * CT + j;
            float b = bias ? bias[col] : 0.f;
            float lo, hi;
            UNPK2(lo, hi, acc2[p][j]);
            if (gr0 < nrows)     out[(size_t)gr0 * opitch + ocol + col]       = lo + b;
            if (gr0 + 1 < nrows) out[(size_t)(gr0 + 1) * opitch + ocol + col] = hi + b;
        }
    }
    // ---- fused attention dots (TC=128 only) ----
    if (ATTN) {
#pragma unroll
        for (int p = 0; p < 4; p++) {
            float s1lo = 0.f, s2lo = 0.f, s1hi = 0.f, s2hi = 0.f;
#pragma unroll
            for (int j = 0; j < CT; j++) {
                int col = tcol * CT + j;
                float aS = __ldg(&as[col]), aD = __ldg(&ad[col]);
                float lo, hi;
                UNPK2(lo, hi, acc2[p][j]);
                s1lo = fmaf(lo, aS, s1lo); s2lo = fmaf(lo, aD, s2lo);
                s1hi = fmaf(hi, aS, s1hi); s2hi = fmaf(hi, aD, s2hi);
            }
            s1lo += __shfl_xor_sync(0xffffffffu, s1lo, 1);
            s2lo += __shfl_xor_sync(0xffffffffu, s2lo, 1);
            s1hi += __shfl_xor_sync(0xffffffffu, s1hi, 1);
            s2hi += __shfl_xor_sync(0xffffffffu, s2hi, 1);
            if (!(tcol & 1)) {
                int h = tcol >> 1;
                int rlo = r0 + trow * 8 + 2 * p;
                if (rlo < nrows)     { asrc[rlo * 8 + h] = s1lo;       adst[rlo * 8 + h] = s2lo; }
                if (rlo + 1 < nrows) { asrc[(rlo + 1) * 8 + h] = s1hi; adst[(rlo + 1) * 8 + h] = s2hi; }
            }
        }
    }
    // ---- fused per-feature BN statistics ----
    if (STATS) {
        __shared__ float s_s[8][TC], s_q[8][TC];
#pragma unroll
        for (int j = 0; j < CT; j++) {
            int col = tcol * CT + j;
            float b = bias ? bias[col] : 0.f;
            float ps = 0.f, pq = 0.f;
#pragma unroll
            for (int p = 0; p < 4; p++) {
                int gr0 = r0 + trow * 8 + 2 * p;
                float lo, hi;
                UNPK2(lo, hi, acc2[p][j]);
                if (gr0 < nrows)     { float v = lo + b; ps += v; pq = fmaf(v, v, pq); }
                if (gr0 + 1 < nrows) { float v = hi + b; ps += v; pq = fmaf(v, v, pq); }
            }
            s_s[trow][col] = ps;
            s_q[trow][col] = pq;
        }
        __syncthreads();
        if (tid < TC) {
            float S = 0.f, Q = 0.f;
#pragma unroll
            for (int w = 0; w < 8; w++) { S += s_s[w][tid]; Q += s_q[w][tid]; }
            atomicAdd(&gsum[tid], S);
            atomicAdd(&gsq[tid],  Q);
        }
    }
}

// ======================= GAT aggregation (online softmax + BN stats) =======
// one warp per node; unrolled x2 for memory-level parallelism

__global__ void __launch_bounds__(256)
gat_aggregate(const float* __restrict__ hfeat,
              const float* __restrict__ asrc, const float* __restrict__ adst,
              const int* __restrict__ off, const int* __restrict__ csr,
              const float* __restrict__ bg, float* __restrict__ outp,
              float* gsum, float* gsq) {
    __shared__ float s_v[8][128];
    int gw = (blockIdx.x * blockDim.x + threadIdx.x) >> 5;
    int lane = threadIdx.x & 31;
    int wib = threadIdx.x >> 5;
    int head = lane >> 2;
    float ad = adst[gw * 8 + head];
    float mm = -INFINITY, den = 0.f;
    float4 acc = make_float4(0.f, 0.f, 0.f, 0.f);
    int s0 = off[gw], s1 = off[gw + 1];
    int i = s0;
    for (; i + 1 < s1; i += 2) {
        int sa = csr[i], sb = csr[i + 1];
        float ea = asrc[sa * 8 + head] + ad;
        float eb = asrc[sb * 8 + head] + ad;
        ea = (ea >= 0.f) ? ea : 0.2f * ea;
        eb = (eb >= 0.f) ? eb : 0.2f * eb;
        float4 ha = *(const float4*)&hfeat[(size_t)sa * 128 + lane * 4];
        float4 hb = *(const float4*)&hfeat[(size_t)sb * 128 + lane * 4];
        float m2 = fmaxf(ea, eb);
        if (m2 > mm) {
            float sc = __expf(mm - m2);
            den *= sc;
            acc.x *= sc; acc.y *= sc; acc.z *= sc; acc.w *= sc;
            mm = m2;
        }
        float pa = __expf(ea - mm);
        float pb = __expf(eb - mm);
        den += pa + pb;
        acc.x = fmaf(ha.x, pa, fmaf(hb.x, pb, acc.x));
        acc.y = fmaf(ha.y, pa, fmaf(hb.y, pb, acc.y));
        acc.z = fmaf(ha.z, pa, fmaf(hb.z, pb, acc.z));
        acc.w = fmaf(ha.w, pa, fmaf(hb.w, pb, acc.w));
    }
    if (i < s1) {
        int s = csr[i];
        float e = asrc[s * 8 + head] + ad;
        e = (e >= 0.f) ? e : 0.2f * e;
        if (e > mm) {
            float sc = __expf(mm - e);
            den *= sc;
            acc.x *= sc; acc.y *= sc; acc.z *= sc; acc.w *= sc;
            mm = e;
        }
        float p = __expf(e - mm);
        den += p;
        float4 hv = *(const float4*)&hfeat[(size_t)s * 128 + lane * 4];
        acc.x = fmaf(hv.x, p, acc.x);
        acc.y = fmaf(hv.y, p, acc.y);
        acc.z = fmaf(hv.z, p, acc.z);
        acc.w = fmaf(hv.w, p, acc.w);
    }
    float inv = 1.f / (den + 1e-16f);
    float4 bgv = *(const float4*)&bg[lane * 4];
    acc.x = fmaf(acc.x, inv, bgv.x);
    acc.y = fmaf(acc.y, inv, bgv.y);
    acc.z = fmaf(acc.z, inv, bgv.z);
    acc.w = fmaf(acc.w, inv, bgv.w);
    *(float4*)&outp[(size_t)gw * 128 + lane * 4] = acc;
    *(float4*)&s_v[wib][lane * 4] = acc;
    __syncthreads();
    int t = threadIdx.x;
    if (t < 128) {
        float S = 0.f, Q = 0.f;
#pragma unroll
        for (int w = 0; w < 8; w++) { float v = s_v[w][t]; S += v; Q = fmaf(v, v, Q); }
        atomicAdd(&gsum[t], S);
        atomicAdd(&gsq[t],  Q);
    }
}

// ======================= BN finalize + BN-ELU ==============================

__global__ void bn_finalize(const float* __restrict__ gs, const float* __restrict__ gq,
                            float* mean, float* rstd, int F) {
    int f = threadIdx.x;
    if (f < F) {
        double invN = 1.0 / (double)NN;
        double mu = (double)gs[f] * invN;
        double var = (double)gq[f] * invN - mu * mu;
        if (var < 0.0) var = 0.0;
        mean[f] = (float)mu;
        rstd[f] = rsqrtf((float)var + 1e-5f);
    }
}

__global__ void bn_elu_kernel(const float* __restrict__ x, const float* __restrict__ mean,
                              const float* __restrict__ rstd, const float* __restrict__ gamma,
                              const float* __restrict__ beta, float* __restrict__ out, int total) {
    int i = (blockIdx.x * blockDim.x + threadIdx.x) * 4;
    if (i >= total) return;
    float4 v = *(const float4*)&x[i];
    int f = i & 127;
    float r[4] = {v.x, v.y, v.z, v.w};
#pragma unroll
    for (int k = 0; k < 4; k++) {
        int ff = f + k;
        float t = (r[k] - mean[ff]) * rstd[ff] * gamma[ff] + beta[ff];
        r[k] = (t > 0.f) ? t : expm1f(t);
    }
    *(float4*)&out[i] = make_float4(r[0], r[1], r[2], r[3]);
}

// ======================= Edge scorer, row-grouped ==========================
// warp per row-node; pr[row] kept in registers, only pc[col] gathered.

__global__ void __launch_bounds__(256)
edge_logits_row(const float* __restrict__ prpc,
                const int* __restrict__ off2,
                const int* __restrict__ col2, const int* __restrict__ eid2,
                const float* __restrict__ gumbel,
                const float* __restrict__ bs1,
                const float* __restrict__ ws2,
                const float* __restrict__ bs2,
                float* __restrict__ wout, float* __restrict__ lrout) {
    __shared__ float sw2[64];
    __shared__ float sb1[64];
    if (threadIdx.x < 64) { sw2[threadIdx.x] = ws2[threadIdx.x]; sb1[threadIdx.x] = bs1[threadIdx.x]; }
    __syncthreads();
    int gw = (blockIdx.x * blockDim.x + threadIdx.x) >> 5;
    if (gw >= NN) return;
    int lane = threadIdx.x & 31;
    float pr0 = prpc[(size_t)gw * 128 + lane]      + sb1[lane];
    float pr1 = prpc[(size_t)gw * 128 + 32 + lane] + sb1[32 + lane];
    float w0 = sw2[lane], w1 = sw2[32 + lane];
    float bias2 = bs2[0];
    int s0 = off2[gw], s1 = off2[gw + 1];
    int i = s0;
    for (; i + 1 < s1; i += 2) {
        int ca = col2[i],  cb = col2[i + 1];
        int ea = eid2[i],  eb = eid2[i + 1];
        float a0 = prpc[(size_t)ca * 128 + 64 + lane];
        float a1 = prpc[(size_t)ca * 128 + 96 + lane];
        float b0 = prpc[(size_t)cb * 128 + 64 + lane];
        float b1 = prpc[(size_t)cb * 128 + 96 + lane];
        float pa = fmaxf(pr0 + a0, 0.f) * w0 + fmaxf(pr1 + a1, 0.f) * w1;
        float pb = fmaxf(pr0 + b0, 0.f) * w0 + fmaxf(pr1 + b1, 0.f) * w1;
#pragma unroll
        for (int d = 16; d; d >>= 1) {
            pa += __shfl_xor_sync(0xffffffffu, pa, d);
            pb += __shfl_xor_sync(0xffffffffu, pb, d);
        }
        if (lane == 0) {
            float lra = pa + bias2, lrb = pb + bias2;
            lrout[ea] = lra;
            lrout[eb] = lrb;
            float ga0 = gumbel[2 * (size_t)ea], ga1 = gumbel[2 * (size_t)ea + 1];
            float gb0 = gumbel[2 * (size_t)eb], gb1 = gumbel[2 * (size_t)eb + 1];
            wout[ea] = (lra + ga1 > ga0) ? 1.f : 0.f;
            wout[eb] = (lrb + gb1 > gb0) ? 1.f : 0.f;
        }
    }
    if (i < s1) {
        int c = col2[i], e = eid2[i];
        float a0 = prpc[(size_t)c * 128 + 64 + lane];
        float a1 = prpc[(size_t)c * 128 + 96 + lane];
        float p = fmaxf(pr0 + a0, 0.f) * w0 + fmaxf(pr1 + a1, 0.f) * w1;
#pragma unroll
        for (int d = 16; d; d >>= 1) p += __shfl_xor_sync(0xffffffffu, p, d);
        if (lane == 0) {
            float lr = p + bias2;
            lrout[e] = lr;
            float g0 = gumbel[2 * (size_t)e], g1 = gumbel[2 * (size_t)e + 1];
            wout[e] = (lr + g1 > g0) ? 1.f : 0.f;
        }
    }
}

// h_sparse = h_base + segment_sum(weights * h_base[col], row), unrolled x2
__global__ void sparse_agg_kernel(const float* __restrict__ hbase,
                                  const int* __restrict__ off2,
                                  const int* __restrict__ col, const int* __restrict__ eid,
                                  const float* __restrict__ w, float* __restrict__ outp) {
    int gw = (blockIdx.x * blockDim.x + threadIdx.x) >> 5;
    if (gw >= NN) return;
    int lane = threadIdx.x & 31;
    float4 acc = *(const float4*)&hbase[(size_t)gw * 128 + lane * 4];
    int s0 = off2[gw], s1 = off2[gw + 1];
    int i = s0;
    for (; i + 1 < s1; i += 2) {
        int e0 = eid[i],  e1 = eid[i + 1];
        int c0 = col[i],  c1 = col[i + 1];
        float w0 = w[e0], w1 = w[e1];
        if (w0 != 0.f) {
            float4 h = *(const float4*)&hbase[(size_t)c0 * 128 + lane * 4];
            acc.x += h.x; acc.y += h.y; acc.z += h.z; acc.w += h.w;
        }
        if (w1 != 0.f) {
            float4 h = *(const float4*)&hbase[(size_t)c1 * 128 + lane * 4];
            acc.x += h.x; acc.y += h.y; acc.z += h.z; acc.w += h.w;
        }
    }
    if (i < s1) {
        int e = eid[i];
        if (w[e] != 0.f) {
            int c = col[i];
            float4 h = *(const float4*)&hbase[(size_t)c * 128 + lane * 4];
            acc.x += h.x; acc.y += h.y; acc.z += h.z; acc.w += h.w;
        }
    }
    *(float4*)&outp[(size_t)gw * 128 + lane * 4] = acc;
}

// ======================= Classifier head ===================================

__global__ void __launch_bounds__(256)
classifier_kernel(const float* __restrict__ cpre, const float* __restrict__ mean,
                  const float* __restrict__ rstd, const float* __restrict__ gc,
                  const float* __restrict__ bec, const float* __restrict__ Wc2,
                  const float* __restrict__ bc2, float* __restrict__ outls) {
    __shared__ float sW[64 * 64];
    __shared__ float sb[40];
    __shared__ float sc[8][64];
    for (int idx = threadIdx.x; idx < 64 * 64; idx += blockDim.x) {
        int f = idx >> 6, j = idx & 63;
        sW[idx] = (j < 40) ? Wc2[j * 64 + f] : 0.f;
    }
    if (threadIdx.x < 40) sb[threadIdx.x] = bc2[threadIdx.x];
    __syncthreads();
    int gw = (blockIdx.x * blockDim.x + threadIdx.x) >> 5;
    int lane = threadIdx.x & 31;
    int wib = threadIdx.x >> 5;
    if (gw >= NN) return;
    float v0 = cpre[(size_t)gw * 64 + lane];
    float v1 = cpre[(size_t)gw * 64 + 32 + lane];
    int f0 = lane, f1 = lane + 32;
    sc[wib][lane]      = fmaxf((v0 - mean[f0]) * rstd[f0] * gc[f0] + bec[f0], 0.f);
    sc[wib][lane + 32] = fmaxf((v1 - mean[f1]) * rstd[f1] * gc[f1] + bec[f1], 0.f);
    __syncwarp();
    float l0 = sb[lane];
    float l1 = (lane < 8) ? sb[lane + 32] : 0.f;
#pragma unroll
    for (int f = 0; f < 64; f++) {
        float cv = sc[wib][f];
        l0 = fmaf(cv, sW[f * 64 + lane], l0);
        l1 = fmaf(cv, sW[f * 64 + lane + 32], l1);
    }
    float mx = fmaxf(l0, (lane < 8) ? l1 : -INFINITY);
#pragma unroll
    for (int d = 16; d; d >>= 1) mx = fmaxf(mx, __shfl_xor_sync(0xffffffffu, mx, d));
    float s = expf(l0 - mx) + ((lane < 8) ? expf(l1 - mx) : 0.f);
#pragma unroll
    for (int d = 16; d; d >>= 1) s += __shfl_xor_sync(0xffffffffu, s, d);
    float lse = mx + logf(s);
    outls[(size_t)gw * 40 + lane] = l0 - lse;
    if (lane < 8) outls[(size_t)gw * 40 + 32 + lane] = l1 - lse;
}

// ======================= Host orchestration ================================

extern "C" void kernel_launch(void* const* d_in, const int* in_sizes, int n_in,
                              void* d_out, int out_size) {
    (void)in_sizes; (void)n_in; (void)out_size;

    float* S = nullptr;
    cudaGetSymbolAddress((void**)&S, g_scratch);

    float* bufA = S;                       // N*128
    float* bufH = S + 6400000;             // N*128
    float* bufG = S + 12800000;            // N*128
    float* bufC = S + 19200000;            // N*64
    float* asrc = S + 22400000;            // N*8
    float* adst = S + 22800000;
    float* fpar = S + 23200000;
    float* mean1 = fpar,       * rstd1 = fpar + 128;
    float* mean2 = fpar + 256, * rstd2 = fpar + 384;
    float* meanc = fpar + 512, * rstdc = fpar + 640;
    float* stat  = S + 23201024;
    float* s1s = stat,       * s1q = stat + 128;
    float* s2s = stat + 256, * s2q = stat + 384;
    float* scs = stat + 512, * scq = stat + 576;
    float* Wf   = S + 23300000;            // 128*128 fused weight
    float* bf   = Wf + 16384;              // 128 fused bias
    int* ip    = (int*)(S + 24000000);
    int* rowA  = ip;
    int* colA  = rowA + EE;
    int* off1  = colA + EE;
    int* off2  = off1 + (NN + 1);
    int* cur1  = off2 + (NN + 1);
    int* cur2  = cur1 + NN;
    int* cnt1  = cur2 + NN;
    int* cnt2  = cnt1 + NN;
    int* csr1  = cnt2 + NN;
    int* csr2c = csr1 + (EE + NN);
    int* csr2e = csr2c + EE;
    int* flag64 = csr2e + EE;
    int* btot   = flag64 + 1;

    const float* x      = (const float*)d_in[0];
    const int*   eiw    = (const int*)d_in[1];
    const float* gumbel = (const float*)d_in[2];
    const float* W_res  = (const float*)d_in[3];
    const float* b_res  = (const float*)d_in[4];
    const float* Wg1    = (const float*)d_in[5];
    const float* as1    = (const float*)d_in[6];
    const float* ad1    = (const float*)d_in[7];
    const float* bg1    = (const float*)d_in[8];
    const float* g1     = (const float*)d_in[9];
    const float* be1    = (const float*)d_in[10];
    const float* Wg2    = (const float*)d_in[11];
    const float* as2    = (const float*)d_in[12];
    const float* ad2    = (const float*)d_in[13];
    const float* bg2    = (const float*)d_in[14];
    const float* g2     = (const float*)d_in[15];
    const float* be2    = (const float*)d_in[16];
    const float* Ws1    = (const float*)d_in[17];
    const float* bs1    = (const float*)d_in[18];
    const float* Ws2    = (const float*)d_in[19];
    const float* bs2    = (const float*)d_in[20];
    const float* Wc1    = (const float*)d_in[21];
    const float* bc1    = (const float*)d_in[22];
    const float* gc     = (const float*)d_in[23];
    const float* bec    = (const float*)d_in[24];
    const float* Wc2    = (const float*)d_in[25];
    const float* bc2    = (const float*)d_in[26];

    float* out_ls = (float*)d_out;
    float* out_w  = out_ls + (size_t)NN * OUTC;
    float* out_lr = out_w + EE;

    const int NB   = (NN + 255) / 256;
    const int EB   = (EE + 255) / 256;
    const int WRPN = (NN * 32) / 256;
    const int GEMG = (NN + 63) / 64;

    // ---- fork: CSR build on side stream, GEMMs on main stream ----
    cudaStream_t s1str;
    cudaEvent_t evFork, evJoin;
    cudaStreamCreateWithFlags(&s1str, cudaStreamNonBlocking);
    cudaEventCreateWithFlags(&evFork, cudaEventDisableTiming);
    cudaEventCreateWithFlags(&evJoin, cudaEventDisableTiming);

    cudaEventRecord(evFork, 0);
    cudaStreamWaitEvent(s1str, evFork, 0);

    // side stream: CSR build chain
    init_kernel<<<NB, 256, 0, s1str>>>(cnt1, cnt2, flag64, stat);
    detect_kernel<<<256, 256, 0, s1str>>>(eiw, flag64);
    convert_hist_kernel<<<EB, 256, 0, s1str>>>(eiw, flag64, rowA, colA, cnt1, cnt2);
    scan_p1<<<dim3(NTILE, 2), 256, 0, s1str>>>(cnt1, cnt2, btot);
    scan_p2<<<dim3(1, 2), 256, 0, s1str>>>(btot);
    scan_p3<<<dim3(NTILE, 2), 256, 0, s1str>>>(cnt1, cnt2, btot, off1, off2, cur1, cur2, csr1);
    fill_kernel<<<EB, 256, 0, s1str>>>(rowA, colA, cur1, csr1, cur2, csr2c, csr2e);
    cudaEventRecord(evJoin, s1str);

    // main stream: weight fusion, then fused h1 GEMM (+attention dots)
    wfuse_kernel<<<128, 128>>>(Wg1, W_res, b_res, Wf, bf);
    gemm_k128<128, true, false, false><<<GEMG, 128>>>(
        x, Wf, 128, 0, bf, bufH, 128, 0, NN,
        as1, ad1, asrc, adst, nullptr, nullptr);

    // join: aggregation needs CSR + stats-zeroing from side stream
    cudaStreamWaitEvent(0, evJoin, 0);

    gat_aggregate<<<WRPN, 256>>>(bufH, asrc, adst, off1, csr1, bg1, bufG, s1s, s1q);
    bn_finalize<<<1, 128>>>(s1s, s1q, mean1, rstd1, 128);

    // layer-1 BN+ELU materialized, then async GEMM (was inline-BNIN sync GEMM)
    bn_elu_kernel<<<(NN * 32 + 255) / 256, 256>>>(bufG, mean1, rstd1, g1, be1, bufA, NN * 128);
    gemm_k128<128, true, false, false><<<GEMG, 128>>>(
        bufA, Wg2, 128, 0, nullptr, bufH, 128, 0, NN,
        as2, ad2, asrc, adst, nullptr, nullptr);
    gat_aggregate<<<WRPN, 256>>>(bufH, asrc, adst, off1, csr1, bg2, bufG, s2s, s2q);
    bn_finalize<<<1, 128>>>(s2s, s2q, mean2, rstd2, 128);
    bn_elu_kernel<<<(NN * 32 + 255) / 256, 256>>>(bufG, mean2, rstd2, g2, be2, bufA, NN * 128);
    // bufA = h_base

    // edge scorer: single merged SPLITW GEMM (pr | pc), then row-grouped gate
    gemm_k128<128, false, false, true><<<GEMG, 128>>>(
        bufA, Ws1, 256, 0, nullptr, bufH, 128, 0, NN,
        nullptr, nullptr, nullptr, nullptr, nullptr, nullptr);
    edge_logits_row<<<WRPN, 256>>>(bufH, off2, csr2c, csr2e, gumbel, bs1, Ws2, bs2, out_w, out_lr);

    // sparse aggregation
    sparse_agg_kernel<<<WRPN, 256>>>(bufA, off2, csr2c, csr2e, out_w, bufG);

    // classifier (BN stats fused into GEMM)
    gemm_k128<64, false, true, false><<<GEMG, 128>>>(
        bufG, Wc1, 128, 0, bc1, bufC, 64, 0, NN,
        nullptr, nullptr, nullptr, nullptr, scs, scq);
    bn_finalize<<<1, 64>>>(scs, scq, meanc, rstdc, 64);
    classifier_kernel<<<WRPN, 256>>>(bufC, meanc, rstdc, gc, bec, Wc2, bc2, out_ls);
}

// round 14
// speedup vs baseline: 1.4898x; 1.0128x over previous
#include <cuda_runtime.h>
#include <cuda_bf16.h>
#include <cuda_pipeline.h>
#include <math.h>

#define NN 50000
#define EE 800000
#define OUTC 40
#define NTILE 196            // ceil(50000/256)

__device__ __align__(128) float g_scratch[29000000];

#define PACK2(dst, lo, hi) asm("mov.b64 %0, {%1, %2};" : "=l"(dst) : "f"(lo), "f"(hi))
#define UNPK2(lo, hi, v)   asm("mov.b64 {%0, %1}, %2;" : "=f"(lo), "=f"(hi) : "l"(v))
#define FMA2(acc, a, b)    asm("fma.rn.f32x2 %0, %1, %2, %0;" : "+l"(acc) : "l"(a), "l"(b))

// ======================= init: counts, flag, float stat accumulators =======
__global__ void init_kernel(int* c1, int* c2, int* flag64, float* statz) {
    int i = blockIdx.x * blockDim.x + threadIdx.x;
    if (i < NN) { c1[i] = 1; c2[i] = 0; }     // c1 starts at 1 (self-loop)
    if (i == 0) *flag64 = 1;
    if (i < 640) statz[i] = 0.f;
}

__global__ void detect_kernel(const int* __restrict__ w, int* flag64) {
    int any = 0;
    for (int i = blockIdx.x * blockDim.x + threadIdx.x; i < EE; i += gridDim.x * blockDim.x)
        any |= w[2 * i + 1];
    if (any) atomicAnd(flag64, 0);
}

// convert edge_index to int32 row/col AND histogram in one pass
__global__ void convert_hist_kernel(const int* __restrict__ w, const int* __restrict__ flag64,
                                    int* __restrict__ rowA, int* __restrict__ colA,
                                    int* c1, int* c2) {
    int e = blockIdx.x * blockDim.x + threadIdx.x;
    if (e >= EE) return;
    int r, c;
    if (*flag64) { r = w[2 * e]; c = w[2 * (EE + e)]; }
    else         { r = w[e];     c = w[EE + e]; }
    rowA[e] = r; colA[e] = c;
    atomicAdd(&c1[c], 1);
    atomicAdd(&c2[r], 1);
}

// ---- parallel 3-phase exclusive scan over two arrays (gridDim.y selects) ----
__global__ void scan_p1(const int* __restrict__ cnt1, const int* __restrict__ cnt2,
                        int* __restrict__ btot) {
    const int* cnt = blockIdx.y ? cnt2 : cnt1;
    __shared__ int sw[8];
    int idx = blockIdx.x * 256 + threadIdx.x;
    int v = (idx < NN) ? cnt[idx] : 0;
#pragma unroll
    for (int d = 16; d; d >>= 1) v += __shfl_xor_sync(0xffffffffu, v, d);
    if ((threadIdx.x & 31) == 0) sw[threadIdx.x >> 5] = v;
    __syncthreads();
    if (threadIdx.x == 0) {
        int s = 0;
#pragma unroll
        for (int i = 0; i < 8; i++) s += sw[i];
        btot[blockIdx.y * (NTILE + 1) + blockIdx.x] = s;
    }
}

__global__ void scan_p2(int* __restrict__ btot) {
    int* b = btot + blockIdx.y * (NTILE + 1);
    __shared__ int sw[8], sw2[9];
    int t = threadIdx.x, lane = t & 31, wid = t >> 5;
    int v = (t < NTILE) ? b[t] : 0;
    int inc = v;
#pragma unroll
    for (int d = 1; d < 32; d <<= 1) { int y = __shfl_up_sync(0xffffffffu, inc, d); if (lane >= d) inc += y; }
    if (lane == 31) sw[wid] = inc;
    __syncthreads();
    if (t == 0) { sw2[0] = 0; for (int i = 0; i < 8; i++) sw2[i + 1] = sw2[i] + sw[i]; }
    __syncthreads();
    int excl = sw2[wid] + inc - v;
    if (t < NTILE) b[t] = excl;
    if (t == 0) b[NTILE] = sw2[8];
}

// scan phase 3 + cursor init + self-loop placement
__global__ void scan_p3(const int* __restrict__ cnt1, const int* __restrict__ cnt2,
                        const int* __restrict__ btot,
                        int* __restrict__ off1, int* __restrict__ off2,
                        int* __restrict__ cur1, int* __restrict__ cur2, int* __restrict__ csr1) {
    const int* cnt = blockIdx.y ? cnt2 : cnt1;
    int* off = blockIdx.y ? off2 : off1;
    const int* b = btot + blockIdx.y * (NTILE + 1);
    __shared__ int sw[8], sw2[9];
    int t = threadIdx.x, lane = t & 31, wid = t >> 5;
    int idx = blockIdx.x * 256 + t;
    int v = (idx < NN) ? cnt[idx] : 0;
    int inc = v;
#pragma unroll
    for (int d = 1; d < 32; d <<= 1) { int y = __shfl_up_sync(0xffffffffu, inc, d); if (lane >= d) inc += y; }
    if (lane == 31) sw[wid] = inc;
    __syncthreads();
    if (t == 0) { sw2[0] = 0; for (int i = 0; i < 8; i++) sw2[i + 1] = sw2[i] + sw[i]; }
    __syncthreads();
    int excl = b[blockIdx.x] + sw2[wid] + inc - v;
    if (idx < NN) {
        off[idx] = excl;
        if (blockIdx.y == 0) { cur1[idx] = excl + 1; csr1[excl] = idx; }
        else                 cur2[idx] = excl;
    }
    if (blockIdx.x == 0 && t == 0) off[NN] = b[NTILE];
}

__global__ void fill_kernel(const int* __restrict__ rowA, const int* __restrict__ colA,
                            int* cur1, int* csr1,
                            int* cur2, int* csr2c, int* csr2e) {
    int e = blockIdx.x * blockDim.x + threadIdx.x;
    if (e >= EE) return;
    int r = rowA[e];
    int c = colA[e];
    int p = atomicAdd(&cur1[c], 1);
    csr1[p] = r;
    int q = atomicAdd(&cur2[r], 1);
    csr2c[q] = c;
    csr2e[q] = e;
}

// ======================= weight fusion: Wf = Wg1 @ W_res, bf = Wg1 @ b_res ==
__global__ void wfuse_kernel(const float* __restrict__ Wg1, const float* __restrict__ W_res,
                             const float* __restrict__ b_res,
                             float* __restrict__ Wf, float* __restrict__ bf) {
    __shared__ float sWg[128];
    __shared__ float red[128];
    int d = blockIdx.x, k = threadIdx.x;
    sWg[k] = Wg1[d * 128 + k];
    __syncthreads();
    float s = 0.f;
#pragma unroll 8
    for (int j = 0; j < 128; j++) s = fmaf(sWg[j], W_res[j * 128 + k], s);
    Wf[d * 128 + k] = s;
    red[k] = sWg[k] * b_res[k];
    __syncthreads();
    for (int st = 64; st; st >>= 1) { if (k < st) red[k] += red[k + st]; __syncthreads(); }
    if (k == 0) bf[d] = red[0];
}

// ======================= GEMM (K = 128 fixed, f32x2 FMA, cp.async) =========

template <int TC, bool ATTN, bool STATS, bool SPLITW>
__global__ void __launch_bounds__(128, 4)
gemm_k128(const float* __restrict__ A, const float* __restrict__ W,
          int ldw, int woff, const float* __restrict__ bias,
          float* __restrict__ out, int opitch, int ocol, int nrows,
          const float* __restrict__ as, const float* __restrict__ ad,
          float* __restrict__ asrc, float* __restrict__ adst,
          float* gsum, float* gsq) {
    constexpr int CT = TC / 16;
    constexpr int PA = 68;
    constexpr int PW = TC + 4;
    __shared__ float sA[2][32 * PA];
    __shared__ float sW[2][32 * PW];
    const int tid = threadIdx.x;
    const int trow = tid >> 4;     // 0..7
    const int tcol = tid & 15;     // 0..15
    const int r0 = blockIdx.x * 64;

    unsigned long long acc2[4][CT];   // row-pairs x cols
#pragma unroll
    for (int p = 0; p < 4; p++)
#pragma unroll
        for (int j = 0; j < CT; j++) acc2[p][j] = 0ull;

    auto loadTiles = [&](int buf, int kb) {
#pragma unroll
        for (int i = 0; i < 16; i++) {
            int idx = tid + i * 128;
            int row = idx >> 5, kk = idx & 31;
            int gr = r0 + row;
            if (gr < nrows)
                __pipeline_memcpy_async(&sA[buf][kk * PA + row],
                                        &A[(size_t)gr * 128 + kb + kk], 4);
            else
                sA[buf][kk * PA + row] = 0.f;
        }
#pragma unroll
        for (int i = 0; i < (TC * 32) / 128; i++) {
            int idx = tid + i * 128;
            int col = idx >> 5, kk = idx & 31;
            int wrow = SPLITW ? (col & 63) : col;
            int wko  = SPLITW ? ((col >> 6) * 128) : 0;
            __pipeline_memcpy_async(&sW[buf][kk * PW + col],
                                    &W[(size_t)wrow * ldw + woff + wko + kb + kk], 4);
        }
        __pipeline_commit();
    };

    loadTiles(0, 0);
    int buf = 0;

    for (int kb = 0; kb < 128; kb += 32) {
        if (kb + 32 < 128) loadTiles(buf ^ 1, kb + 32);
        if (kb + 32 < 128) __pipeline_wait_prior(1);
        else               __pipeline_wait_prior(0);
        __syncthreads();
        const float* cA = sA[buf];
        const float* cW = sW[buf];
#pragma unroll
        for (int kk = 0; kk < 32; kk++) {
            unsigned long long ap[4];
#pragma unroll
            for (int p = 0; p < 4; p++)
                ap[p] = *(const unsigned long long*)&cA[kk * PA + trow * 8 + 2 * p];
            float w[CT];
#pragma unroll
            for (int j = 0; j < CT; j += 4) {
                float4 wv = *(const float4*)&cW[kk * PW + tcol * CT + j];
                w[j] = wv.x; w[j + 1] = wv.y; w[j + 2] = wv.z; w[j + 3] = wv.w;
            }
            unsigned long long wd[CT];
#pragma unroll
            for (int j = 0; j < CT; j++) PACK2(wd[j], w[j], w[j]);
#pragma unroll
            for (int p = 0; p < 4; p++)
#pragma unroll
                for (int j = 0; j < CT; j++) FMA2(acc2[p][j], ap[p], wd[j]);
        }
        __syncthreads();
        buf ^= 1;
    }
    // ---- store ----
#pragma unroll
    for (int p = 0; p < 4; p++) {
        int gr0 = r0 + trow * 8 + 2 * p;
#pragma unroll
        for (int j = 0; j < CT; j++) {
            int col = tcol * CT + j;
            float b = bias ? bias[col] : 0.f;
            float lo, hi;
            UNPK2(lo, hi, acc2[p][j]);
            if (gr0 < nrows)     out[(size_t)gr0 * opitch + ocol + col]       = lo + b;
            if (gr0 + 1 < nrows) out[(size_t)(gr0 + 1) * opitch + ocol + col] = hi + b;
        }
    }
    // ---- fused attention dots (TC=128 only) ----
    if (ATTN) {
#pragma unroll
        for (int p = 0; p < 4; p++) {
            float s1lo = 0.f, s2lo = 0.f, s1hi = 0.f, s2hi = 0.f;
#pragma unroll
            for (int j = 0; j < CT; j++) {
                int col = tcol * CT + j;
                float aS = __ldg(&as[col]), aD = __ldg(&ad[col]);
                float lo, hi;
                UNPK2(lo, hi, acc2[p][j]);
                s1lo = fmaf(lo, aS, s1lo); s2lo = fmaf(lo, aD, s2lo);
                s1hi = fmaf(hi, aS, s1hi); s2hi = fmaf(hi, aD, s2hi);
            }
            s1lo += __shfl_xor_sync(0xffffffffu, s1lo, 1);
            s2lo += __shfl_xor_sync(0xffffffffu, s2lo, 1);
            s1hi += __shfl_xor_sync(0xffffffffu, s1hi, 1);
            s2hi += __shfl_xor_sync(0xffffffffu, s2hi, 1);
            if (!(tcol & 1)) {
                int h = tcol >> 1;
                int rlo = r0 + trow * 8 + 2 * p;
                if (rlo < nrows)     { asrc[rlo * 8 + h] = s1lo;       adst[rlo * 8 + h] = s2lo; }
                if (rlo + 1 < nrows) { asrc[(rlo + 1) * 8 + h] = s1hi; adst[(rlo + 1) * 8 + h] = s2hi; }
            }
        }
    }
    // ---- fused per-feature BN statistics ----
    if (STATS) {
        __shared__ float s_s[8][TC], s_q[8][TC];
#pragma unroll
        for (int j = 0; j < CT; j++) {
            int col = tcol * CT + j;
            float b = bias ? bias[col] : 0.f;
            float ps = 0.f, pq = 0.f;
#pragma unroll
            for (int p = 0; p < 4; p++) {
                int gr0 = r0 + trow * 8 + 2 * p;
                float lo, hi;
                UNPK2(lo, hi, acc2[p][j]);
                if (gr0 < nrows)     { float v = lo + b; ps += v; pq = fmaf(v, v, pq); }
                if (gr0 + 1 < nrows) { float v = hi + b; ps += v; pq = fmaf(v, v, pq); }
            }
            s_s[trow][col] = ps;
            s_q[trow][col] = pq;
        }
        __syncthreads();
        if (tid < TC) {
            float S = 0.f, Q = 0.f;
#pragma unroll
            for (int w = 0; w < 8; w++) { S += s_s[w][tid]; Q += s_q[w][tid]; }
            atomicAdd(&gsum[tid], S);
            atomicAdd(&gsq[tid],  Q);
        }
    }
}

// ======================= GAT aggregation (online softmax + BN stats) =======
// one warp per node; unrolled x2 for memory-level parallelism

__global__ void __launch_bounds__(256)
gat_aggregate(const float* __restrict__ hfeat,
              const float* __restrict__ asrc, const float* __restrict__ adst,
              const int* __restrict__ off, const int* __restrict__ csr,
              const float* __restrict__ bg, float* __restrict__ outp,
              float* gsum, float* gsq) {
    __shared__ float s_v[8][128];
    int gw = (blockIdx.x * blockDim.x + threadIdx.x) >> 5;
    int lane = threadIdx.x & 31;
    int wib = threadIdx.x >> 5;
    int head = lane >> 2;
    float ad = adst[gw * 8 + head];
    float mm = -INFINITY, den = 0.f;
    float4 acc = make_float4(0.f, 0.f, 0.f, 0.f);
    int s0 = off[gw], s1 = off[gw + 1];
    int i = s0;
    for (; i + 1 < s1; i += 2) {
        int sa = csr[i], sb = csr[i + 1];
        float ea = asrc[sa * 8 + head] + ad;
        float eb = asrc[sb * 8 + head] + ad;
        ea = (ea >= 0.f) ? ea : 0.2f * ea;
        eb = (eb >= 0.f) ? eb : 0.2f * eb;
        float4 ha = *(const float4*)&hfeat[(size_t)sa * 128 + lane * 4];
        float4 hb = *(const float4*)&hfeat[(size_t)sb * 128 + lane * 4];
        float m2 = fmaxf(ea, eb);
        if (m2 > mm) {
            float sc = __expf(mm - m2);
            den *= sc;
            acc.x *= sc; acc.y *= sc; acc.z *= sc; acc.w *= sc;
            mm = m2;
        }
        float pa = __expf(ea - mm);
        float pb = __expf(eb - mm);
        den += pa + pb;
        acc.x = fmaf(ha.x, pa, fmaf(hb.x, pb, acc.x));
        acc.y = fmaf(ha.y, pa, fmaf(hb.y, pb, acc.y));
        acc.z = fmaf(ha.z, pa, fmaf(hb.z, pb, acc.z));
        acc.w = fmaf(ha.w, pa, fmaf(hb.w, pb, acc.w));
    }
    if (i < s1) {
        int s = csr[i];
        float e = asrc[s * 8 + head] + ad;
        e = (e >= 0.f) ? e : 0.2f * e;
        if (e > mm) {
            float sc = __expf(mm - e);
            den *= sc;
            acc.x *= sc; acc.y *= sc; acc.z *= sc; acc.w *= sc;
            mm = e;
        }
        float p = __expf(e - mm);
        den += p;
        float4 hv = *(const float4*)&hfeat[(size_t)s * 128 + lane * 4];
        acc.x = fmaf(hv.x, p, acc.x);
        acc.y = fmaf(hv.y, p, acc.y);
        acc.z = fmaf(hv.z, p, acc.z);
        acc.w = fmaf(hv.w, p, acc.w);
    }
    float inv = 1.f / (den + 1e-16f);
    float4 bgv = *(const float4*)&bg[lane * 4];
    acc.x = fmaf(acc.x, inv, bgv.x);
    acc.y = fmaf(acc.y, inv, bgv.y);
    acc.z = fmaf(acc.z, inv, bgv.z);
    acc.w = fmaf(acc.w, inv, bgv.w);
    *(float4*)&outp[(size_t)gw * 128 + lane * 4] = acc;
    *(float4*)&s_v[wib][lane * 4] = acc;
    __syncthreads();
    int t = threadIdx.x;
    if (t < 128) {
        float S = 0.f, Q = 0.f;
#pragma unroll
        for (int w = 0; w < 8; w++) { float v = s_v[w][t]; S += v; Q = fmaf(v, v, Q); }
        atomicAdd(&gsum[t], S);
        atomicAdd(&gsq[t],  Q);
    }
}

// ======================= BN finalize + BN-ELU ==============================

__global__ void bn_finalize(const float* __restrict__ gs, const float* __restrict__ gq,
                            float* mean, float* rstd, int F) {
    int f = threadIdx.x;
    if (f < F) {
        double invN = 1.0 / (double)NN;
        double mu = (double)gs[f] * invN;
        double var = (double)gq[f] * invN - mu * mu;
        if (var < 0.0) var = 0.0;
        mean[f] = (float)mu;
        rstd[f] = rsqrtf((float)var + 1e-5f);
    }
}

__global__ void bn_elu_kernel(const float* __restrict__ x, const float* __restrict__ mean,
                              const float* __restrict__ rstd, const float* __restrict__ gamma,
                              const float* __restrict__ beta, float* __restrict__ out, int total) {
    int i = (blockIdx.x * blockDim.x + threadIdx.x) * 4;
    if (i >= total) return;
    float4 v = *(const float4*)&x[i];
    int f = i & 127;
    float r[4] = {v.x, v.y, v.z, v.w};
#pragma unroll
    for (int k = 0; k < 4; k++) {
        int ff = f + k;
        float t = (r[k] - mean[ff]) * rstd[ff] * gamma[ff] + beta[ff];
        r[k] = (t > 0.f) ? t : expm1f(t);
    }
    *(float4*)&out[i] = make_float4(r[0], r[1], r[2], r[3]);
}

// ======================= Edge gate + sparse aggregation, fused =============
// warp per row-node; pr[row] in registers; per edge: gather pc[col], compute
// logit + gumbel gate, then conditionally accumulate h_base[col].
// Writes out_w / out_lr per edge and h_sparse per node.

__global__ void __launch_bounds__(256)
edge_gate_agg(const float* __restrict__ prpc,
              const float* __restrict__ hbase,
              const int* __restrict__ off2,
              const int* __restrict__ col2, const int* __restrict__ eid2,
              const float* __restrict__ gumbel,
              const float* __restrict__ bs1,
              const float* __restrict__ ws2,
              const float* __restrict__ bs2,
              float* __restrict__ wout, float* __restrict__ lrout,
              float* __restrict__ outp) {
    __shared__ float sw2[64];
    __shared__ float sb1[64];
    if (threadIdx.x < 64) { sw2[threadIdx.x] = ws2[threadIdx.x]; sb1[threadIdx.x] = bs1[threadIdx.x]; }
    __syncthreads();
    int gw = (blockIdx.x * blockDim.x + threadIdx.x) >> 5;
    if (gw >= NN) return;
    int lane = threadIdx.x & 31;
    float pr0 = prpc[(size_t)gw * 128 + lane]      + sb1[lane];
    float pr1 = prpc[(size_t)gw * 128 + 32 + lane] + sb1[32 + lane];
    float w0 = sw2[lane], w1 = sw2[32 + lane];
    float bias2 = bs2[0];
    float4 acc = *(const float4*)&hbase[(size_t)gw * 128 + lane * 4];
    int s0 = off2[gw], s1 = off2[gw + 1];
    int i = s0;
    for (; i + 1 < s1; i += 2) {
        int ca = col2[i],  cb = col2[i + 1];
        int ea = eid2[i],  eb = eid2[i + 1];
        float a0 = prpc[(size_t)ca * 128 + 64 + lane];
        float a1 = prpc[(size_t)ca * 128 + 96 + lane];
        float b0 = prpc[(size_t)cb * 128 + 64 + lane];
        float b1 = prpc[(size_t)cb * 128 + 96 + lane];
        float pa = fmaxf(pr0 + a0, 0.f) * w0 + fmaxf(pr1 + a1, 0.f) * w1;
        float pb = fmaxf(pr0 + b0, 0.f) * w0 + fmaxf(pr1 + b1, 0.f) * w1;
#pragma unroll
        for (int d = 16; d; d >>= 1) {
            pa += __shfl_xor_sync(0xffffffffu, pa, d);
            pb += __shfl_xor_sync(0xffffffffu, pb, d);
        }
        float lra = pa + bias2, lrb = pb + bias2;
        int ga = 0, gb = 0;
        if (lane == 0) {
            lrout[ea] = lra;
            lrout[eb] = lrb;
            float ga0 = gumbel[2 * (size_t)ea], ga1 = gumbel[2 * (size_t)ea + 1];
            float gb0 = gumbel[2 * (size_t)eb], gb1 = gumbel[2 * (size_t)eb + 1];
            ga = (lra + ga1 > ga0) ? 1 : 0;
            gb = (lrb + gb1 > gb0) ? 1 : 0;
            wout[ea] = ga ? 1.f : 0.f;
            wout[eb] = gb ? 1.f : 0.f;
        }
        ga = __shfl_sync(0xffffffffu, ga, 0);
        gb = __shfl_sync(0xffffffffu, gb, 0);
        if (ga) {
            float4 h = *(const float4*)&hbase[(size_t)ca * 128 + lane * 4];
            acc.x += h.x; acc.y += h.y; acc.z += h.z; acc.w += h.w;
        }
        if (gb) {
            float4 h = *(const float4*)&hbase[(size_t)cb * 128 + lane * 4];
            acc.x += h.x; acc.y += h.y; acc.z += h.z; acc.w += h.w;
        }
    }
    if (i < s1) {
        int c = col2[i], e = eid2[i];
        float a0 = prpc[(size_t)c * 128 + 64 + lane];
        float a1 = prpc[(size_t)c * 128 + 96 + lane];
        float p = fmaxf(pr0 + a0, 0.f) * w0 + fmaxf(pr1 + a1, 0.f) * w1;
#pragma unroll
        for (int d = 16; d; d >>= 1) p += __shfl_xor_sync(0xffffffffu, p, d);
        float lr = p + bias2;
        int g = 0;
        if (lane == 0) {
            lrout[e] = lr;
            float g0 = gumbel[2 * (size_t)e], g1 = gumbel[2 * (size_t)e + 1];
            g = (lr + g1 > g0) ? 1 : 0;
            wout[e] = g ? 1.f : 0.f;
        }
        g = __shfl_sync(0xffffffffu, g, 0);
        if (g) {
            float4 h = *(const float4*)&hbase[(size_t)c * 128 + lane * 4];
            acc.x += h.x; acc.y += h.y; acc.z += h.z; acc.w += h.w;
        }
    }
    *(float4*)&outp[(size_t)gw * 128 + lane * 4] = acc;
}

// ======================= Classifier head ===================================

__global__ void __launch_bounds__(256)
classifier_kernel(const float* __restrict__ cpre, const float* __restrict__ mean,
                  const float* __restrict__ rstd, const float* __restrict__ gc,
                  const float* __restrict__ bec, const float* __restrict__ Wc2,
                  const float* __restrict__ bc2, float* __restrict__ outls) {
    __shared__ float sW[64 * 64];
    __shared__ float sb[40];
    __shared__ float sc[8][64];
    for (int idx = threadIdx.x; idx < 64 * 64; idx += blockDim.x) {
        int f = idx >> 6, j = idx & 63;
        sW[idx] = (j < 40) ? Wc2[j * 64 + f] : 0.f;
    }
    if (threadIdx.x < 40) sb[threadIdx.x] = bc2[threadIdx.x];
    __syncthreads();
    int gw = (blockIdx.x * blockDim.x + threadIdx.x) >> 5;
    int lane = threadIdx.x & 31;
    int wib = threadIdx.x >> 5;
    if (gw >= NN) return;
    float v0 = cpre[(size_t)gw * 64 + lane];
    float v1 = cpre[(size_t)gw * 64 + 32 + lane];
    int f0 = lane, f1 = lane + 32;
    sc[wib][lane]      = fmaxf((v0 - mean[f0]) * rstd[f0] * gc[f0] + bec[f0], 0.f);
    sc[wib][lane + 32] = fmaxf((v1 - mean[f1]) * rstd[f1] * gc[f1] + bec[f1], 0.f);
    __syncwarp();
    float l0 = sb[lane];
    float l1 = (lane < 8) ? sb[lane + 32] : 0.f;
#pragma unroll
    for (int f = 0; f < 64; f++) {
        float cv = sc[wib][f];
        l0 = fmaf(cv, sW[f * 64 + lane], l0);
        l1 = fmaf(cv, sW[f * 64 + lane + 32], l1);
    }
    float mx = fmaxf(l0, (lane < 8) ? l1 : -INFINITY);
#pragma unroll
    for (int d = 16; d; d >>= 1) mx = fmaxf(mx, __shfl_xor_sync(0xffffffffu, mx, d));
    float s = expf(l0 - mx) + ((lane < 8) ? expf(l1 - mx) : 0.f);
#pragma unroll
    for (int d = 16; d; d >>= 1) s += __shfl_xor_sync(0xffffffffu, s, d);
    float lse = mx + logf(s);
    outls[(size_t)gw * 40 + lane] = l0 - lse;
    if (lane < 8) outls[(size_t)gw * 40 + 32 + lane] = l1 - lse;
}

// ======================= Host orchestration ================================

extern "C" void kernel_launch(void* const* d_in, const int* in_sizes, int n_in,
                              void* d_out, int out_size) {
    (void)in_sizes; (void)n_in; (void)out_size;

    float* S = nullptr;
    cudaGetSymbolAddress((void**)&S, g_scratch);

    float* bufA = S;                       // N*128
    float* bufH = S + 6400000;             // N*128
    float* bufG = S + 12800000;            // N*128
    float* bufC = S + 19200000;            // N*64
    float* asrc = S + 22400000;            // N*8
    float* adst = S + 22800000;
    float* fpar = S + 23200000;
    float* mean1 = fpar,       * rstd1 = fpar + 128;
    float* mean2 = fpar + 256, * rstd2 = fpar + 384;
    float* meanc = fpar + 512, * rstdc = fpar + 640;
    float* stat  = S + 23201024;
    float* s1s = stat,       * s1q = stat + 128;
    float* s2s = stat + 256, * s2q = stat + 384;
    float* scs = stat + 512, * scq = stat + 576;
    float* Wf   = S + 23300000;            // 128*128 fused weight
    float* bf   = Wf + 16384;              // 128 fused bias
    int* ip    = (int*)(S + 24000000);
    int* rowA  = ip;
    int* colA  = rowA + EE;
    int* off1  = colA + EE;
    int* off2  = off1 + (NN + 1);
    int* cur1  = off2 + (NN + 1);
    int* cur2  = cur1 + NN;
    int* cnt1  = cur2 + NN;
    int* cnt2  = cnt1 + NN;
    int* csr1  = cnt2 + NN;
    int* csr2c = csr1 + (EE + NN);
    int* csr2e = csr2c + EE;
    int* flag64 = csr2e + EE;
    int* btot   = flag64 + 1;

    const float* x      = (const float*)d_in[0];
    const int*   eiw    = (const int*)d_in[1];
    const float* gumbel = (const float*)d_in[2];
    const float* W_res  = (const float*)d_in[3];
    const float* b_res  = (const float*)d_in[4];
    const float* Wg1    = (const float*)d_in[5];
    const float* as1    = (const float*)d_in[6];
    const float* ad1    = (const float*)d_in[7];
    const float* bg1    = (const float*)d_in[8];
    const float* g1     = (const float*)d_in[9];
    const float* be1    = (const float*)d_in[10];
    const float* Wg2    = (const float*)d_in[11];
    const float* as2    = (const float*)d_in[12];
    const float* ad2    = (const float*)d_in[13];
    const float* bg2    = (const float*)d_in[14];
    const float* g2     = (const float*)d_in[15];
    const float* be2    = (const float*)d_in[16];
    const float* Ws1    = (const float*)d_in[17];
    const float* bs1    = (const float*)d_in[18];
    const float* Ws2    = (const float*)d_in[19];
    const float* bs2    = (const float*)d_in[20];
    const float* Wc1    = (const float*)d_in[21];
    const float* bc1    = (const float*)d_in[22];
    const float* gc     = (const float*)d_in[23];
    const float* bec    = (const float*)d_in[24];
    const float* Wc2    = (const float*)d_in[25];
    const float* bc2    = (const float*)d_in[26];

    float* out_ls = (float*)d_out;
    float* out_w  = out_ls + (size_t)NN * OUTC;
    float* out_lr = out_w + EE;

    const int NB   = (NN + 255) / 256;
    const int EB   = (EE + 255) / 256;
    const int WRPN = (NN * 32) / 256;
    const int GEMG = (NN + 63) / 64;

    // ---- fork: CSR build on side stream, GEMMs on main stream ----
    cudaStream_t s1str;
    cudaEvent_t evFork, evJoin;
    cudaStreamCreateWithFlags(&s1str, cudaStreamNonBlocking);
    cudaEventCreateWithFlags(&evFork, cudaEventDisableTiming);
    cudaEventCreateWithFlags(&evJoin, cudaEventDisableTiming);

    cudaEventRecord(evFork, 0);
    cudaStreamWaitEvent(s1str, evFork, 0);

    // side stream: CSR build chain
    init_kernel<<<NB, 256, 0, s1str>>>(cnt1, cnt2, flag64, stat);
    detect_kernel<<<256, 256, 0, s1str>>>(eiw, flag64);
    convert_hist_kernel<<<EB, 256, 0, s1str>>>(eiw, flag64, rowA, colA, cnt1, cnt2);
    scan_p1<<<dim3(NTILE, 2), 256, 0, s1str>>>(cnt1, cnt2, btot);
    scan_p2<<<dim3(1, 2), 256, 0, s1str>>>(btot);
    scan_p3<<<dim3(NTILE, 2), 256, 0, s1str>>>(cnt1, cnt2, btot, off1, off2, cur1, cur2, csr1);
    fill_kernel<<<EB, 256, 0, s1str>>>(rowA, colA, cur1, csr1, cur2, csr2c, csr2e);
    cudaEventRecord(evJoin, s1str);

    // main stream: weight fusion, then fused h1 GEMM (+attention dots)
    wfuse_kernel<<<128, 128>>>(Wg1, W_res, b_res, Wf, bf);
    gemm_k128<128, true, false, false><<<GEMG, 128>>>(
        x, Wf, 128, 0, bf, bufH, 128, 0, NN,
        as1, ad1, asrc, adst, nullptr, nullptr);

    // join: aggregation needs CSR + stats-zeroing from side stream
    cudaStreamWaitEvent(0, evJoin, 0);

    gat_aggregate<<<WRPN, 256>>>(bufH, asrc, adst, off1, csr1, bg1, bufG, s1s, s1q);
    bn_finalize<<<1, 128>>>(s1s, s1q, mean1, rstd1, 128);

    // layer-1 BN+ELU materialized, then async GEMM
    bn_elu_kernel<<<(NN * 32 + 255) / 256, 256>>>(bufG, mean1, rstd1, g1, be1, bufA, NN * 128);
    gemm_k128<128, true, false, false><<<GEMG, 128>>>(
        bufA, Wg2, 128, 0, nullptr, bufH, 128, 0, NN,
        as2, ad2, asrc, adst, nullptr, nullptr);
    gat_aggregate<<<WRPN, 256>>>(bufH, asrc, adst, off1, csr1, bg2, bufG, s2s, s2q);
    bn_finalize<<<1, 128>>>(s2s, s2q, mean2, rstd2, 128);
    bn_elu_kernel<<<(NN * 32 + 255) / 256, 256>>>(bufG, mean2, rstd2, g2, be2, bufA, NN * 128);
    // bufA = h_base

    // edge scorer GEMM (pr | pc), then fused gate + sparse aggregation
    gemm_k128<128, false, false, true><<<GEMG, 128>>>(
        bufA, Ws1, 256, 0, nullptr, bufH, 128, 0, NN,
        nullptr, nullptr, nullptr, nullptr, nullptr, nullptr);
    edge_gate_agg<<<WRPN, 256>>>(bufH, bufA, off2, csr2c, csr2e, gumbel,
                                 bs1, Ws2, bs2, out_w, out_lr, bufG);

    // classifier (BN stats fused into GEMM)
    gemm_k128<64, false, true, false><<<GEMG, 128>>>(
        bufG, Wc1, 128, 0, bc1, bufC, 64, 0, NN,
        nullptr, nullptr, nullptr, nullptr, scs, scq);
    bn_finalize<<<1, 64>>>(scs, scq, meanc, rstdc, 64);
    classifier_kernel<<<WRPN, 256>>>(bufC, meanc, rstdc, gc, bec, Wc2, bc2, out_ls);
}

// round 15
// speedup vs baseline: 1.5107x; 1.0140x over previous
#include <cuda_runtime.h>
#include <cuda_bf16.h>
#include <cuda_pipeline.h>
#include <math.h>

#define NN 50000
#define EE 800000
#define OUTC 40
#define NTILE 196            // ceil(50000/256)

__device__ __align__(128) float g_scratch[29000000];

#define PACK2(dst, lo, hi) asm("mov.b64 %0, {%1, %2};" : "=l"(dst) : "f"(lo), "f"(hi))
#define UNPK2(lo, hi, v)   asm("mov.b64 {%0, %1}, %2;" : "=f"(lo), "=f"(hi) : "l"(v))
#define FMA2(acc, a, b)    asm("fma.rn.f32x2 %0, %1, %2, %0;" : "+l"(acc) : "l"(a), "l"(b))

// ======================= init: counts, flag, float stat accumulators =======
__global__ void init_kernel(int* c1, int* c2, int* flag64, float* statz) {
    int i = blockIdx.x * blockDim.x + threadIdx.x;
    if (i < NN) { c1[i] = 1; c2[i] = 0; }     // c1 starts at 1 (self-loop)
    if (i == 0) *flag64 = 1;
    if (i < 640) statz[i] = 0.f;
}

__global__ void detect_kernel(const int* __restrict__ w, int* flag64) {
    int any = 0;
    for (int i = blockIdx.x * blockDim.x + threadIdx.x; i < EE; i += gridDim.x * blockDim.x)
        any |= w[2 * i + 1];
    if (any) atomicAnd(flag64, 0);
}

// convert edge_index to int32 row/col AND histogram in one pass
__global__ void convert_hist_kernel(const int* __restrict__ w, const int* __restrict__ flag64,
                                    int* __restrict__ rowA, int* __restrict__ colA,
                                    int* c1, int* c2) {
    int e = blockIdx.x * blockDim.x + threadIdx.x;
    if (e >= EE) return;
    int r, c;
    if (*flag64) { r = w[2 * e]; c = w[2 * (EE + e)]; }
    else         { r = w[e];     c = w[EE + e]; }
    rowA[e] = r; colA[e] = c;
    atomicAdd(&c1[c], 1);
    atomicAdd(&c2[r], 1);
}

// ---- parallel 3-phase exclusive scan over two arrays (gridDim.y selects) ----
__global__ void scan_p1(const int* __restrict__ cnt1, const int* __restrict__ cnt2,
                        int* __restrict__ btot) {
    const int* cnt = blockIdx.y ? cnt2 : cnt1;
    __shared__ int sw[8];
    int idx = blockIdx.x * 256 + threadIdx.x;
    int v = (idx < NN) ? cnt[idx] : 0;
#pragma unroll
    for (int d = 16; d; d >>= 1) v += __shfl_xor_sync(0xffffffffu, v, d);
    if ((threadIdx.x & 31) == 0) sw[threadIdx.x >> 5] = v;
    __syncthreads();
    if (threadIdx.x == 0) {
        int s = 0;
#pragma unroll
        for (int i = 0; i < 8; i++) s += sw[i];
        btot[blockIdx.y * (NTILE + 1) + blockIdx.x] = s;
    }
}

__global__ void scan_p2(int* __restrict__ btot) {
    int* b = btot + blockIdx.y * (NTILE + 1);
    __shared__ int sw[8], sw2[9];
    int t = threadIdx.x, lane = t & 31, wid = t >> 5;
    int v = (t < NTILE) ? b[t] : 0;
    int inc = v;
#pragma unroll
    for (int d = 1; d < 32; d <<= 1) { int y = __shfl_up_sync(0xffffffffu, inc, d); if (lane >= d) inc += y; }
    if (lane == 31) sw[wid] = inc;
    __syncthreads();
    if (t == 0) { sw2[0] = 0; for (int i = 0; i < 8; i++) sw2[i + 1] = sw2[i] + sw[i]; }
    __syncthreads();
    int excl = sw2[wid] + inc - v;
    if (t < NTILE) b[t] = excl;
    if (t == 0) b[NTILE] = sw2[8];
}

// scan phase 3 + cursor init + self-loop placement
__global__ void scan_p3(const int* __restrict__ cnt1, const int* __restrict__ cnt2,
                        const int* __restrict__ btot,
                        int* __restrict__ off1, int* __restrict__ off2,
                        int* __restrict__ cur1, int* __restrict__ cur2, int* __restrict__ csr1) {
    const int* cnt = blockIdx.y ? cnt2 : cnt1;
    int* off = blockIdx.y ? off2 : off1;
    const int* b = btot + blockIdx.y * (NTILE + 1);
    __shared__ int sw[8], sw2[9];
    int t = threadIdx.x, lane = t & 31, wid = t >> 5;
    int idx = blockIdx.x * 256 + t;
    int v = (idx < NN) ? cnt[idx] : 0;
    int inc = v;
#pragma unroll
    for (int d = 1; d < 32; d <<= 1) { int y = __shfl_up_sync(0xffffffffu, inc, d); if (lane >= d) inc += y; }
    if (lane == 31) sw[wid] = inc;
    __syncthreads();
    if (t == 0) { sw2[0] = 0; for (int i = 0; i < 8; i++) sw2[i + 1] = sw2[i] + sw[i]; }
    __syncthreads();
    int excl = b[blockIdx.x] + sw2[wid] + inc - v;
    if (idx < NN) {
        off[idx] = excl;
        if (blockIdx.y == 0) { cur1[idx] = excl + 1; csr1[excl] = idx; }
        else                 cur2[idx] = excl;
    }
    if (blockIdx.x == 0 && t == 0) off[NN] = b[NTILE];
}

__global__ void fill_kernel(const int* __restrict__ rowA, const int* __restrict__ colA,
                            int* cur1, int* csr1,
                            int* cur2, int* csr2c, int* csr2e) {
    int e = blockIdx.x * blockDim.x + threadIdx.x;
    if (e >= EE) return;
    int r = rowA[e];
    int c = colA[e];
    int p = atomicAdd(&cur1[c], 1);
    csr1[p] = r;
    int q = atomicAdd(&cur2[r], 1);
    csr2c[q] = c;
    csr2e[q] = e;
}

// ======================= weight fusion: Wf = Wg1 @ W_res, bf = Wg1 @ b_res ==
__global__ void wfuse_kernel(const float* __restrict__ Wg1, const float* __restrict__ W_res,
                             const float* __restrict__ b_res,
                             float* __restrict__ Wf, float* __restrict__ bf) {
    __shared__ float sWg[128];
    __shared__ float red[128];
    int d = blockIdx.x, k = threadIdx.x;
    sWg[k] = Wg1[d * 128 + k];
    __syncthreads();
    float s = 0.f;
#pragma unroll 8
    for (int j = 0; j < 128; j++) s = fmaf(sWg[j], W_res[j * 128 + k], s);
    Wf[d * 128 + k] = s;
    red[k] = sWg[k] * b_res[k];
    __syncthreads();
    for (int st = 64; st; st >>= 1) { if (k < st) red[k] += red[k + st]; __syncthreads(); }
    if (k == 0) bf[d] = red[0];
}

// ======================= GEMM (K = 128 fixed, f32x2 FMA, cp.async) =========

template <int TC, bool ATTN, bool STATS, bool SPLITW>
__global__ void __launch_bounds__(128, 4)
gemm_k128(const float* __restrict__ A, const float* __restrict__ W,
          int ldw, int woff, const float* __restrict__ bias,
          float* __restrict__ out, int opitch, int ocol, int nrows,
          const float* __restrict__ as, const float* __restrict__ ad,
          float* __restrict__ asrc, float* __restrict__ adst,
          float* gsum, float* gsq) {
    constexpr int CT = TC / 16;
    constexpr int PA = 68;
    constexpr int PW = TC + 4;
    __shared__ float sA[2][32 * PA];
    __shared__ float sW[2][32 * PW];
    const int tid = threadIdx.x;
    const int trow = tid >> 4;     // 0..7
    const int tcol = tid & 15;     // 0..15
    const int r0 = blockIdx.x * 64;

    unsigned long long acc2[4][CT];   // row-pairs x cols
#pragma unroll
    for (int p = 0; p < 4; p++)
#pragma unroll
        for (int j = 0; j < CT; j++) acc2[p][j] = 0ull;

    auto loadTiles = [&](int buf, int kb) {
#pragma unroll
        for (int i = 0; i < 16; i++) {
            int idx = tid + i * 128;
            int row = idx >> 5, kk = idx & 31;
            int gr = r0 + row;
            if (gr < nrows)
                __pipeline_memcpy_async(&sA[buf][kk * PA + row],
                                        &A[(size_t)gr * 128 + kb + kk], 4);
            else
                sA[buf][kk * PA + row] = 0.f;
        }
#pragma unroll
        for (int i = 0; i < (TC * 32) / 128; i++) {
            int idx = tid + i * 128;
            int col = idx >> 5, kk = idx & 31;
            int wrow = SPLITW ? (col & 63) : col;
            int wko  = SPLITW ? ((col >> 6) * 128) : 0;
            __pipeline_memcpy_async(&sW[buf][kk * PW + col],
                                    &W[(size_t)wrow * ldw + woff + wko + kb + kk], 4);
        }
        __pipeline_commit();
    };

    loadTiles(0, 0);
    int buf = 0;

    for (int kb = 0; kb < 128; kb += 32) {
        if (kb + 32 < 128) loadTiles(buf ^ 1, kb + 32);
        if (kb + 32 < 128) __pipeline_wait_prior(1);
        else               __pipeline_wait_prior(0);
        __syncthreads();
        const float* cA = sA[buf];
        const float* cW = sW[buf];
#pragma unroll
        for (int kk = 0; kk < 32; kk++) {
            unsigned long long ap[4];
#pragma unroll
            for (int p = 0; p < 4; p++)
                ap[p] = *(const unsigned long long*)&cA[kk * PA + trow * 8 + 2 * p];
            float w[CT];
#pragma unroll
            for (int j = 0; j < CT; j += 4) {
                float4 wv = *(const float4*)&cW[kk * PW + tcol * CT + j];
                w[j] = wv.x; w[j + 1] = wv.y; w[j + 2] = wv.z; w[j + 3] = wv.w;
            }
            unsigned long long wd[CT];
#pragma unroll
            for (int j = 0; j < CT; j++) PACK2(wd[j], w[j], w[j]);
#pragma unroll
            for (int p = 0; p < 4; p++)
#pragma unroll
                for (int j = 0; j < CT; j++) FMA2(acc2[p][j], ap[p], wd[j]);
        }
        __syncthreads();
        buf ^= 1;
    }
    // ---- store ----
#pragma unroll
    for (int p = 0; p < 4; p++) {
        int gr0 = r0 + trow * 8 + 2 * p;
#pragma unroll
        for (int j = 0; j < CT; j++) {
            int col = tcol * CT + j;
            float b = bias ? bias[col] : 0.f;
            float lo, hi;
            UNPK2(lo, hi, acc2[p][j]);
            if (gr0 < nrows)     out[(size_t)gr0 * opitch + ocol + col]       = lo + b;
            if (gr0 + 1 < nrows) out[(size_t)(gr0 + 1) * opitch + ocol + col] = hi + b;
        }
    }
    // ---- fused attention dots (TC=128 only) ----
    if (ATTN) {
#pragma unroll
        for (int p = 0; p < 4; p++) {
            float s1lo = 0.f, s2lo = 0.f, s1hi = 0.f, s2hi = 0.f;
#pragma unroll
            for (int j = 0; j < CT; j++) {
                int col = tcol * CT + j;
                float aS = __ldg(&as[col]), aD = __ldg(&ad[col]);
                float lo, hi;
                UNPK2(lo, hi, acc2[p][j]);
                s1lo = fmaf(lo, aS, s1lo); s2lo = fmaf(lo, aD, s2lo);
                s1hi = fmaf(hi, aS, s1hi); s2hi = fmaf(hi, aD, s2hi);
            }
            s1lo += __shfl_xor_sync(0xffffffffu, s1lo, 1);
            s2lo += __shfl_xor_sync(0xffffffffu, s2lo, 1);
            s1hi += __shfl_xor_sync(0xffffffffu, s1hi, 1);
            s2hi += __shfl_xor_sync(0xffffffffu, s2hi, 1);
            if (!(tcol & 1)) {
                int h = tcol >> 1;
                int rlo = r0 + trow * 8 + 2 * p;
                if (rlo < nrows)     { asrc[rlo * 8 + h] = s1lo;       adst[rlo * 8 + h] = s2lo; }
                if (rlo + 1 < nrows) { asrc[(rlo + 1) * 8 + h] = s1hi; adst[(rlo + 1) * 8 + h] = s2hi; }
            }
        }
    }
    // ---- fused per-feature BN statistics ----
    if (STATS) {
        __shared__ float s_s[8][TC], s_q[8][TC];
#pragma unroll
        for (int j = 0; j < CT; j++) {
            int col = tcol * CT + j;
            float b = bias ? bias[col] : 0.f;
            float ps = 0.f, pq = 0.f;
#pragma unroll
            for (int p = 0; p < 4; p++) {
                int gr0 = r0 + trow * 8 + 2 * p;
                float lo, hi;
                UNPK2(lo, hi, acc2[p][j]);
                if (gr0 < nrows)     { float v = lo + b; ps += v; pq = fmaf(v, v, pq); }
                if (gr0 + 1 < nrows) { float v = hi + b; ps += v; pq = fmaf(v, v, pq); }
            }
            s_s[trow][col] = ps;
            s_q[trow][col] = pq;
        }
        __syncthreads();
        if (tid < TC) {
            float S = 0.f, Q = 0.f;
#pragma unroll
            for (int w = 0; w < 8; w++) { S += s_s[w][tid]; Q += s_q[w][tid]; }
            atomicAdd(&gsum[tid], S);
            atomicAdd(&gsq[tid],  Q);
        }
    }
}

// ======================= GAT aggregation (online softmax + BN stats) =======
// one warp per node; unrolled x4 for memory-level parallelism

__global__ void __launch_bounds__(256)
gat_aggregate(const float* __restrict__ hfeat,
              const float* __restrict__ asrc, const float* __restrict__ adst,
              const int* __restrict__ off, const int* __restrict__ csr,
              const float* __restrict__ bg, float* __restrict__ outp,
              float* gsum, float* gsq) {
    __shared__ float s_v[8][128];
    int gw = (blockIdx.x * blockDim.x + threadIdx.x) >> 5;
    int lane = threadIdx.x & 31;
    int wib = threadIdx.x >> 5;
    int head = lane >> 2;
    float ad = adst[gw * 8 + head];
    float mm = -INFINITY, den = 0.f;
    float4 acc = make_float4(0.f, 0.f, 0.f, 0.f);
    int s0 = off[gw], s1 = off[gw + 1];
    int i = s0;
    for (; i + 3 < s1; i += 4) {
        int sa = csr[i], sb = csr[i + 1], sc2 = csr[i + 2], sd = csr[i + 3];
        float ea = asrc[sa * 8 + head] + ad;
        float eb = asrc[sb * 8 + head] + ad;
        float ec = asrc[sc2 * 8 + head] + ad;
        float ed = asrc[sd * 8 + head] + ad;
        ea = (ea >= 0.f) ? ea : 0.2f * ea;
        eb = (eb >= 0.f) ? eb : 0.2f * eb;
        ec = (ec >= 0.f) ? ec : 0.2f * ec;
        ed = (ed >= 0.f) ? ed : 0.2f * ed;
        float4 ha = *(const float4*)&hfeat[(size_t)sa * 128 + lane * 4];
        float4 hb = *(const float4*)&hfeat[(size_t)sb * 128 + lane * 4];
        float4 hc = *(const float4*)&hfeat[(size_t)sc2 * 128 + lane * 4];
        float4 hd = *(const float4*)&hfeat[(size_t)sd * 128 + lane * 4];
        float m4 = fmaxf(fmaxf(ea, eb), fmaxf(ec, ed));
        if (m4 > mm) {
            float sc = __expf(mm - m4);
            den *= sc;
            acc.x *= sc; acc.y *= sc; acc.z *= sc; acc.w *= sc;
            mm = m4;
        }
        float pa = __expf(ea - mm);
        float pb = __expf(eb - mm);
        float pc = __expf(ec - mm);
        float pd = __expf(ed - mm);
        den += (pa + pb) + (pc + pd);
        acc.x = fmaf(ha.x, pa, fmaf(hb.x, pb, fmaf(hc.x, pc, fmaf(hd.x, pd, acc.x))));
        acc.y = fmaf(ha.y, pa, fmaf(hb.y, pb, fmaf(hc.y, pc, fmaf(hd.y, pd, acc.y))));
        acc.z = fmaf(ha.z, pa, fmaf(hb.z, pb, fmaf(hc.z, pc, fmaf(hd.z, pd, acc.z))));
        acc.w = fmaf(ha.w, pa, fmaf(hb.w, pb, fmaf(hc.w, pc, fmaf(hd.w, pd, acc.w))));
    }
    for (; i < s1; i++) {
        int s = csr[i];
        float e = asrc[s * 8 + head] + ad;
        e = (e >= 0.f) ? e : 0.2f * e;
        if (e > mm) {
            float sc = __expf(mm - e);
            den *= sc;
            acc.x *= sc; acc.y *= sc; acc.z *= sc; acc.w *= sc;
            mm = e;
        }
        float p = __expf(e - mm);
        den += p;
        float4 hv = *(const float4*)&hfeat[(size_t)s * 128 + lane * 4];
        acc.x = fmaf(hv.x, p, acc.x);
        acc.y = fmaf(hv.y, p, acc.y);
        acc.z = fmaf(hv.z, p, acc.z);
        acc.w = fmaf(hv.w, p, acc.w);
    }
    float inv = 1.f / (den + 1e-16f);
    float4 bgv = *(const float4*)&bg[lane * 4];
    acc.x = fmaf(acc.x, inv, bgv.x);
    acc.y = fmaf(acc.y, inv, bgv.y);
    acc.z = fmaf(acc.z, inv, bgv.z);
    acc.w = fmaf(acc.w, inv, bgv.w);
    *(float4*)&outp[(size_t)gw * 128 + lane * 4] = acc;
    *(float4*)&s_v[wib][lane * 4] = acc;
    __syncthreads();
    int t = threadIdx.x;
    if (t < 128) {
        float S = 0.f, Q = 0.f;
#pragma unroll
        for (int w = 0; w < 8; w++) { float v = s_v[w][t]; S += v; Q = fmaf(v, v, Q); }
        atomicAdd(&gsum[t], S);
        atomicAdd(&gsq[t],  Q);
    }
}

// ======================= BN finalize + BN-ELU ==============================

__global__ void bn_finalize(const float* __restrict__ gs, const float* __restrict__ gq,
                            float* mean, float* rstd, int F) {
    int f = threadIdx.x;
    if (f < F) {
        double invN = 1.0 / (double)NN;
        double mu = (double)gs[f] * invN;
        double var = (double)gq[f] * invN - mu * mu;
        if (var < 0.0) var = 0.0;
        mean[f] = (float)mu;
        rstd[f] = rsqrtf((float)var + 1e-5f);
    }
}

__global__ void bn_elu_kernel(const float* __restrict__ x, const float* __restrict__ mean,
                              const float* __restrict__ rstd, const float* __restrict__ gamma,
                              const float* __restrict__ beta, float* __restrict__ out, int total) {
    int i = (blockIdx.x * blockDim.x + threadIdx.x) * 4;
    if (i >= total) return;
    float4 v = *(const float4*)&x[i];
    int f = i & 127;
    float r[4] = {v.x, v.y, v.z, v.w};
#pragma unroll
    for (int k = 0; k < 4; k++) {
        int ff = f + k;
        float t = (r[k] - mean[ff]) * rstd[ff] * gamma[ff] + beta[ff];
        r[k] = (t > 0.f) ? t : expm1f(t);
    }
    *(float4*)&out[i] = make_float4(r[0], r[1], r[2], r[3]);
}

// ======================= Edge gate + sparse aggregation, fused =============
// warp per row-node; gumbel loads hoisted above the butterfly reduction.

__global__ void __launch_bounds__(256)
edge_gate_agg(const float* __restrict__ prpc,
              const float* __restrict__ hbase,
              const int* __restrict__ off2,
              const int* __restrict__ col2, const int* __restrict__ eid2,
              const float* __restrict__ gumbel,
              const float* __restrict__ bs1,
              const float* __restrict__ ws2,
              const float* __restrict__ bs2,
              float* __restrict__ wout, float* __restrict__ lrout,
              float* __restrict__ outp) {
    __shared__ float sw2[64];
    __shared__ float sb1[64];
    if (threadIdx.x < 64) { sw2[threadIdx.x] = ws2[threadIdx.x]; sb1[threadIdx.x] = bs1[threadIdx.x]; }
    __syncthreads();
    int gw = (blockIdx.x * blockDim.x + threadIdx.x) >> 5;
    if (gw >= NN) return;
    int lane = threadIdx.x & 31;
    float pr0 = prpc[(size_t)gw * 128 + lane]      + sb1[lane];
    float pr1 = prpc[(size_t)gw * 128 + 32 + lane] + sb1[32 + lane];
    float w0 = sw2[lane], w1 = sw2[32 + lane];
    float bias2 = bs2[0];
    float4 acc = *(const float4*)&hbase[(size_t)gw * 128 + lane * 4];
    int s0 = off2[gw], s1 = off2[gw + 1];
    int i = s0;
    for (; i + 1 < s1; i += 2) {
        int ca = col2[i],  cb = col2[i + 1];
        int ea = eid2[i],  eb = eid2[i + 1];
        // hoist gumbel loads (lane 0/1) so they complete under the butterfly
        float ga0 = 0.f, ga1 = 0.f, gb0 = 0.f, gb1 = 0.f;
        if (lane == 0) {
            float2 gA = *(const float2*)&gumbel[2 * (size_t)ea];
            float2 gB = *(const float2*)&gumbel[2 * (size_t)eb];
            ga0 = gA.x; ga1 = gA.y; gb0 = gB.x; gb1 = gB.y;
        }
        float a0 = prpc[(size_t)ca * 128 + 64 + lane];
        float a1 = prpc[(size_t)ca * 128 + 96 + lane];
        float b0 = prpc[(size_t)cb * 128 + 64 + lane];
        float b1 = prpc[(size_t)cb * 128 + 96 + lane];
        float pa = fmaxf(pr0 + a0, 0.f) * w0 + fmaxf(pr1 + a1, 0.f) * w1;
        float pb = fmaxf(pr0 + b0, 0.f) * w0 + fmaxf(pr1 + b1, 0.f) * w1;
#pragma unroll
        for (int d = 16; d; d >>= 1) {
            pa += __shfl_xor_sync(0xffffffffu, pa, d);
            pb += __shfl_xor_sync(0xffffffffu, pb, d);
        }
        float lra = pa + bias2, lrb = pb + bias2;
        int ga = 0, gb = 0;
        if (lane == 0) {
            lrout[ea] = lra;
            lrout[eb] = lrb;
            ga = (lra + ga1 > ga0) ? 1 : 0;
            gb = (lrb + gb1 > gb0) ? 1 : 0;
            wout[ea] = ga ? 1.f : 0.f;
            wout[eb] = gb ? 1.f : 0.f;
        }
        ga = __shfl_sync(0xffffffffu, ga, 0);
        gb = __shfl_sync(0xffffffffu, gb, 0);
        if (ga) {
            float4 h = *(const float4*)&hbase[(size_t)ca * 128 + lane * 4];
            acc.x += h.x; acc.y += h.y; acc.z += h.z; acc.w += h.w;
        }
        if (gb) {
            float4 h = *(const float4*)&hbase[(size_t)cb * 128 + lane * 4];
            acc.x += h.x; acc.y += h.y; acc.z += h.z; acc.w += h.w;
        }
    }
    if (i < s1) {
        int c = col2[i], e = eid2[i];
        float g0 = 0.f, g1 = 0.f;
        if (lane == 0) {
            float2 gA = *(const float2*)&gumbel[2 * (size_t)e];
            g0 = gA.x; g1 = gA.y;
        }
        float a0 = prpc[(size_t)c * 128 + 64 + lane];
        float a1 = prpc[(size_t)c * 128 + 96 + lane];
        float p = fmaxf(pr0 + a0, 0.f) * w0 + fmaxf(pr1 + a1, 0.f) * w1;
#pragma unroll
        for (int d = 16; d; d >>= 1) p += __shfl_xor_sync(0xffffffffu, p, d);
        float lr = p + bias2;
        int g = 0;
        if (lane == 0) {
            lrout[e] = lr;
            g = (lr + g1 > g0) ? 1 : 0;
            wout[e] = g ? 1.f : 0.f;
        }
        g = __shfl_sync(0xffffffffu, g, 0);
        if (g) {
            float4 h = *(const float4*)&hbase[(size_t)c * 128 + lane * 4];
            acc.x += h.x; acc.y += h.y; acc.z += h.z; acc.w += h.w;
        }
    }
    *(float4*)&outp[(size_t)gw * 128 + lane * 4] = acc;
}

// ======================= Classifier head ===================================

__global__ void __launch_bounds__(256)
classifier_kernel(const float* __restrict__ cpre, const float* __restrict__ mean,
                  const float* __restrict__ rstd, const float* __restrict__ gc,
                  const float* __restrict__ bec, const float* __restrict__ Wc2,
                  const float* __restrict__ bc2, float* __restrict__ outls) {
    __shared__ float sW[64 * 64];
    __shared__ float sb[40];
    __shared__ float sc[8][64];
    for (int idx = threadIdx.x; idx < 64 * 64; idx += blockDim.x) {
        int f = idx >> 6, j = idx & 63;
        sW[idx] = (j < 40) ? Wc2[j * 64 + f] : 0.f;
    }
    if (threadIdx.x < 40) sb[threadIdx.x] = bc2[threadIdx.x];
    __syncthreads();
    int gw = (blockIdx.x * blockDim.x + threadIdx.x) >> 5;
    int lane = threadIdx.x & 31;
    int wib = threadIdx.x >> 5;
    if (gw >= NN) return;
    float v0 = cpre[(size_t)gw * 64 + lane];
    float v1 = cpre[(size_t)gw * 64 + 32 + lane];
    int f0 = lane, f1 = lane + 32;
    sc[wib][lane]      = fmaxf((v0 - mean[f0]) * rstd[f0] * gc[f0] + bec[f0], 0.f);
    sc[wib][lane + 32] = fmaxf((v1 - mean[f1]) * rstd[f1] * gc[f1] + bec[f1], 0.f);
    __syncwarp();
    float l0 = sb[lane];
    float l1 = (lane < 8) ? sb[lane + 32] : 0.f;
#pragma unroll
    for (int f = 0; f < 64; f++) {
        float cv = sc[wib][f];
        l0 = fmaf(cv, sW[f * 64 + lane], l0);
        l1 = fmaf(cv, sW[f * 64 + lane + 32], l1);
    }
    float mx = fmaxf(l0, (lane < 8) ? l1 : -INFINITY);
#pragma unroll
    for (int d = 16; d; d >>= 1) mx = fmaxf(mx, __shfl_xor_sync(0xffffffffu, mx, d));
    float s = expf(l0 - mx) + ((lane < 8) ? expf(l1 - mx) : 0.f);
#pragma unroll
    for (int d = 16; d; d >>= 1) s += __shfl_xor_sync(0xffffffffu, s, d);
    float lse = mx + logf(s);
    outls[(size_t)gw * 40 + lane] = l0 - lse;
    if (lane < 8) outls[(size_t)gw * 40 + 32 + lane] = l1 - lse;
}

// ======================= Host orchestration ================================

extern "C" void kernel_launch(void* const* d_in, const int* in_sizes, int n_in,
                              void* d_out, int out_size) {
    (void)in_sizes; (void)n_in; (void)out_size;

    float* S = nullptr;
    cudaGetSymbolAddress((void**)&S, g_scratch);

    float* bufA = S;                       // N*128
    float* bufH = S + 6400000;             // N*128
    float* bufG = S + 12800000;            // N*128
    float* bufC = S + 19200000;            // N*64
    float* asrc = S + 22400000;            // N*8
    float* adst = S + 22800000;
    float* fpar = S + 23200000;
    float* mean1 = fpar,       * rstd1 = fpar + 128;
    float* mean2 = fpar + 256, * rstd2 = fpar + 384;
    float* meanc = fpar + 512, * rstdc = fpar + 640;
    float* stat  = S + 23201024;
    float* s1s = stat,       * s1q = stat + 128;
    float* s2s = stat + 256, * s2q = stat + 384;
    float* scs = stat + 512, * scq = stat + 576;
    float* Wf   = S + 23300000;            // 128*128 fused weight
    float* bf   = Wf + 16384;              // 128 fused bias
    int* ip    = (int*)(S + 24000000);
    int* rowA  = ip;
    int* colA  = rowA + EE;
    int* off1  = colA + EE;
    int* off2  = off1 + (NN + 1);
    int* cur1  = off2 + (NN + 1);
    int* cur2  = cur1 + NN;
    int* cnt1  = cur2 + NN;
    int* cnt2  = cnt1 + NN;
    int* csr1  = cnt2 + NN;
    int* csr2c = csr1 + (EE + NN);
    int* csr2e = csr2c + EE;
    int* flag64 = csr2e + EE;
    int* btot   = flag64 + 1;

    const float* x      = (const float*)d_in[0];
    const int*   eiw    = (const int*)d_in[1];
    const float* gumbel = (const float*)d_in[2];
    const float* W_res  = (const float*)d_in[3];
    const float* b_res  = (const float*)d_in[4];
    const float* Wg1    = (const float*)d_in[5];
    const float* as1    = (const float*)d_in[6];
    const float* ad1    = (const float*)d_in[7];
    const float* bg1    = (const float*)d_in[8];
    const float* g1     = (const float*)d_in[9];
    const float* be1    = (const float*)d_in[10];
    const float* Wg2    = (const float*)d_in[11];
    const float* as2    = (const float*)d_in[12];
    const float* ad2    = (const float*)d_in[13];
    const float* bg2    = (const float*)d_in[14];
    const float* g2     = (const float*)d_in[15];
    const float* be2    = (const float*)d_in[16];
    const float* Ws1    = (const float*)d_in[17];
    const float* bs1    = (const float*)d_in[18];
    const float* Ws2    = (const float*)d_in[19];
    const float* bs2    = (const float*)d_in[20];
    const float* Wc1    = (const float*)d_in[21];
    const float* bc1    = (const float*)d_in[22];
    const float* gc     = (const float*)d_in[23];
    const float* bec    = (const float*)d_in[24];
    const float* Wc2    = (const float*)d_in[25];
    const float* bc2    = (const float*)d_in[26];

    float* out_ls = (float*)d_out;
    float* out_w  = out_ls + (size_t)NN * OUTC;
    float* out_lr = out_w + EE;

    const int NB   = (NN + 255) / 256;
    const int EB   = (EE + 255) / 256;
    const int WRPN = (NN * 32) / 256;
    const int GEMG = (NN + 63) / 64;

    // ---- fork: CSR build on side stream, GEMMs on main stream ----
    cudaStream_t s1str;
    cudaEvent_t evFork, evJoin;
    cudaStreamCreateWithFlags(&s1str, cudaStreamNonBlocking);
    cudaEventCreateWithFlags(&evFork, cudaEventDisableTiming);
    cudaEventCreateWithFlags(&evJoin, cudaEventDisableTiming);

    cudaEventRecord(evFork, 0);
    cudaStreamWaitEvent(s1str, evFork, 0);

    // side stream: CSR build chain
    init_kernel<<<NB, 256, 0, s1str>>>(cnt1, cnt2, flag64, stat);
    detect_kernel<<<256, 256, 0, s1str>>>(eiw, flag64);
    convert_hist_kernel<<<EB, 256, 0, s1str>>>(eiw, flag64, rowA, colA, cnt1, cnt2);
    scan_p1<<<dim3(NTILE, 2), 256, 0, s1str>>>(cnt1, cnt2, btot);
    scan_p2<<<dim3(1, 2), 256, 0, s1str>>>(btot);
    scan_p3<<<dim3(NTILE, 2), 256, 0, s1str>>>(cnt1, cnt2, btot, off1, off2, cur1, cur2, csr1);
    fill_kernel<<<EB, 256, 0, s1str>>>(rowA, colA, cur1, csr1, cur2, csr2c, csr2e);
    cudaEventRecord(evJoin, s1str);

    // main stream: weight fusion, then fused h1 GEMM (+attention dots)
    wfuse_kernel<<<128, 128>>>(Wg1, W_res, b_res, Wf, bf);
    gemm_k128<128, true, false, false><<<GEMG, 128>>>(
        x, Wf, 128, 0, bf, bufH, 128, 0, NN,
        as1, ad1, asrc, adst, nullptr, nullptr);

    // join: aggregation needs CSR + stats-zeroing from side stream
    cudaStreamWaitEvent(0, evJoin, 0);

    gat_aggregate<<<WRPN, 256>>>(bufH, asrc, adst, off1, csr1, bg1, bufG, s1s, s1q);
    bn_finalize<<<1, 128>>>(s1s, s1q, mean1, rstd1, 128);

    // layer-1 BN+ELU materialized, then async GEMM
    bn_elu_kernel<<<(NN * 32 + 255) / 256, 256>>>(bufG, mean1, rstd1, g1, be1, bufA, NN * 128);
    gemm_k128<128, true, false, false><<<GEMG, 128>>>(
        bufA, Wg2, 128, 0, nullptr, bufH, 128, 0, NN,
        as2, ad2, asrc, adst, nullptr, nullptr);
    gat_aggregate<<<WRPN, 256>>>(bufH, asrc, adst, off1, csr1, bg2, bufG, s2s, s2q);
    bn_finalize<<<1, 128>>>(s2s, s2q, mean2, rstd2, 128);
    bn_elu_kernel<<<(NN * 32 + 255) / 256, 256>>>(bufG, mean2, rstd2, g2, be2, bufA, NN * 128);
    // bufA = h_base

    // edge scorer GEMM (pr | pc), then fused gate + sparse aggregation
    gemm_k128<128, false, false, true><<<GEMG, 128>>>(
        bufA, Ws1, 256, 0, nullptr, bufH, 128, 0, NN,
        nullptr, nullptr, nullptr, nullptr, nullptr, nullptr);
    edge_gate_agg<<<WRPN, 256>>>(bufH, bufA, off2, csr2c, csr2e, gumbel,
                                 bs1, Ws2, bs2, out_w, out_lr, bufG);

    // classifier (BN stats fused into GEMM)
    gemm_k128<64, false, true, false><<<GEMG, 128>>>(
        bufG, Wc1, 128, 0, bc1, bufC, 64, 0, NN,
        nullptr, nullptr, nullptr, nullptr, scs, scq);
    bn_finalize<<<1, 64>>>(scs, scq, meanc, rstdc, 64);
    classifier_kernel<<<WRPN, 256>>>(bufC, meanc, rstdc, gc, bec, Wc2, bc2, out_ls);
}

// round 16
// speedup vs baseline: 1.5790x; 1.0452x over previous
#include <cuda_runtime.h>
#include <cuda_bf16.h>
#include <cuda_pipeline.h>
#include <math.h>

#define NN 50000
#define EE 800000
#define OUTC 40
#define NTILE 196            // ceil(50000/256)
#define NBKT 8               // stat atomic buckets

__device__ __align__(128) float g_scratch[29000000];

#define PACK2(dst, lo, hi) asm("mov.b64 %0, {%1, %2};" : "=l"(dst) : "f"(lo), "f"(hi))
#define UNPK2(lo, hi, v)   asm("mov.b64 {%0, %1}, %2;" : "=f"(lo), "=f"(hi) : "l"(v))
#define FMA2(acc, a, b)    asm("fma.rn.f32x2 %0, %1, %2, %0;" : "+l"(acc) : "l"(a), "l"(b))

// ======================= init: counts, flag, float stat accumulators =======
// stat layout: s1s[8*128] s1q[8*128] s2s[8*128] s2q[8*128] scs[8*64] scq[8*64]
#define STATN (4 * NBKT * 128 + 2 * NBKT * 64)

__global__ void init_kernel(int* c1, int* c2, int* flag64, float* statz) {
    int i = blockIdx.x * blockDim.x + threadIdx.x;
    if (i < NN) { c1[i] = 1; c2[i] = 0; }     // c1 starts at 1 (self-loop)
    if (i == 0) *flag64 = 1;
    if (i < STATN) statz[i] = 0.f;
}

__global__ void detect_kernel(const int* __restrict__ w, int* flag64) {
    int any = 0;
    for (int i = blockIdx.x * blockDim.x + threadIdx.x; i < EE; i += gridDim.x * blockDim.x)
        any |= w[2 * i + 1];
    if (any) atomicAnd(flag64, 0);
}

// convert edge_index to int32 row/col AND histogram in one pass
__global__ void convert_hist_kernel(const int* __restrict__ w, const int* __restrict__ flag64,
                                    int* __restrict__ rowA, int* __restrict__ colA,
                                    int* c1, int* c2) {
    int e = blockIdx.x * blockDim.x + threadIdx.x;
    if (e >= EE) return;
    int r, c;
    if (*flag64) { r = w[2 * e]; c = w[2 * (EE + e)]; }
    else         { r = w[e];     c = w[EE + e]; }
    rowA[e] = r; colA[e] = c;
    atomicAdd(&c1[c], 1);
    atomicAdd(&c2[r], 1);
}

// ---- parallel 3-phase exclusive scan over two arrays (gridDim.y selects) ----
__global__ void scan_p1(const int* __restrict__ cnt1, const int* __restrict__ cnt2,
                        int* __restrict__ btot) {
    const int* cnt = blockIdx.y ? cnt2 : cnt1;
    __shared__ int sw[8];
    int idx = blockIdx.x * 256 + threadIdx.x;
    int v = (idx < NN) ? cnt[idx] : 0;
#pragma unroll
    for (int d = 16; d; d >>= 1) v += __shfl_xor_sync(0xffffffffu, v, d);
    if ((threadIdx.x & 31) == 0) sw[threadIdx.x >> 5] = v;
    __syncthreads();
    if (threadIdx.x == 0) {
        int s = 0;
#pragma unroll
        for (int i = 0; i < 8; i++) s += sw[i];
        btot[blockIdx.y * (NTILE + 1) + blockIdx.x] = s;
    }
}

__global__ void scan_p2(int* __restrict__ btot) {
    int* b = btot + blockIdx.y * (NTILE + 1);
    __shared__ int sw[8], sw2[9];
    int t = threadIdx.x, lane = t & 31, wid = t >> 5;
    int v = (t < NTILE) ? b[t] : 0;
    int inc = v;
#pragma unroll
    for (int d = 1; d < 32; d <<= 1) { int y = __shfl_up_sync(0xffffffffu, inc, d); if (lane >= d) inc += y; }
    if (lane == 31) sw[wid] = inc;
    __syncthreads();
    if (t == 0) { sw2[0] = 0; for (int i = 0; i < 8; i++) sw2[i + 1] = sw2[i] + sw[i]; }
    __syncthreads();
    int excl = sw2[wid] + inc - v;
    if (t < NTILE) b[t] = excl;
    if (t == 0) b[NTILE] = sw2[8];
}

// scan phase 3 + cursor init + self-loop placement
__global__ void scan_p3(const int* __restrict__ cnt1, const int* __restrict__ cnt2,
                        const int* __restrict__ btot,
                        int* __restrict__ off1, int* __restrict__ off2,
                        int* __restrict__ cur1, int* __restrict__ cur2, int* __restrict__ csr1) {
    const int* cnt = blockIdx.y ? cnt2 : cnt1;
    int* off = blockIdx.y ? off2 : off1;
    const int* b = btot + blockIdx.y * (NTILE + 1);
    __shared__ int sw[8], sw2[9];
    int t = threadIdx.x, lane = t & 31, wid = t >> 5;
    int idx = blockIdx.x * 256 + t;
    int v = (idx < NN) ? cnt[idx] : 0;
    int inc = v;
#pragma unroll
    for (int d = 1; d < 32; d <<= 1) { int y = __shfl_up_sync(0xffffffffu, inc, d); if (lane >= d) inc += y; }
    if (lane == 31) sw[wid] = inc;
    __syncthreads();
    if (t == 0) { sw2[0] = 0; for (int i = 0; i < 8; i++) sw2[i + 1] = sw2[i] + sw[i]; }
    __syncthreads();
    int excl = b[blockIdx.x] + sw2[wid] + inc - v;
    if (idx < NN) {
        off[idx] = excl;
        if (blockIdx.y == 0) { cur1[idx] = excl + 1; csr1[excl] = idx; }
        else                 cur2[idx] = excl;
    }
    if (blockIdx.x == 0 && t == 0) off[NN] = b[NTILE];
}

__global__ void fill_kernel(const int* __restrict__ rowA, const int* __restrict__ colA,
                            int* cur1, int* csr1,
                            int* cur2, int* csr2c, int* csr2e) {
    int e = blockIdx.x * blockDim.x + threadIdx.x;
    if (e >= EE) return;
    int r = rowA[e];
    int c = colA[e];
    int p = atomicAdd(&cur1[c], 1);
    csr1[p] = r;
    int q = atomicAdd(&cur2[r], 1);
    csr2c[q] = c;
    csr2e[q] = e;
}

// ======================= weight fusion: Wf = Wg1 @ W_res, bf = Wg1 @ b_res ==
__global__ void wfuse_kernel(const float* __restrict__ Wg1, const float* __restrict__ W_res,
                             const float* __restrict__ b_res,
                             float* __restrict__ Wf, float* __restrict__ bf) {
    __shared__ float sWg[128];
    __shared__ float red[128];
    int d = blockIdx.x, k = threadIdx.x;
    sWg[k] = Wg1[d * 128 + k];
    __syncthreads();
    float s = 0.f;
#pragma unroll 8
    for (int j = 0; j < 128; j++) s = fmaf(sWg[j], W_res[j * 128 + k], s);
    Wf[d * 128 + k] = s;
    red[k] = sWg[k] * b_res[k];
    __syncthreads();
    for (int st = 64; st; st >>= 1) { if (k < st) red[k] += red[k + st]; __syncthreads(); }
    if (k == 0) bf[d] = red[0];
}

// ======================= GEMM (K = 128 fixed, f32x2 FMA, cp.async) =========

template <int TC, bool ATTN, bool STATS, bool SPLITW>
__global__ void __launch_bounds__(128, 4)
gemm_k128(const float* __restrict__ A, const float* __restrict__ W,
          int ldw, int woff, const float* __restrict__ bias,
          float* __restrict__ out, int opitch, int ocol, int nrows,
          const float* __restrict__ as, const float* __restrict__ ad,
          float* __restrict__ asrc, float* __restrict__ adst,
          float* gsum, float* gsq) {
    constexpr int CT = TC / 16;
    constexpr int PA = 68;
    constexpr int PW = TC + 4;
    __shared__ float sA[2][32 * PA];
    __shared__ float sW[2][32 * PW];
    const int tid = threadIdx.x;
    const int trow = tid >> 4;     // 0..7
    const int tcol = tid & 15;     // 0..15
    const int r0 = blockIdx.x * 64;

    unsigned long long acc2[4][CT];   // row-pairs x cols
#pragma unroll
    for (int p = 0; p < 4; p++)
#pragma unroll
        for (int j = 0; j < CT; j++) acc2[p][j] = 0ull;

    auto loadTiles = [&](int buf, int kb) {
#pragma unroll
        for (int i = 0; i < 16; i++) {
            int idx = tid + i * 128;
            int row = idx >> 5, kk = idx & 31;
            int gr = r0 + row;
            if (gr < nrows)
                __pipeline_memcpy_async(&sA[buf][kk * PA + row],
                                        &A[(size_t)gr * 128 + kb + kk], 4);
            else
                sA[buf][kk * PA + row] = 0.f;
        }
#pragma unroll
        for (int i = 0; i < (TC * 32) / 128; i++) {
            int idx = tid + i * 128;
            int col = idx >> 5, kk = idx & 31;
            int wrow = SPLITW ? (col & 63) : col;
            int wko  = SPLITW ? ((col >> 6) * 128) : 0;
            __pipeline_memcpy_async(&sW[buf][kk * PW + col],
                                    &W[(size_t)wrow * ldw + woff + wko + kb + kk], 4);
        }
        __pipeline_commit();
    };

    loadTiles(0, 0);
    int buf = 0;

    for (int kb = 0; kb < 128; kb += 32) {
        if (kb + 32 < 128) loadTiles(buf ^ 1, kb + 32);
        if (kb + 32 < 128) __pipeline_wait_prior(1);
        else               __pipeline_wait_prior(0);
        __syncthreads();
        const float* cA = sA[buf];
        const float* cW = sW[buf];
#pragma unroll
        for (int kk = 0; kk < 32; kk++) {
            unsigned long long ap[4];
#pragma unroll
            for (int p = 0; p < 4; p++)
                ap[p] = *(const unsigned long long*)&cA[kk * PA + trow * 8 + 2 * p];
            float w[CT];
#pragma unroll
            for (int j = 0; j < CT; j += 4) {
                float4 wv = *(const float4*)&cW[kk * PW + tcol * CT + j];
                w[j] = wv.x; w[j + 1] = wv.y; w[j + 2] = wv.z; w[j + 3] = wv.w;
            }
            unsigned long long wd[CT];
#pragma unroll
            for (int j = 0; j < CT; j++) PACK2(wd[j], w[j], w[j]);
#pragma unroll
            for (int p = 0; p < 4; p++)
#pragma unroll
                for (int j = 0; j < CT; j++) FMA2(acc2[p][j], ap[p], wd[j]);
        }
        __syncthreads();
        buf ^= 1;
    }
    // ---- store ----
#pragma unroll
    for (int p = 0; p < 4; p++) {
        int gr0 = r0 + trow * 8 + 2 * p;
#pragma unroll
        for (int j = 0; j < CT; j++) {
            int col = tcol * CT + j;
            float b = bias ? bias[col] : 0.f;
            float lo, hi;
            UNPK2(lo, hi, acc2[p][j]);
            if (gr0 < nrows)     out[(size_t)gr0 * opitch + ocol + col]       = lo + b;
            if (gr0 + 1 < nrows) out[(size_t)(gr0 + 1) * opitch + ocol + col] = hi + b;
        }
    }
    // ---- fused attention dots (TC=128 only) ----
    if (ATTN) {
#pragma unroll
        for (int p = 0; p < 4; p++) {
            float s1lo = 0.f, s2lo = 0.f, s1hi = 0.f, s2hi = 0.f;
#pragma unroll
            for (int j = 0; j < CT; j++) {
                int col = tcol * CT + j;
                float aS = __ldg(&as[col]), aD = __ldg(&ad[col]);
                float lo, hi;
                UNPK2(lo, hi, acc2[p][j]);
                s1lo = fmaf(lo, aS, s1lo); s2lo = fmaf(lo, aD, s2lo);
                s1hi = fmaf(hi, aS, s1hi); s2hi = fmaf(hi, aD, s2hi);
            }
            s1lo += __shfl_xor_sync(0xffffffffu, s1lo, 1);
            s2lo += __shfl_xor_sync(0xffffffffu, s2lo, 1);
            s1hi += __shfl_xor_sync(0xffffffffu, s1hi, 1);
            s2hi += __shfl_xor_sync(0xffffffffu, s2hi, 1);
            if (!(tcol & 1)) {
                int h = tcol >> 1;
                int rlo = r0 + trow * 8 + 2 * p;
                if (rlo < nrows)     { asrc[rlo * 8 + h] = s1lo;       adst[rlo * 8 + h] = s2lo; }
                if (rlo + 1 < nrows) { asrc[(rlo + 1) * 8 + h] = s1hi; adst[(rlo + 1) * 8 + h] = s2hi; }
            }
        }
    }
    // ---- fused per-feature BN statistics (bucketed) ----
    if (STATS) {
        __shared__ float s_s[8][TC], s_q[8][TC];
#pragma unroll
        for (int j = 0; j < CT; j++) {
            int col = tcol * CT + j;
            float b = bias ? bias[col] : 0.f;
            float ps = 0.f, pq = 0.f;
#pragma unroll
            for (int p = 0; p < 4; p++) {
                int gr0 = r0 + trow * 8 + 2 * p;
                float lo, hi;
                UNPK2(lo, hi, acc2[p][j]);
                if (gr0 < nrows)     { float v = lo + b; ps += v; pq = fmaf(v, v, pq); }
                if (gr0 + 1 < nrows) { float v = hi + b; ps += v; pq = fmaf(v, v, pq); }
            }
            s_s[trow][col] = ps;
            s_q[trow][col] = pq;
        }
        __syncthreads();
        if (tid < TC) {
            float S = 0.f, Q = 0.f;
#pragma unroll
            for (int w = 0; w < 8; w++) { S += s_s[w][tid]; Q += s_q[w][tid]; }
            int bk = (blockIdx.x & (NBKT - 1)) * TC;
            atomicAdd(&gsum[bk + tid], S);
            atomicAdd(&gsq[bk + tid],  Q);
        }
    }
}

// ======================= GAT aggregation (online softmax + BN stats) =======
// one warp per node; unrolled x4; bucketed stats

__global__ void __launch_bounds__(256)
gat_aggregate(const float* __restrict__ hfeat,
              const float* __restrict__ asrc, const float* __restrict__ adst,
              const int* __restrict__ off, const int* __restrict__ csr,
              const float* __restrict__ bg, float* __restrict__ outp,
              float* gsum, float* gsq) {
    __shared__ float s_v[8][128];
    int gw = (blockIdx.x * blockDim.x + threadIdx.x) >> 5;
    int lane = threadIdx.x & 31;
    int wib = threadIdx.x >> 5;
    int head = lane >> 2;
    float ad = adst[gw * 8 + head];
    float mm = -INFINITY, den = 0.f;
    float4 acc = make_float4(0.f, 0.f, 0.f, 0.f);
    int s0 = off[gw], s1 = off[gw + 1];
    int i = s0;
    for (; i + 3 < s1; i += 4) {
        int sa = csr[i], sb = csr[i + 1], sc2 = csr[i + 2], sd = csr[i + 3];
        float ea = asrc[sa * 8 + head] + ad;
        float eb = asrc[sb * 8 + head] + ad;
        float ec = asrc[sc2 * 8 + head] + ad;
        float ed = asrc[sd * 8 + head] + ad;
        ea = (ea >= 0.f) ? ea : 0.2f * ea;
        eb = (eb >= 0.f) ? eb : 0.2f * eb;
        ec = (ec >= 0.f) ? ec : 0.2f * ec;
        ed = (ed >= 0.f) ? ed : 0.2f * ed;
        float4 ha = *(const float4*)&hfeat[(size_t)sa * 128 + lane * 4];
        float4 hb = *(const float4*)&hfeat[(size_t)sb * 128 + lane * 4];
        float4 hc = *(const float4*)&hfeat[(size_t)sc2 * 128 + lane * 4];
        float4 hd = *(const float4*)&hfeat[(size_t)sd * 128 + lane * 4];
        float m4 = fmaxf(fmaxf(ea, eb), fmaxf(ec, ed));
        if (m4 > mm) {
            float sc = __expf(mm - m4);
            den *= sc;
            acc.x *= sc; acc.y *= sc; acc.z *= sc; acc.w *= sc;
            mm = m4;
        }
        float pa = __expf(ea - mm);
        float pb = __expf(eb - mm);
        float pc = __expf(ec - mm);
        float pd = __expf(ed - mm);
        den += (pa + pb) + (pc + pd);
        acc.x = fmaf(ha.x, pa, fmaf(hb.x, pb, fmaf(hc.x, pc, fmaf(hd.x, pd, acc.x))));
        acc.y = fmaf(ha.y, pa, fmaf(hb.y, pb, fmaf(hc.y, pc, fmaf(hd.y, pd, acc.y))));
        acc.z = fmaf(ha.z, pa, fmaf(hb.z, pb, fmaf(hc.z, pc, fmaf(hd.z, pd, acc.z))));
        acc.w = fmaf(ha.w, pa, fmaf(hb.w, pb, fmaf(hc.w, pc, fmaf(hd.w, pd, acc.w))));
    }
    for (; i < s1; i++) {
        int s = csr[i];
        float e = asrc[s * 8 + head] + ad;
        e = (e >= 0.f) ? e : 0.2f * e;
        if (e > mm) {
            float sc = __expf(mm - e);
            den *= sc;
            acc.x *= sc; acc.y *= sc; acc.z *= sc; acc.w *= sc;
            mm = e;
        }
        float p = __expf(e - mm);
        den += p;
        float4 hv = *(const float4*)&hfeat[(size_t)s * 128 + lane * 4];
        acc.x = fmaf(hv.x, p, acc.x);
        acc.y = fmaf(hv.y, p, acc.y);
        acc.z = fmaf(hv.z, p, acc.z);
        acc.w = fmaf(hv.w, p, acc.w);
    }
    float inv = 1.f / (den + 1e-16f);
    float4 bgv = *(const float4*)&bg[lane * 4];
    acc.x = fmaf(acc.x, inv, bgv.x);
    acc.y = fmaf(acc.y, inv, bgv.y);
    acc.z = fmaf(acc.z, inv, bgv.z);
    acc.w = fmaf(acc.w, inv, bgv.w);
    *(float4*)&outp[(size_t)gw * 128 + lane * 4] = acc;
    *(float4*)&s_v[wib][lane * 4] = acc;
    __syncthreads();
    int t = threadIdx.x;
    if (t < 128) {
        float S = 0.f, Q = 0.f;
#pragma unroll
        for (int w = 0; w < 8; w++) { float v = s_v[w][t]; S += v; Q = fmaf(v, v, Q); }
        int bk = (blockIdx.x & (NBKT - 1)) * 128;
        atomicAdd(&gsum[bk + t], S);
        atomicAdd(&gsq[bk + t],  Q);
    }
}

// ======================= BN+ELU with fused finalize ========================
// mean/rstd computed per block from bucketed stat sums (fp64 finalize).

__global__ void bn_elu_kernel(const float* __restrict__ x,
                              const float* __restrict__ gs, const float* __restrict__ gq,
                              const float* __restrict__ gamma, const float* __restrict__ beta,
                              float* __restrict__ out, int total) {
    __shared__ float smean[128], srstd[128];
    int t = threadIdx.x;
    if (t < 128) {
        float S = 0.f, Q = 0.f;
#pragma unroll
        for (int b = 0; b < NBKT; b++) { S += gs[b * 128 + t]; Q += gq[b * 128 + t]; }
        double invN = 1.0 / (double)NN;
        double mu = (double)S * invN;
        double var = (double)Q * invN - mu * mu;
        if (var < 0.0) var = 0.0;
        smean[t] = (float)mu;
        srstd[t] = rsqrtf((float)var + 1e-5f);
    }
    __syncthreads();
    int i = (blockIdx.x * blockDim.x + threadIdx.x) * 4;
    if (i >= total) return;
    float4 v = *(const float4*)&x[i];
    int f = i & 127;
    float r[4] = {v.x, v.y, v.z, v.w};
#pragma unroll
    for (int k = 0; k < 4; k++) {
        int ff = f + k;
        float tt = (r[k] - smean[ff]) * srstd[ff] * gamma[ff] + beta[ff];
        r[k] = (tt > 0.f) ? tt : expm1f(tt);
    }
    *(float4*)&out[i] = make_float4(r[0], r[1], r[2], r[3]);
}

// ======================= Edge gate + sparse aggregation, fused =============

__global__ void __launch_bounds__(256)
edge_gate_agg(const float* __restrict__ prpc,
              const float* __restrict__ hbase,
              const int* __restrict__ off2,
              const int* __restrict__ col2, const int* __restrict__ eid2,
              const float* __restrict__ gumbel,
              const float* __restrict__ bs1,
              const float* __restrict__ ws2,
              const float* __restrict__ bs2,
              float* __restrict__ wout, float* __restrict__ lrout,
              float* __restrict__ outp) {
    __shared__ float sw2[64];
    __shared__ float sb1[64];
    if (threadIdx.x < 64) { sw2[threadIdx.x] = ws2[threadIdx.x]; sb1[threadIdx.x] = bs1[threadIdx.x]; }
    __syncthreads();
    int gw = (blockIdx.x * blockDim.x + threadIdx.x) >> 5;
    if (gw >= NN) return;
    int lane = threadIdx.x & 31;
    float pr0 = prpc[(size_t)gw * 128 + lane]      + sb1[lane];
    float pr1 = prpc[(size_t)gw * 128 + 32 + lane] + sb1[32 + lane];
    float w0 = sw2[lane], w1 = sw2[32 + lane];
    float bias2 = bs2[0];
    float4 acc = *(const float4*)&hbase[(size_t)gw * 128 + lane * 4];
    int s0 = off2[gw], s1 = off2[gw + 1];
    int i = s0;
    for (; i + 1 < s1; i += 2) {
        int ca = col2[i],  cb = col2[i + 1];
        int ea = eid2[i],  eb = eid2[i + 1];
        float ga0 = 0.f, ga1 = 0.f, gb0 = 0.f, gb1 = 0.f;
        if (lane == 0) {
            float2 gA = *(const float2*)&gumbel[2 * (size_t)ea];
            float2 gB = *(const float2*)&gumbel[2 * (size_t)eb];
            ga0 = gA.x; ga1 = gA.y; gb0 = gB.x; gb1 = gB.y;
        }
        float a0 = prpc[(size_t)ca * 128 + 64 + lane];
        float a1 = prpc[(size_t)ca * 128 + 96 + lane];
        float b0 = prpc[(size_t)cb * 128 + 64 + lane];
        float b1 = prpc[(size_t)cb * 128 + 96 + lane];
        float pa = fmaxf(pr0 + a0, 0.f) * w0 + fmaxf(pr1 + a1, 0.f) * w1;
        float pb = fmaxf(pr0 + b0, 0.f) * w0 + fmaxf(pr1 + b1, 0.f) * w1;
#pragma unroll
        for (int d = 16; d; d >>= 1) {
            pa += __shfl_xor_sync(0xffffffffu, pa, d);
            pb += __shfl_xor_sync(0xffffffffu, pb, d);
        }
        float lra = pa + bias2, lrb = pb + bias2;
        int ga = 0, gb = 0;
        if (lane == 0) {
            lrout[ea] = lra;
            lrout[eb] = lrb;
            ga = (lra + ga1 > ga0) ? 1 : 0;
            gb = (lrb + gb1 > gb0) ? 1 : 0;
            wout[ea] = ga ? 1.f : 0.f;
            wout[eb] = gb ? 1.f : 0.f;
        }
        ga = __shfl_sync(0xffffffffu, ga, 0);
        gb = __shfl_sync(0xffffffffu, gb, 0);
        if (ga) {
            float4 h = *(const float4*)&hbase[(size_t)ca * 128 + lane * 4];
            acc.x += h.x; acc.y += h.y; acc.z += h.z; acc.w += h.w;
        }
        if (gb) {
            float4 h = *(const float4*)&hbase[(size_t)cb * 128 + lane * 4];
            acc.x += h.x; acc.y += h.y; acc.z += h.z; acc.w += h.w;
        }
    }
    if (i < s1) {
        int c = col2[i], e = eid2[i];
        float g0 = 0.f, g1 = 0.f;
        if (lane == 0) {
            float2 gA = *(const float2*)&gumbel[2 * (size_t)e];
            g0 = gA.x; g1 = gA.y;
        }
        float a0 = prpc[(size_t)c * 128 + 64 + lane];
        float a1 = prpc[(size_t)c * 128 + 96 + lane];
        float p = fmaxf(pr0 + a0, 0.f) * w0 + fmaxf(pr1 + a1, 0.f) * w1;
#pragma unroll
        for (int d = 16; d; d >>= 1) p += __shfl_xor_sync(0xffffffffu, p, d);
        float lr = p + bias2;
        int g = 0;
        if (lane == 0) {
            lrout[e] = lr;
            g = (lr + g1 > g0) ? 1 : 0;
            wout[e] = g ? 1.f : 0.f;
        }
        g = __shfl_sync(0xffffffffu, g, 0);
        if (g) {
            float4 h = *(const float4*)&hbase[(size_t)c * 128 + lane * 4];
            acc.x += h.x; acc.y += h.y; acc.z += h.z; acc.w += h.w;
        }
    }
    *(float4*)&outp[(size_t)gw * 128 + lane * 4] = acc;
}

// ======================= Classifier head (fused BN finalize) ===============

__global__ void __launch_bounds__(256)
classifier_kernel(const float* __restrict__ cpre,
                  const float* __restrict__ gs, const float* __restrict__ gq,
                  const float* __restrict__ gc,
                  const float* __restrict__ bec, const float* __restrict__ Wc2,
                  const float* __restrict__ bc2, float* __restrict__ outls) {
    __shared__ float sW[64 * 64];
    __shared__ float sb[40];
    __shared__ float sc[8][64];
    __shared__ float smean[64], srstd[64];
    int t = threadIdx.x;
    if (t < 64) {
        float S = 0.f, Q = 0.f;
#pragma unroll
        for (int b = 0; b < NBKT; b++) { S += gs[b * 64 + t]; Q += gq[b * 64 + t]; }
        double invN = 1.0 / (double)NN;
        double mu = (double)S * invN;
        double var = (double)Q * invN - mu * mu;
        if (var < 0.0) var = 0.0;
        smean[t] = (float)mu;
        srstd[t] = rsqrtf((float)var + 1e-5f);
    }
    for (int idx = t; idx < 64 * 64; idx += blockDim.x) {
        int f = idx >> 6, j = idx & 63;
        sW[idx] = (j < 40) ? Wc2[j * 64 + f] : 0.f;
    }
    if (t < 40) sb[t] = bc2[t];
    __syncthreads();
    int gw = (blockIdx.x * blockDim.x + t) >> 5;
    int lane = t & 31;
    int wib = t >> 5;
    if (gw >= NN) return;
    float v0 = cpre[(size_t)gw * 64 + lane];
    float v1 = cpre[(size_t)gw * 64 + 32 + lane];
    int f0 = lane, f1 = lane + 32;
    sc[wib][lane]      = fmaxf((v0 - smean[f0]) * srstd[f0] * gc[f0] + bec[f0], 0.f);
    sc[wib][lane + 32] = fmaxf((v1 - smean[f1]) * srstd[f1] * gc[f1] + bec[f1], 0.f);
    __syncwarp();
    float l0 = sb[lane];
    float l1 = (lane < 8) ? sb[lane + 32] : 0.f;
#pragma unroll
    for (int f = 0; f < 64; f++) {
        float cv = sc[wib][f];
        l0 = fmaf(cv, sW[f * 64 + lane], l0);
        l1 = fmaf(cv, sW[f * 64 + lane + 32], l1);
    }
    float mx = fmaxf(l0, (lane < 8) ? l1 : -INFINITY);
#pragma unroll
    for (int d = 16; d; d >>= 1) mx = fmaxf(mx, __shfl_xor_sync(0xffffffffu, mx, d));
    float s = expf(l0 - mx) + ((lane < 8) ? expf(l1 - mx) : 0.f);
#pragma unroll
    for (int d = 16; d; d >>= 1) s += __shfl_xor_sync(0xffffffffu, s, d);
    float lse = mx + logf(s);
    outls[(size_t)gw * 40 + lane] = l0 - lse;
    if (lane < 8) outls[(size_t)gw * 40 + 32 + lane] = l1 - lse;
}

// ======================= Host orchestration ================================

extern "C" void kernel_launch(void* const* d_in, const int* in_sizes, int n_in,
                              void* d_out, int out_size) {
    (void)in_sizes; (void)n_in; (void)out_size;

    float* S = nullptr;
    cudaGetSymbolAddress((void**)&S, g_scratch);

    float* bufA = S;                       // N*128
    float* bufH = S + 6400000;             // N*128
    float* bufG = S + 12800000;            // N*128
    float* bufC = S + 19200000;            // N*64
    float* asrc = S + 22400000;            // N*8
    float* adst = S + 22800000;
    float* stat  = S + 23201024;           // bucketed stats (STATN floats)
    float* s1s = stat;                          // 8*128
    float* s1q = s1s + NBKT * 128;
    float* s2s = s1q + NBKT * 128;
    float* s2q = s2s + NBKT * 128;
    float* scs = s2q + NBKT * 128;              // 8*64
    float* scq = scs + NBKT * 64;
    float* Wf   = S + 23300000;            // 128*128 fused weight
    float* bf   = Wf + 16384;              // 128 fused bias
    int* ip    = (int*)(S + 24000000);
    int* rowA  = ip;
    int* colA  = rowA + EE;
    int* off1  = colA + EE;
    int* off2  = off1 + (NN + 1);
    int* cur1  = off2 + (NN + 1);
    int* cur2  = cur1 + NN;
    int* cnt1  = cur2 + NN;
    int* cnt2  = cnt1 + NN;
    int* csr1  = cnt2 + NN;
    int* csr2c = csr1 + (EE + NN);
    int* csr2e = csr2c + EE;
    int* flag64 = csr2e + EE;
    int* btot   = flag64 + 1;

    const float* x      = (const float*)d_in[0];
    const int*   eiw    = (const int*)d_in[1];
    const float* gumbel = (const float*)d_in[2];
    const float* W_res  = (const float*)d_in[3];
    const float* b_res  = (const float*)d_in[4];
    const float* Wg1    = (const float*)d_in[5];
    const float* as1    = (const float*)d_in[6];
    const float* ad1    = (const float*)d_in[7];
    const float* bg1    = (const float*)d_in[8];
    const float* g1     = (const float*)d_in[9];
    const float* be1    = (const float*)d_in[10];
    const float* Wg2    = (const float*)d_in[11];
    const float* as2    = (const float*)d_in[12];
    const float* ad2    = (const float*)d_in[13];
    const float* bg2    = (const float*)d_in[14];
    const float* g2     = (const float*)d_in[15];
    const float* be2    = (const float*)d_in[16];
    const float* Ws1    = (const float*)d_in[17];
    const float* bs1    = (const float*)d_in[18];
    const float* Ws2    = (const float*)d_in[19];
    const float* bs2    = (const float*)d_in[20];
    const float* Wc1    = (const float*)d_in[21];
    const float* bc1    = (const float*)d_in[22];
    const float* gc     = (const float*)d_in[23];
    const float* bec    = (const float*)d_in[24];
    const float* Wc2    = (const float*)d_in[25];
    const float* bc2    = (const float*)d_in[26];

    float* out_ls = (float*)d_out;
    float* out_w  = out_ls + (size_t)NN * OUTC;
    float* out_lr = out_w + EE;

    const int NB   = (NN + 255) / 256;
    const int EB   = (EE + 255) / 256;
    const int WRPN = (NN * 32) / 256;
    const int GEMG = (NN + 63) / 64;

    // ---- fork: CSR build on side stream, GEMMs on main stream ----
    cudaStream_t s1str;
    cudaEvent_t evFork, evJoin;
    cudaStreamCreateWithFlags(&s1str, cudaStreamNonBlocking);
    cudaEventCreateWithFlags(&evFork, cudaEventDisableTiming);
    cudaEventCreateWithFlags(&evJoin, cudaEventDisableTiming);

    cudaEventRecord(evFork, 0);
    cudaStreamWaitEvent(s1str, evFork, 0);

    // side stream: CSR build chain
    init_kernel<<<NB, 256, 0, s1str>>>(cnt1, cnt2, flag64, stat);
    detect_kernel<<<256, 256, 0, s1str>>>(eiw, flag64);
    convert_hist_kernel<<<EB, 256, 0, s1str>>>(eiw, flag64, rowA, colA, cnt1, cnt2);
    scan_p1<<<dim3(NTILE, 2), 256, 0, s1str>>>(cnt1, cnt2, btot);
    scan_p2<<<dim3(1, 2), 256, 0, s1str>>>(btot);
    scan_p3<<<dim3(NTILE, 2), 256, 0, s1str>>>(cnt1, cnt2, btot, off1, off2, cur1, cur2, csr1);
    fill_kernel<<<EB, 256, 0, s1str>>>(rowA, colA, cur1, csr1, cur2, csr2c, csr2e);
    cudaEventRecord(evJoin, s1str);

    // main stream: weight fusion, then fused h1 GEMM (+attention dots)
    wfuse_kernel<<<128, 128>>>(Wg1, W_res, b_res, Wf, bf);
    gemm_k128<128, true, false, false><<<GEMG, 128>>>(
        x, Wf, 128, 0, bf, bufH, 128, 0, NN,
        as1, ad1, asrc, adst, nullptr, nullptr);

    // join: aggregation needs CSR + stats-zeroing from side stream
    cudaStreamWaitEvent(0, evJoin, 0);

    gat_aggregate<<<WRPN, 256>>>(bufH, asrc, adst, off1, csr1, bg1, bufG, s1s, s1q);
    bn_elu_kernel<<<(NN * 32 + 255) / 256, 256>>>(bufG, s1s, s1q, g1, be1, bufA, NN * 128);
    gemm_k128<128, true, false, false><<<GEMG, 128>>>(
        bufA, Wg2, 128, 0, nullptr, bufH, 128, 0, NN,
        as2, ad2, asrc, adst, nullptr, nullptr);
    gat_aggregate<<<WRPN, 256>>>(bufH, asrc, adst, off1, csr1, bg2, bufG, s2s, s2q);
    bn_elu_kernel<<<(NN * 32 + 255) / 256, 256>>>(bufG, s2s, s2q, g2, be2, bufA, NN * 128);
    // bufA = h_base

    // edge scorer GEMM (pr | pc), then fused gate + sparse aggregation
    gemm_k128<128, false, false, true><<<GEMG, 128>>>(
        bufA, Ws1, 256, 0, nullptr, bufH, 128, 0, NN,
        nullptr, nullptr, nullptr, nullptr, nullptr, nullptr);
    edge_gate_agg<<<WRPN, 256>>>(bufH, bufA, off2, csr2c, csr2e, gumbel,
                                 bs1, Ws2, bs2, out_w, out_lr, bufG);

    // classifier (BN stats fused into GEMM, finalize fused into classifier)
    gemm_k128<64, false, true, false><<<GEMG, 128>>>(
        bufG, Wc1, 128, 0, bc1, bufC, 64, 0, NN,
        nullptr, nullptr, nullptr, nullptr, scs, scq);
    classifier_kernel<<<WRPN, 256>>>(bufC, scs, scq, gc, bec, Wc2, bc2, out_ls);
}

// round 17
// speedup vs baseline: 1.7837x; 1.1296x over previous
#include <cuda_runtime.h>
#include <cuda_bf16.h>
#include <cuda_pipeline.h>
#include <math.h>

#define NN 50000
#define EE 800000
#define OUTC 40
#define NTILE 196            // ceil(50000/256)
#define NBKT 8               // stat atomic buckets

__device__ __align__(128) float g_scratch[29000000];

#define PACK2(dst, lo, hi) asm("mov.b64 %0, {%1, %2};" : "=l"(dst) : "f"(lo), "f"(hi))
#define UNPK2(lo, hi, v)   asm("mov.b64 {%0, %1}, %2;" : "=f"(lo), "=f"(hi) : "l"(v))
#define FMA2(acc, a, b)    asm("fma.rn.f32x2 %0, %1, %2, %0;" : "+l"(acc) : "l"(a), "l"(b))

// ======================= init: counts, flag, float stat accumulators =======
#define STATN (4 * NBKT * 128 + 2 * NBKT * 64)

__global__ void init_kernel(int* c1, int* c2, int* flag64, float* statz) {
    int i = blockIdx.x * blockDim.x + threadIdx.x;
    if (i < NN) { c1[i] = 1; c2[i] = 0; }     // c1 starts at 1 (self-loop)
    if (i == 0) *flag64 = 1;
    if (i < STATN) statz[i] = 0.f;
}

__global__ void detect_kernel(const int* __restrict__ w, int* flag64) {
    int any = 0;
    for (int i = blockIdx.x * blockDim.x + threadIdx.x; i < EE; i += gridDim.x * blockDim.x)
        any |= w[2 * i + 1];
    if (any) atomicAnd(flag64, 0);
}

// convert edge_index to int32 row/col AND histogram in one pass
__global__ void convert_hist_kernel(const int* __restrict__ w, const int* __restrict__ flag64,
                                    int* __restrict__ rowA, int* __restrict__ colA,
                                    int* c1, int* c2) {
    int e = blockIdx.x * blockDim.x + threadIdx.x;
    if (e >= EE) return;
    int r, c;
    if (*flag64) { r = w[2 * e]; c = w[2 * (EE + e)]; }
    else         { r = w[e];     c = w[EE + e]; }
    rowA[e] = r; colA[e] = c;
    atomicAdd(&c1[c], 1);
    atomicAdd(&c2[r], 1);
}

// ---- parallel 3-phase exclusive scan over two arrays (gridDim.y selects) ----
__global__ void scan_p1(const int* __restrict__ cnt1, const int* __restrict__ cnt2,
                        int* __restrict__ btot) {
    const int* cnt = blockIdx.y ? cnt2 : cnt1;
    __shared__ int sw[8];
    int idx = blockIdx.x * 256 + threadIdx.x;
    int v = (idx < NN) ? cnt[idx] : 0;
#pragma unroll
    for (int d = 16; d; d >>= 1) v += __shfl_xor_sync(0xffffffffu, v, d);
    if ((threadIdx.x & 31) == 0) sw[threadIdx.x >> 5] = v;
    __syncthreads();
    if (threadIdx.x == 0) {
        int s = 0;
#pragma unroll
        for (int i = 0; i < 8; i++) s += sw[i];
        btot[blockIdx.y * (NTILE + 1) + blockIdx.x] = s;
    }
}

__global__ void scan_p2(int* __restrict__ btot) {
    int* b = btot + blockIdx.y * (NTILE + 1);
    __shared__ int sw[8], sw2[9];
    int t = threadIdx.x, lane = t & 31, wid = t >> 5;
    int v = (t < NTILE) ? b[t] : 0;
    int inc = v;
#pragma unroll
    for (int d = 1; d < 32; d <<= 1) { int y = __shfl_up_sync(0xffffffffu, inc, d); if (lane >= d) inc += y; }
    if (lane == 31) sw[wid] = inc;
    __syncthreads();
    if (t == 0) { sw2[0] = 0; for (int i = 0; i < 8; i++) sw2[i + 1] = sw2[i] + sw[i]; }
    __syncthreads();
    int excl = sw2[wid] + inc - v;
    if (t < NTILE) b[t] = excl;
    if (t == 0) b[NTILE] = sw2[8];
}

// scan phase 3 + cursor init + self-loop placement
__global__ void scan_p3(const int* __restrict__ cnt1, const int* __restrict__ cnt2,
                        const int* __restrict__ btot,
                        int* __restrict__ off1, int* __restrict__ off2,
                        int* __restrict__ cur1, int* __restrict__ cur2, int* __restrict__ csr1) {
    const int* cnt = blockIdx.y ? cnt2 : cnt1;
    int* off = blockIdx.y ? off2 : off1;
    const int* b = btot + blockIdx.y * (NTILE + 1);
    __shared__ int sw[8], sw2[9];
    int t = threadIdx.x, lane = t & 31, wid = t >> 5;
    int idx = blockIdx.x * 256 + t;
    int v = (idx < NN) ? cnt[idx] : 0;
    int inc = v;
#pragma unroll
    for (int d = 1; d < 32; d <<= 1) { int y = __shfl_up_sync(0xffffffffu, inc, d); if (lane >= d) inc += y; }
    if (lane == 31) sw[wid] = inc;
    __syncthreads();
    if (t == 0) { sw2[0] = 0; for (int i = 0; i < 8; i++) sw2[i + 1] = sw2[i] + sw[i]; }
    __syncthreads();
    int excl = b[blockIdx.x] + sw2[wid] + inc - v;
    if (idx < NN) {
        off[idx] = excl;
        if (blockIdx.y == 0) { cur1[idx] = excl + 1; csr1[excl] = idx; }
        else                 cur2[idx] = excl;
    }
    if (blockIdx.x == 0 && t == 0) off[NN] = b[NTILE];
}

__global__ void fill_kernel(const int* __restrict__ rowA, const int* __restrict__ colA,
                            int* cur1, int* csr1,
                            int* cur2, int* csr2c, int* csr2e) {
    int e = blockIdx.x * blockDim.x + threadIdx.x;
    if (e >= EE) return;
    int r = rowA[e];
    int c = colA[e];
    int p = atomicAdd(&cur1[c], 1);
    csr1[p] = r;
    int q = atomicAdd(&cur2[r], 1);
    csr2c[q] = c;
    csr2e[q] = e;
}

// ======================= weight fusion: Wf = Wg1 @ W_res, bf = Wg1 @ b_res ==
__global__ void wfuse_kernel(const float* __restrict__ Wg1, const float* __restrict__ W_res,
                             const float* __restrict__ b_res,
                             float* __restrict__ Wf, float* __restrict__ bf) {
    __shared__ float sWg[128];
    __shared__ float red[128];
    int d = blockIdx.x, k = threadIdx.x;
    sWg[k] = Wg1[d * 128 + k];
    __syncthreads();
    float s = 0.f;
#pragma unroll 8
    for (int j = 0; j < 128; j++) s = fmaf(sWg[j], W_res[j * 128 + k], s);
    Wf[d * 128 + k] = s;
    red[k] = sWg[k] * b_res[k];
    __syncthreads();
    for (int st = 64; st; st >>= 1) { if (k < st) red[k] += red[k + st]; __syncthreads(); }
    if (k == 0) bf[d] = red[0];
}

// ======================= GEMM (K = 128 fixed, f32x2 FMA, cp.async) =========

template <int TC, bool ATTN, bool STATS, bool SPLITW>
__global__ void __launch_bounds__(128, 4)
gemm_k128(const float* __restrict__ A, const float* __restrict__ W,
          int ldw, int woff, const float* __restrict__ bias,
          float* __restrict__ out, int opitch, int ocol, int nrows,
          const float* __restrict__ as, const float* __restrict__ ad,
          float* __restrict__ asrc, float* __restrict__ adst,
          float* gsum, float* gsq) {
    constexpr int CT = TC / 16;
    constexpr int PA = 68;
    constexpr int PW = TC + 4;
    __shared__ float sA[2][32 * PA];
    __shared__ float sW[2][32 * PW];
    const int tid = threadIdx.x;
    const int trow = tid >> 4;     // 0..7
    const int tcol = tid & 15;     // 0..15
    const int r0 = blockIdx.x * 64;

    unsigned long long acc2[4][CT];   // row-pairs x cols
#pragma unroll
    for (int p = 0; p < 4; p++)
#pragma unroll
        for (int j = 0; j < CT; j++) acc2[p][j] = 0ull;

    auto loadTiles = [&](int buf, int kb) {
#pragma unroll
        for (int i = 0; i < 16; i++) {
            int idx = tid + i * 128;
            int row = idx >> 5, kk = idx & 31;
            int gr = r0 + row;
            if (gr < nrows)
                __pipeline_memcpy_async(&sA[buf][kk * PA + row],
                                        &A[(size_t)gr * 128 + kb + kk], 4);
            else
                sA[buf][kk * PA + row] = 0.f;
        }
#pragma unroll
        for (int i = 0; i < (TC * 32) / 128; i++) {
            int idx = tid + i * 128;
            int col = idx >> 5, kk = idx & 31;
            int wrow = SPLITW ? (col & 63) : col;
            int wko  = SPLITW ? ((col >> 6) * 128) : 0;
            __pipeline_memcpy_async(&sW[buf][kk * PW + col],
                                    &W[(size_t)wrow * ldw + woff + wko + kb + kk], 4);
        }
        __pipeline_commit();
    };

    loadTiles(0, 0);
    int buf = 0;

    for (int kb = 0; kb < 128; kb += 32) {
        if (kb + 32 < 128) loadTiles(buf ^ 1, kb + 32);
        if (kb + 32 < 128) __pipeline_wait_prior(1);
        else               __pipeline_wait_prior(0);
        __syncthreads();
        const float* cA = sA[buf];
        const float* cW = sW[buf];
#pragma unroll
        for (int kk = 0; kk < 32; kk++) {
            unsigned long long ap[4];
#pragma unroll
            for (int p = 0; p < 4; p++)
                ap[p] = *(const unsigned long long*)&cA[kk * PA + trow * 8 + 2 * p];
            float w[CT];
#pragma unroll
            for (int j = 0; j < CT; j += 4) {
                float4 wv = *(const float4*)&cW[kk * PW + tcol * CT + j];
                w[j] = wv.x; w[j + 1] = wv.y; w[j + 2] = wv.z; w[j + 3] = wv.w;
            }
            unsigned long long wd[CT];
#pragma unroll
            for (int j = 0; j < CT; j++) PACK2(wd[j], w[j], w[j]);
#pragma unroll
            for (int p = 0; p < 4; p++)
#pragma unroll
                for (int j = 0; j < CT; j++) FMA2(acc2[p][j], ap[p], wd[j]);
        }
        __syncthreads();
        buf ^= 1;
    }
    // ---- store ----
#pragma unroll
    for (int p = 0; p < 4; p++) {
        int gr0 = r0 + trow * 8 + 2 * p;
#pragma unroll
        for (int j = 0; j < CT; j++) {
            int col = tcol * CT + j;
            float b = bias ? bias[col] : 0.f;
            float lo, hi;
            UNPK2(lo, hi, acc2[p][j]);
            if (gr0 < nrows)     out[(size_t)gr0 * opitch + ocol + col]       = lo + b;
            if (gr0 + 1 < nrows) out[(size_t)(gr0 + 1) * opitch + ocol + col] = hi + b;
        }
    }
    // ---- fused attention dots (TC=128 only) ----
    if (ATTN) {
#pragma unroll
        for (int p = 0; p < 4; p++) {
            float s1lo = 0.f, s2lo = 0.f, s1hi = 0.f, s2hi = 0.f;
#pragma unroll
            for (int j = 0; j < CT; j++) {
                int col = tcol * CT + j;
                float aS = __ldg(&as[col]), aD = __ldg(&ad[col]);
                float lo, hi;
                UNPK2(lo, hi, acc2[p][j]);
                s1lo = fmaf(lo, aS, s1lo); s2lo = fmaf(lo, aD, s2lo);
                s1hi = fmaf(hi, aS, s1hi); s2hi = fmaf(hi, aD, s2hi);
            }
            s1lo += __shfl_xor_sync(0xffffffffu, s1lo, 1);
            s2lo += __shfl_xor_sync(0xffffffffu, s2lo, 1);
            s1hi += __shfl_xor_sync(0xffffffffu, s1hi, 1);
            s2hi += __shfl_xor_sync(0xffffffffu, s2hi, 1);
            if (!(tcol & 1)) {
                int h = tcol >> 1;
                int rlo = r0 + trow * 8 + 2 * p;
                if (rlo < nrows)     { asrc[rlo * 8 + h] = s1lo;       adst[rlo * 8 + h] = s2lo; }
                if (rlo + 1 < nrows) { asrc[(rlo + 1) * 8 + h] = s1hi; adst[(rlo + 1) * 8 + h] = s2hi; }
            }
        }
    }
    // ---- fused per-feature BN statistics (bucketed) ----
    if (STATS) {
        __shared__ float s_s[8][TC], s_q[8][TC];
#pragma unroll
        for (int j = 0; j < CT; j++) {
            int col = tcol * CT + j;
            float b = bias ? bias[col] : 0.f;
            float ps = 0.f, pq = 0.f;
#pragma unroll
            for (int p = 0; p < 4; p++) {
                int gr0 = r0 + trow * 8 + 2 * p;
                float lo, hi;
                UNPK2(lo, hi, acc2[p][j]);
                if (gr0 < nrows)     { float v = lo + b; ps += v; pq = fmaf(v, v, pq); }
                if (gr0 + 1 < nrows) { float v = hi + b; ps += v; pq = fmaf(v, v, pq); }
            }
            s_s[trow][col] = ps;
            s_q[trow][col] = pq;
        }
        __syncthreads();
        if (tid < TC) {
            float S = 0.f, Q = 0.f;
#pragma unroll
            for (int w = 0; w < 8; w++) { S += s_s[w][tid]; Q += s_q[w][tid]; }
            int bk = (blockIdx.x & (NBKT - 1)) * TC;
            atomicAdd(&gsum[bk + tid], S);
            atomicAdd(&gsq[bk + tid],  Q);
        }
    }
}

// ======================= GAT aggregation (online softmax + BN stats) =======
// one warp per node; unrolled x4; bucketed stats

__global__ void __launch_bounds__(256)
gat_aggregate(const float* __restrict__ hfeat,
              const float* __restrict__ asrc, const float* __restrict__ adst,
              const int* __restrict__ off, const int* __restrict__ csr,
              const float* __restrict__ bg, float* __restrict__ outp,
              float* gsum, float* gsq) {
    __shared__ float s_v[8][128];
    int gw = (blockIdx.x * blockDim.x + threadIdx.x) >> 5;
    int lane = threadIdx.x & 31;
    int wib = threadIdx.x >> 5;
    int head = lane >> 2;
    float ad = adst[gw * 8 + head];
    float mm = -INFINITY, den = 0.f;
    float4 acc = make_float4(0.f, 0.f, 0.f, 0.f);
    int s0 = off[gw], s1 = off[gw + 1];
    int i = s0;
    for (; i + 3 < s1; i += 4) {
        int sa = csr[i], sb = csr[i + 1], sc2 = csr[i + 2], sd = csr[i + 3];
        float ea = asrc[sa * 8 + head] + ad;
        float eb = asrc[sb * 8 + head] + ad;
        float ec = asrc[sc2 * 8 + head] + ad;
        float ed = asrc[sd * 8 + head] + ad;
        ea = (ea >= 0.f) ? ea : 0.2f * ea;
        eb = (eb >= 0.f) ? eb : 0.2f * eb;
        ec = (ec >= 0.f) ? ec : 0.2f * ec;
        ed = (ed >= 0.f) ? ed : 0.2f * ed;
        float4 ha = *(const float4*)&hfeat[(size_t)sa * 128 + lane * 4];
        float4 hb = *(const float4*)&hfeat[(size_t)sb * 128 + lane * 4];
        float4 hc = *(const float4*)&hfeat[(size_t)sc2 * 128 + lane * 4];
        float4 hd = *(const float4*)&hfeat[(size_t)sd * 128 + lane * 4];
        float m4 = fmaxf(fmaxf(ea, eb), fmaxf(ec, ed));
        if (m4 > mm) {
            float sc = __expf(mm - m4);
            den *= sc;
            acc.x *= sc; acc.y *= sc; acc.z *= sc; acc.w *= sc;
            mm = m4;
        }
        float pa = __expf(ea - mm);
        float pb = __expf(eb - mm);
        float pc = __expf(ec - mm);
        float pd = __expf(ed - mm);
        den += (pa + pb) + (pc + pd);
        acc.x = fmaf(ha.x, pa, fmaf(hb.x, pb, fmaf(hc.x, pc, fmaf(hd.x, pd, acc.x))));
        acc.y = fmaf(ha.y, pa, fmaf(hb.y, pb, fmaf(hc.y, pc, fmaf(hd.y, pd, acc.y))));
        acc.z = fmaf(ha.z, pa, fmaf(hb.z, pb, fmaf(hc.z, pc, fmaf(hd.z, pd, acc.z))));
        acc.w = fmaf(ha.w, pa, fmaf(hb.w, pb, fmaf(hc.w, pc, fmaf(hd.w, pd, acc.w))));
    }
    for (; i < s1; i++) {
        int s = csr[i];
        float e = asrc[s * 8 + head] + ad;
        e = (e >= 0.f) ? e : 0.2f * e;
        if (e > mm) {
            float sc = __expf(mm - e);
            den *= sc;
            acc.x *= sc; acc.y *= sc; acc.z *= sc; acc.w *= sc;
            mm = e;
        }
        float p = __expf(e - mm);
        den += p;
        float4 hv = *(const float4*)&hfeat[(size_t)s * 128 + lane * 4];
        acc.x = fmaf(hv.x, p, acc.x);
        acc.y = fmaf(hv.y, p, acc.y);
        acc.z = fmaf(hv.z, p, acc.z);
        acc.w = fmaf(hv.w, p, acc.w);
    }
    float inv = 1.f / (den + 1e-16f);
    float4 bgv = *(const float4*)&bg[lane * 4];
    acc.x = fmaf(acc.x, inv, bgv.x);
    acc.y = fmaf(acc.y, inv, bgv.y);
    acc.z = fmaf(acc.z, inv, bgv.z);
    acc.w = fmaf(acc.w, inv, bgv.w);
    *(float4*)&outp[(size_t)gw * 128 + lane * 4] = acc;
    *(float4*)&s_v[wib][lane * 4] = acc;
    __syncthreads();
    int t = threadIdx.x;
    if (t < 128) {
        float S = 0.f, Q = 0.f;
#pragma unroll
        for (int w = 0; w < 8; w++) { float v = s_v[w][t]; S += v; Q = fmaf(v, v, Q); }
        int bk = (blockIdx.x & (NBKT - 1)) * 128;
        atomicAdd(&gsum[bk + t], S);
        atomicAdd(&gsq[bk + t],  Q);
    }
}

// ======================= BN+ELU with fused finalize ========================

__global__ void bn_elu_kernel(const float* __restrict__ x,
                              const float* __restrict__ gs, const float* __restrict__ gq,
                              const float* __restrict__ gamma, const float* __restrict__ beta,
                              float* __restrict__ out, int total) {
    __shared__ float smean[128], srstd[128];
    int t = threadIdx.x;
    if (t < 128) {
        float S = 0.f, Q = 0.f;
#pragma unroll
        for (int b = 0; b < NBKT; b++) { S += gs[b * 128 + t]; Q += gq[b * 128 + t]; }
        double invN = 1.0 / (double)NN;
        double mu = (double)S * invN;
        double var = (double)Q * invN - mu * mu;
        if (var < 0.0) var = 0.0;
        smean[t] = (float)mu;
        srstd[t] = rsqrtf((float)var + 1e-5f);
    }
    __syncthreads();
    int i = (blockIdx.x * blockDim.x + threadIdx.x) * 4;
    if (i >= total) return;
    float4 v = *(const float4*)&x[i];
    int f = i & 127;
    float r[4] = {v.x, v.y, v.z, v.w};
#pragma unroll
    for (int k = 0; k < 4; k++) {
        int ff = f + k;
        float tt = (r[k] - smean[ff]) * srstd[ff] * gamma[ff] + beta[ff];
        r[k] = (tt > 0.f) ? tt : expm1f(tt);
    }
    *(float4*)&out[i] = make_float4(r[0], r[1], r[2], r[3]);
}

// ======================= Edge gate + sparse aggregation, fused, x4 =========

__global__ void __launch_bounds__(256)
edge_gate_agg(const float* __restrict__ prpc,
              const float* __restrict__ hbase,
              const int* __restrict__ off2,
              const int* __restrict__ col2, const int* __restrict__ eid2,
              const float* __restrict__ gumbel,
              const float* __restrict__ bs1,
              const float* __restrict__ ws2,
              const float* __restrict__ bs2,
              float* __restrict__ wout, float* __restrict__ lrout,
              float* __restrict__ outp) {
    __shared__ float sw2[64];
    __shared__ float sb1[64];
    if (threadIdx.x < 64) { sw2[threadIdx.x] = ws2[threadIdx.x]; sb1[threadIdx.x] = bs1[threadIdx.x]; }
    __syncthreads();
    int gw = (blockIdx.x * blockDim.x + threadIdx.x) >> 5;
    if (gw >= NN) return;
    int lane = threadIdx.x & 31;
    float pr0 = prpc[(size_t)gw * 128 + lane]      + sb1[lane];
    float pr1 = prpc[(size_t)gw * 128 + 32 + lane] + sb1[32 + lane];
    float w0 = sw2[lane], w1 = sw2[32 + lane];
    float bias2 = bs2[0];
    float4 acc = *(const float4*)&hbase[(size_t)gw * 128 + lane * 4];
    int s0 = off2[gw], s1 = off2[gw + 1];
    int i = s0;
    for (; i + 3 < s1; i += 4) {
        int c0 = col2[i], c1 = col2[i + 1], c2 = col2[i + 2], c3 = col2[i + 3];
        int e0 = eid2[i], e1 = eid2[i + 1], e2 = eid2[i + 2], e3 = eid2[i + 3];
        float g00 = 0.f, g01 = 0.f, g10 = 0.f, g11 = 0.f;
        float g20 = 0.f, g21 = 0.f, g30 = 0.f, g31 = 0.f;
        if (lane == 0) {
            float2 gA = *(const float2*)&gumbel[2 * (size_t)e0];
            float2 gB = *(const float2*)&gumbel[2 * (size_t)e1];
            float2 gC = *(const float2*)&gumbel[2 * (size_t)e2];
            float2 gD = *(const float2*)&gumbel[2 * (size_t)e3];
            g00 = gA.x; g01 = gA.y; g10 = gB.x; g11 = gB.y;
            g20 = gC.x; g21 = gC.y; g30 = gD.x; g31 = gD.y;
        }
        float a0 = prpc[(size_t)c0 * 128 + 64 + lane];
        float a1 = prpc[(size_t)c0 * 128 + 96 + lane];
        float b0 = prpc[(size_t)c1 * 128 + 64 + lane];
        float b1 = prpc[(size_t)c1 * 128 + 96 + lane];
        float cc0 = prpc[(size_t)c2 * 128 + 64 + lane];
        float cc1 = prpc[(size_t)c2 * 128 + 96 + lane];
        float d0 = prpc[(size_t)c3 * 128 + 64 + lane];
        float d1 = prpc[(size_t)c3 * 128 + 96 + lane];
        float pa = fmaxf(pr0 + a0, 0.f) * w0 + fmaxf(pr1 + a1, 0.f) * w1;
        float pb = fmaxf(pr0 + b0, 0.f) * w0 + fmaxf(pr1 + b1, 0.f) * w1;
        float pc = fmaxf(pr0 + cc0, 0.f) * w0 + fmaxf(pr1 + cc1, 0.f) * w1;
        float pd = fmaxf(pr0 + d0, 0.f) * w0 + fmaxf(pr1 + d1, 0.f) * w1;
#pragma unroll
        for (int d = 16; d; d >>= 1) {
            pa += __shfl_xor_sync(0xffffffffu, pa, d);
            pb += __shfl_xor_sync(0xffffffffu, pb, d);
            pc += __shfl_xor_sync(0xffffffffu, pc, d);
            pd += __shfl_xor_sync(0xffffffffu, pd, d);
        }
        float lr0 = pa + bias2, lr1 = pb + bias2, lr2 = pc + bias2, lr3 = pd + bias2;
        int gg0 = 0, gg1 = 0, gg2 = 0, gg3 = 0;
        if (lane == 0) {
            lrout[e0] = lr0; lrout[e1] = lr1; lrout[e2] = lr2; lrout[e3] = lr3;
            gg0 = (lr0 + g01 > g00) ? 1 : 0;
            gg1 = (lr1 + g11 > g10) ? 1 : 0;
            gg2 = (lr2 + g21 > g20) ? 1 : 0;
            gg3 = (lr3 + g31 > g30) ? 1 : 0;
            wout[e0] = gg0 ? 1.f : 0.f;
            wout[e1] = gg1 ? 1.f : 0.f;
            wout[e2] = gg2 ? 1.f : 0.f;
            wout[e3] = gg3 ? 1.f : 0.f;
        }
        gg0 = __shfl_sync(0xffffffffu, gg0, 0);
        gg1 = __shfl_sync(0xffffffffu, gg1, 0);
        gg2 = __shfl_sync(0xffffffffu, gg2, 0);
        gg3 = __shfl_sync(0xffffffffu, gg3, 0);
        if (gg0) {
            float4 h = *(const float4*)&hbase[(size_t)c0 * 128 + lane * 4];
            acc.x += h.x; acc.y += h.y; acc.z += h.z; acc.w += h.w;
        }
        if (gg1) {
            float4 h = *(const float4*)&hbase[(size_t)c1 * 128 + lane * 4];
            acc.x += h.x; acc.y += h.y; acc.z += h.z; acc.w += h.w;
        }
        if (gg2) {
            float4 h = *(const float4*)&hbase[(size_t)c2 * 128 + lane * 4];
            acc.x += h.x; acc.y += h.y; acc.z += h.z; acc.w += h.w;
        }
        if (gg3) {
            float4 h = *(const float4*)&hbase[(size_t)c3 * 128 + lane * 4];
            acc.x += h.x; acc.y += h.y; acc.z += h.z; acc.w += h.w;
        }
    }
    for (; i < s1; i++) {
        int c = col2[i], e = eid2[i];
        float g0 = 0.f, g1 = 0.f;
        if (lane == 0) {
            float2 gA = *(const float2*)&gumbel[2 * (size_t)e];
            g0 = gA.x; g1 = gA.y;
        }
        float a0 = prpc[(size_t)c * 128 + 64 + lane];
        float a1 = prpc[(size_t)c * 128 + 96 + lane];
        float p = fmaxf(pr0 + a0, 0.f) * w0 + fmaxf(pr1 + a1, 0.f) * w1;
#pragma unroll
        for (int d = 16; d; d >>= 1) p += __shfl_xor_sync(0xffffffffu, p, d);
        float lr = p + bias2;
        int g = 0;
        if (lane == 0) {
            lrout[e] = lr;
            g = (lr + g1 > g0) ? 1 : 0;
            wout[e] = g ? 1.f : 0.f;
        }
        g = __shfl_sync(0xffffffffu, g, 0);
        if (g) {
            float4 h = *(const float4*)&hbase[(size_t)c * 128 + lane * 4];
            acc.x += h.x; acc.y += h.y; acc.z += h.z; acc.w += h.w;
        }
    }
    *(float4*)&outp[(size_t)gw * 128 + lane * 4] = acc;
}

// ======================= Classifier head (grid-stride, fused finalize) =====

__global__ void __launch_bounds__(256)
classifier_kernel(const float* __restrict__ cpre,
                  const float* __restrict__ gs, const float* __restrict__ gq,
                  const float* __restrict__ gc,
                  const float* __restrict__ bec, const float* __restrict__ Wc2,
                  const float* __restrict__ bc2, float* __restrict__ outls) {
    __shared__ float sW[64 * 64];
    __shared__ float sb[40];
    __shared__ float sc[8][64];
    __shared__ float smean[64], srstd[64];
    int t = threadIdx.x;
    if (t < 64) {
        float S = 0.f, Q = 0.f;
#pragma unroll
        for (int b = 0; b < NBKT; b++) { S += gs[b * 64 + t]; Q += gq[b * 64 + t]; }
        double invN = 1.0 / (double)NN;
        double mu = (double)S * invN;
        double var = (double)Q * invN - mu * mu;
        if (var < 0.0) var = 0.0;
        smean[t] = (float)mu;
        srstd[t] = rsqrtf((float)var + 1e-5f);
    }
    for (int idx = t; idx < 64 * 64; idx += blockDim.x) {
        int f = idx >> 6, j = idx & 63;
        sW[idx] = (j < 40) ? Wc2[j * 64 + f] : 0.f;
    }
    if (t < 40) sb[t] = bc2[t];
    __syncthreads();
    int lane = t & 31;
    int wib = t >> 5;
    int warps_total = gridDim.x * 8;
    for (int gw = blockIdx.x * 8 + wib; gw < NN; gw += warps_total) {
        float v0 = cpre[(size_t)gw * 64 + lane];
        float v1 = cpre[(size_t)gw * 64 + 32 + lane];
        int f0 = lane, f1 = lane + 32;
        sc[wib][lane]      = fmaxf((v0 - smean[f0]) * srstd[f0] * gc[f0] + bec[f0], 0.f);
        sc[wib][lane + 32] = fmaxf((v1 - smean[f1]) * srstd[f1] * gc[f1] + bec[f1], 0.f);
        __syncwarp();
        float l0 = sb[lane];
        float l1 = (lane < 8) ? sb[lane + 32] : 0.f;
#pragma unroll
        for (int f = 0; f < 64; f++) {
            float cv = sc[wib][f];
            l0 = fmaf(cv, sW[f * 64 + lane], l0);
            l1 = fmaf(cv, sW[f * 64 + lane + 32], l1);
        }
        float mx = fmaxf(l0, (lane < 8) ? l1 : -INFINITY);
#pragma unroll
        for (int d = 16; d; d >>= 1) mx = fmaxf(mx, __shfl_xor_sync(0xffffffffu, mx, d));
        float s = expf(l0 - mx) + ((lane < 8) ? expf(l1 - mx) : 0.f);
#pragma unroll
        for (int d = 16; d; d >>= 1) s += __shfl_xor_sync(0xffffffffu, s, d);
        float lse = mx + logf(s);
        outls[(size_t)gw * 40 + lane] = l0 - lse;
        if (lane < 8) outls[(size_t)gw * 40 + 32 + lane] = l1 - lse;
        __syncwarp();
    }
}

// ======================= Host orchestration ================================

extern "C" void kernel_launch(void* const* d_in, const int* in_sizes, int n_in,
                              void* d_out, int out_size) {
    (void)in_sizes; (void)n_in; (void)out_size;

    float* S = nullptr;
    cudaGetSymbolAddress((void**)&S, g_scratch);

    float* bufA = S;                       // N*128
    float* bufH = S + 6400000;             // N*128
    float* bufG = S + 12800000;            // N*128
    float* bufC = S + 19200000;            // N*64
    float* asrc = S + 22400000;            // N*8
    float* adst = S + 22800000;
    float* stat  = S + 23201024;           // bucketed stats
    float* s1s = stat;
    float* s1q = s1s + NBKT * 128;
    float* s2s = s1q + NBKT * 128;
    float* s2q = s2s + NBKT * 128;
    float* scs = s2q + NBKT * 128;
    float* scq = scs + NBKT * 64;
    float* Wf   = S + 23300000;            // 128*128 fused weight
    float* bf   = Wf + 16384;              // 128 fused bias
    int* ip    = (int*)(S + 24000000);
    int* rowA  = ip;
    int* colA  = rowA + EE;
    int* off1  = colA + EE;
    int* off2  = off1 + (NN + 1);
    int* cur1  = off2 + (NN + 1);
    int* cur2  = cur1 + NN;
    int* cnt1  = cur2 + NN;
    int* cnt2  = cnt1 + NN;
    int* csr1  = cnt2 + NN;
    int* csr2c = csr1 + (EE + NN);
    int* csr2e = csr2c + EE;
    int* flag64 = csr2e + EE;
    int* btot   = flag64 + 1;

    const float* x      = (const float*)d_in[0];
    const int*   eiw    = (const int*)d_in[1];
    const float* gumbel = (const float*)d_in[2];
    const float* W_res  = (const float*)d_in[3];
    const float* b_res  = (const float*)d_in[4];
    const float* Wg1    = (const float*)d_in[5];
    const float* as1    = (const float*)d_in[6];
    const float* ad1    = (const float*)d_in[7];
    const float* bg1    = (const float*)d_in[8];
    const float* g1     = (const float*)d_in[9];
    const float* be1    = (const float*)d_in[10];
    const float* Wg2    = (const float*)d_in[11];
    const float* as2    = (const float*)d_in[12];
    const float* ad2    = (const float*)d_in[13];
    const float* bg2    = (const float*)d_in[14];
    const float* g2     = (const float*)d_in[15];
    const float* be2    = (const float*)d_in[16];
    const float* Ws1    = (const float*)d_in[17];
    const float* bs1    = (const float*)d_in[18];
    const float* Ws2    = (const float*)d_in[19];
    const float* bs2    = (const float*)d_in[20];
    const float* Wc1    = (const float*)d_in[21];
    const float* bc1    = (const float*)d_in[22];
    const float* gc     = (const float*)d_in[23];
    const float* bec    = (const float*)d_in[24];
    const float* Wc2    = (const float*)d_in[25];
    const float* bc2    = (const float*)d_in[26];

    float* out_ls = (float*)d_out;
    float* out_w  = out_ls + (size_t)NN * OUTC;
    float* out_lr = out_w + EE;

    const int NB   = (NN + 255) / 256;
    const int EB   = (EE + 255) / 256;
    const int WRPN = (NN * 32) / 256;
    const int GEMG = (NN + 63) / 64;

    // ---- fork: CSR build on side stream, GEMMs on main stream ----
    cudaStream_t s1str;
    cudaEvent_t evFork, evJoin;
    cudaStreamCreateWithFlags(&s1str, cudaStreamNonBlocking);
    cudaEventCreateWithFlags(&evFork, cudaEventDisableTiming);
    cudaEventCreateWithFlags(&evJoin, cudaEventDisableTiming);

    cudaEventRecord(evFork, 0);
    cudaStreamWaitEvent(s1str, evFork, 0);

    // side stream: CSR build chain
    init_kernel<<<NB, 256, 0, s1str>>>(cnt1, cnt2, flag64, stat);
    detect_kernel<<<256, 256, 0, s1str>>>(eiw, flag64);
    convert_hist_kernel<<<EB, 256, 0, s1str>>>(eiw, flag64, rowA, colA, cnt1, cnt2);
    scan_p1<<<dim3(NTILE, 2), 256, 0, s1str>>>(cnt1, cnt2, btot);
    scan_p2<<<dim3(1, 2), 256, 0, s1str>>>(btot);
    scan_p3<<<dim3(NTILE, 2), 256, 0, s1str>>>(cnt1, cnt2, btot, off1, off2, cur1, cur2, csr1);
    fill_kernel<<<EB, 256, 0, s1str>>>(rowA, colA, cur1, csr1, cur2, csr2c, csr2e);
    cudaEventRecord(evJoin, s1str);

    // main stream: weight fusion, then fused h1 GEMM (+attention dots)
    wfuse_kernel<<<128, 128>>>(Wg1, W_res, b_res, Wf, bf);
    gemm_k128<128, true, false, false><<<GEMG, 128>>>(
        x, Wf, 128, 0, bf, bufH, 128, 0, NN,
        as1, ad1, asrc, adst, nullptr, nullptr);

    // join: aggregation needs CSR + stats-zeroing from side stream
    cudaStreamWaitEvent(0, evJoin, 0);

    gat_aggregate<<<WRPN, 256>>>(bufH, asrc, adst, off1, csr1, bg1, bufG, s1s, s1q);
    bn_elu_kernel<<<(NN * 32 + 255) / 256, 256>>>(bufG, s1s, s1q, g1, be1, bufA, NN * 128);
    gemm_k128<128, true, false, false><<<GEMG, 128>>>(
        bufA, Wg2, 128, 0, nullptr, bufH, 128, 0, NN,
        as2, ad2, asrc, adst, nullptr, nullptr);
    gat_aggregate<<<WRPN, 256>>>(bufH, asrc, adst, off1, csr1, bg2, bufG, s2s, s2q);
    bn_elu_kernel<<<(NN * 32 + 255) / 256, 256>>>(bufG, s2s, s2q, g2, be2, bufA, NN * 128);
    // bufA = h_base

    // edge scorer GEMM (pr | pc), then fused gate + sparse aggregation
    gemm_k128<128, false, false, true><<<GEMG, 128>>>(
        bufA, Ws1, 256, 0, nullptr, bufH, 128, 0, NN,
        nullptr, nullptr, nullptr, nullptr, nullptr, nullptr);
    edge_gate_agg<<<WRPN, 256>>>(bufH, bufA, off2, csr2c, csr2e, gumbel,
                                 bs1, Ws2, bs2, out_w, out_lr, bufG);

    // classifier (BN stats fused into GEMM, finalize fused, grid-stride)
    gemm_k128<64, false, true, false><<<GEMG, 128>>>(
        bufG, Wc1, 128, 0, bc1, bufC, 64, 0, NN,
        nullptr, nullptr, nullptr, nullptr, scs, scq);
    classifier_kernel<<<1184, 256>>>(bufC, scs, scq, gc, bec, Wc2, bc2, out_ls);
}